// round 1
// baseline (speedup 1.0000x reference)
#include <cuda_runtime.h>
#include <cuda_bf16.h>
#include <cstdint>

#define NN 20000
#define EE 320000

// ---------------- scratch (device globals; no allocation) ----------------
__device__ float d_bufA[NN * 256];
__device__ float d_bufB[NN * 256];
__device__ float d_h[NN * 256];
__device__ float d_x0[NN * 64];
__device__ float d_P[NN * 128];
__device__ float d_aAff[512];
__device__ float d_bAff[512];
__device__ float d_dinv[NN];
__device__ int   d_indeg[NN];
__device__ int   d_rowptr[NN + 1];
__device__ int   d_cursor[NN];
__device__ int   d_csrsrc[EE];

// ---------------- CSR build ----------------
__global__ void zero_indeg_kernel() {
    int i = blockIdx.x * blockDim.x + threadIdx.x;
    if (i < NN) d_indeg[i] = 0;
}

__global__ void count_kernel(const int* __restrict__ ei) {
    int i = blockIdx.x * blockDim.x + threadIdx.x;
    if (i < EE) atomicAdd(&d_indeg[ei[EE + i]], 1);
}

__global__ void scan_kernel() {
    __shared__ int sh[1024];
    __shared__ int carry;
    int tid = threadIdx.x;
    if (tid == 0) carry = 0;
    __syncthreads();
    for (int base = 0; base < NN; base += 1024) {
        int i = base + tid;
        int v = (i < NN) ? d_indeg[i] : 0;
        sh[tid] = v;
        __syncthreads();
        for (int off = 1; off < 1024; off <<= 1) {
            int t = (tid >= off) ? sh[tid - off] : 0;
            __syncthreads();
            sh[tid] += t;
            __syncthreads();
        }
        int incl = sh[tid];
        int base_c = carry;
        if (i < NN) {
            int excl = base_c + incl - v;
            d_rowptr[i] = excl;
            d_cursor[i] = excl;
            d_dinv[i] = rsqrtf((float)(v + 1));  // deg includes self-loop
        }
        __syncthreads();
        if (tid == 1023) carry = base_c + sh[1023];
        __syncthreads();
    }
    if (tid == 0) d_rowptr[NN] = carry;
}

__global__ void fill_kernel(const int* __restrict__ ei) {
    int i = blockIdx.x * blockDim.x + threadIdx.x;
    if (i < EE) {
        int s = ei[i];
        int d = ei[EE + i];
        int pos = atomicAdd(&d_cursor[d], 1);
        d_csrsrc[pos] = s;
    }
}

// ---------------- generic row-tiled GEMM: out = act(A) @ W (+bias) ----------------
// blockDim = COUT, 4 rows per block. Optional per-column affine+ReLU pre-activation.
template <int K, int COUT, bool PRE>
__global__ void gemm_rows(const float* __restrict__ A, const float* __restrict__ W,
                          const float* __restrict__ bias,
                          const float* __restrict__ aAff, const float* __restrict__ bAff,
                          float* __restrict__ out,
                          int rowStart, int rowStride, int numRows) {
    __shared__ float As[4 * K];
    int tid = threadIdx.x;
    int rblk = blockIdx.x * 4;
    for (int idx = tid; idx < 4 * K; idx += COUT) {
        int r = idx / K, k = idx - r * K;
        int rr = rblk + r;
        float v = 0.f;
        if (rr < numRows) {
            int grow = rowStart + rr * rowStride;
            v = A[(size_t)grow * K + k];
            if (PRE) v = fmaxf(fmaf(aAff[k], v, bAff[k]), 0.f);
        }
        As[idx] = v;
    }
    __syncthreads();
    int c = tid;
    float acc[4] = {0.f, 0.f, 0.f, 0.f};
#pragma unroll 4
    for (int k = 0; k < K; k++) {
        float wv = W[(size_t)k * COUT + c];
        acc[0] = fmaf(As[k], wv, acc[0]);
        acc[1] = fmaf(As[K + k], wv, acc[1]);
        acc[2] = fmaf(As[2 * K + k], wv, acc[2]);
        acc[3] = fmaf(As[3 * K + k], wv, acc[3]);
    }
    float bv = bias ? bias[c] : 0.f;
#pragma unroll
    for (int r = 0; r < 4; r++) {
        int rr = rblk + r;
        if (rr < numRows) {
            int grow = rowStart + rr * rowStride;
            out[(size_t)grow * COUT + c] = acc[r] + bv;
        }
    }
}

// ---------------- GCN aggregation: out[d] = sum_e h[s]*dinv[s]*dinv[d] + h[d]*dinv[d]^2 + b
template <int COUT>
__global__ void gcn_agg(const float* __restrict__ h, const float* __restrict__ bias,
                        float* __restrict__ out) {
    int d = blockIdx.x;
    int c = threadIdx.x;
    float dd = d_dinv[d];
    float acc = h[(size_t)d * COUT + c] * dd * dd;
    int e0 = d_rowptr[d], e1 = d_rowptr[d + 1];
    for (int e = e0; e < e1; e++) {
        int s = d_csrsrc[e];
        acc = fmaf(h[(size_t)s * COUT + c], d_dinv[s] * dd, acc);
    }
    out[(size_t)d * COUT + c] = acc + bias[c];
}

// ---------------- BN affine precompute: a=gamma*rsqrt(var+eps), b=beta-mean*a ----------------
__global__ void bnaff_kernel(const float* __restrict__ g, const float* __restrict__ be,
                             const float* __restrict__ mn, const float* __restrict__ vr, int n) {
    int i = blockIdx.x * blockDim.x + threadIdx.x;
    if (i < n) {
        float a = g[i] * rsqrtf(vr[i] + 1e-5f);
        d_aAff[i] = a;
        d_bAff[i] = fmaf(-mn[i], a, be[i]);
    }
}

// ---------------- EdgeConv max-aggregation over Q(src,dst) ----------------
// out[d] = nE>0 ? P[d] + max_e ReLU(a*(x[s]-x[d])+b) @ Wbot : 0
// Persistent blocks; Wbot staged in smem; 4 warps x 4-edge batches (1 W-row read / 16 FFMA).
template <int C>
__global__ __launch_bounds__(128) void edge_agg(const float* __restrict__ xin,
                                                const float* __restrict__ aAff,
                                                const float* __restrict__ bAff,
                                                const float* __restrict__ Wbot,
                                                const float* __restrict__ Pv,
                                                float* __restrict__ out) {
    extern __shared__ float sm[];
    float* Wsh = sm;              // C*128
    float* xd  = Wsh + C * 128;   // C
    float* tb  = xd + C;          // 16*C (4 warps x 4 edges x C)
    float* red = tb + 16 * C;     // 4*128
    const int tid = threadIdx.x, lane = tid & 31, w = tid >> 5;

    for (int i = tid; i < C * 32; i += 128)
        ((float4*)Wsh)[i] = ((const float4*)Wbot)[i];
    __syncthreads();

    float* tw = tb + w * 4 * C;

    for (int d = blockIdx.x; d < NN; d += gridDim.x) {
        for (int k = tid; k < C; k += 128) xd[k] = xin[(size_t)d * C + k];
        __syncthreads();
        int e0 = d_rowptr[d], eEnd = d_rowptr[d + 1];
        int nE = eEnd - e0;
        float m0 = -3.4e38f, m1 = -3.4e38f, m2 = -3.4e38f, m3 = -3.4e38f;

        for (int base = e0 + w * 4; base < eEnd; base += 16) {
            int cnt = min(4, eEnd - base);
            // phase A: per-edge feature t = ReLU(a*(xs-xd)+b)
#pragma unroll
            for (int j = 0; j < 4; j++) {
                if (j < cnt) {
                    int s = d_csrsrc[base + j];
                    const float* xs = xin + (size_t)s * C;
                    for (int k = lane; k < C; k += 32) {
                        float v = fmaf(aAff[k], xs[k] - xd[k], bAff[k]);
                        tw[j * C + k] = fmaxf(v, 0.f);
                    }
                } else {
                    for (int k = lane; k < C; k += 32) tw[j * C + k] = 0.f;
                }
            }
            __syncwarp();
            // phase B: matvec for 4 edges simultaneously (share W row reads)
            float q00 = 0, q01 = 0, q02 = 0, q03 = 0;
            float q10 = 0, q11 = 0, q12 = 0, q13 = 0;
            float q20 = 0, q21 = 0, q22 = 0, q23 = 0;
            float q30 = 0, q31 = 0, q32 = 0, q33 = 0;
#pragma unroll 4
            for (int k = 0; k < C; k++) {
                float4 wv = *(const float4*)(Wsh + k * 128 + lane * 4);
                float t0 = tw[k], t1 = tw[C + k], t2 = tw[2 * C + k], t3 = tw[3 * C + k];
                q00 = fmaf(t0, wv.x, q00); q01 = fmaf(t0, wv.y, q01);
                q02 = fmaf(t0, wv.z, q02); q03 = fmaf(t0, wv.w, q03);
                q10 = fmaf(t1, wv.x, q10); q11 = fmaf(t1, wv.y, q11);
                q12 = fmaf(t1, wv.z, q12); q13 = fmaf(t1, wv.w, q13);
                q20 = fmaf(t2, wv.x, q20); q21 = fmaf(t2, wv.y, q21);
                q22 = fmaf(t2, wv.z, q22); q23 = fmaf(t2, wv.w, q23);
                q30 = fmaf(t3, wv.x, q30); q31 = fmaf(t3, wv.y, q31);
                q32 = fmaf(t3, wv.z, q32); q33 = fmaf(t3, wv.w, q33);
            }
            if (cnt > 0) { m0 = fmaxf(m0, q00); m1 = fmaxf(m1, q01); m2 = fmaxf(m2, q02); m3 = fmaxf(m3, q03); }
            if (cnt > 1) { m0 = fmaxf(m0, q10); m1 = fmaxf(m1, q11); m2 = fmaxf(m2, q12); m3 = fmaxf(m3, q13); }
            if (cnt > 2) { m0 = fmaxf(m0, q20); m1 = fmaxf(m1, q21); m2 = fmaxf(m2, q22); m3 = fmaxf(m3, q23); }
            if (cnt > 3) { m0 = fmaxf(m0, q30); m1 = fmaxf(m1, q31); m2 = fmaxf(m2, q32); m3 = fmaxf(m3, q33); }
            __syncwarp();
        }
        red[w * 128 + lane * 4 + 0] = m0;
        red[w * 128 + lane * 4 + 1] = m1;
        red[w * 128 + lane * 4 + 2] = m2;
        red[w * 128 + lane * 4 + 3] = m3;
        __syncthreads();
        float v = fmaxf(fmaxf(red[tid], red[128 + tid]), fmaxf(red[256 + tid], red[384 + tid]));
        out[(size_t)d * 128 + tid] = (nE > 0) ? Pv[(size_t)d * 128 + tid] + v : 0.f;
        __syncthreads();
    }
}

// ---------------- final FC: out[i] = h[i] @ Wfc + bfc ----------------
__global__ void fc_kernel(const float* __restrict__ h, const float* __restrict__ Wfc,
                          const float* __restrict__ bfc, float* __restrict__ out) {
    int w = threadIdx.x >> 5, lane = threadIdx.x & 31;
    int d = blockIdx.x * 4 + w;
    if (d >= NN) return;
    float s = 0.f;
#pragma unroll
    for (int u = 0; u < 4; u++) {
        int k = lane + 32 * u;
        s = fmaf(h[(size_t)d * 128 + k], Wfc[k], s);
    }
#pragma unroll
    for (int off = 16; off; off >>= 1) s += __shfl_down_sync(0xffffffffu, s, off);
    if (lane == 0) out[d] = s + bfc[0];
}

// ---------------- host ----------------
extern "C" void kernel_launch(void* const* d_in, const int* in_sizes, int n_in,
                              void* d_out, int out_size) {
    const float* x   = (const float*)d_in[0];
    const int*   ei  = (const int*)d_in[1];
    const float* Wm  = (const float*)d_in[2];
    const float* bm  = (const float*)d_in[3];
    const float* Wc  = (const float*)d_in[4];
    const float* bc  = (const float*)d_in[5];
    const float* Wg1 = (const float*)d_in[6];
    const float* bg1 = (const float*)d_in[7];
    const float* Wg2 = (const float*)d_in[8];
    const float* bg2 = (const float*)d_in[9];
    const float* Wg3 = (const float*)d_in[10];
    const float* bg3 = (const float*)d_in[11];
    const float* e1g = (const float*)d_in[12];
    const float* e1b = (const float*)d_in[13];
    const float* e1m = (const float*)d_in[14];
    const float* e1v = (const float*)d_in[15];
    const float* e1W = (const float*)d_in[16];
    const float* e2g = (const float*)d_in[17];
    const float* e2b = (const float*)d_in[18];
    const float* e2m = (const float*)d_in[19];
    const float* e2v = (const float*)d_in[20];
    const float* e2W = (const float*)d_in[21];
    const float* e3g = (const float*)d_in[22];
    const float* e3b = (const float*)d_in[23];
    const float* e3m = (const float*)d_in[24];
    const float* e3v = (const float*)d_in[25];
    const float* e3W = (const float*)d_in[26];
    const float* Wfc = (const float*)d_in[27];
    const float* bfc = (const float*)d_in[28];
    float* out = (float*)d_out;

    float *pA, *pB, *pH, *pX0, *pP, *pDa, *pDb;
    cudaGetSymbolAddress((void**)&pA,  d_bufA);
    cudaGetSymbolAddress((void**)&pB,  d_bufB);
    cudaGetSymbolAddress((void**)&pH,  d_h);
    cudaGetSymbolAddress((void**)&pX0, d_x0);
    cudaGetSymbolAddress((void**)&pP,  d_P);
    cudaGetSymbolAddress((void**)&pDa, d_aAff);
    cudaGetSymbolAddress((void**)&pDb, d_bAff);

    const int SM256 = (256 * 128 + 256 + 16 * 256 + 512) * 4;  // 150528 B
    const int SM128 = (128 * 128 + 128 + 16 * 128 + 512) * 4;  //  76288 B
    cudaFuncSetAttribute(edge_agg<256>, cudaFuncAttributeMaxDynamicSharedMemorySize, SM256);
    cudaFuncSetAttribute(edge_agg<128>, cudaFuncAttributeMaxDynamicSharedMemorySize, SM128);

    // CSR build
    zero_indeg_kernel<<<(NN + 255) / 256, 256>>>();
    count_kernel<<<(EE + 255) / 256, 256>>>(ei);
    scan_kernel<<<1, 1024>>>();
    fill_kernel<<<(EE + 255) / 256, 256>>>(ei);

    // dual projection: all rows with Wc, then overwrite rows 0::4 with Wm
    gemm_rows<512, 64, false><<<5000, 64>>>(x, Wc, bc, nullptr, nullptr, pX0, 0, 1, NN);
    gemm_rows<512, 64, false><<<1250, 64>>>(x, Wm, bm, nullptr, nullptr, pX0, 0, 4, 5000);

    // GCN stack
    gemm_rows<64, 128, false><<<5000, 128>>>(pX0, Wg1, nullptr, nullptr, nullptr, pH, 0, 1, NN);
    gcn_agg<128><<<NN, 128>>>(pH, bg1, pA);
    gemm_rows<128, 128, false><<<5000, 128>>>(pA, Wg2, nullptr, nullptr, nullptr, pH, 0, 1, NN);
    gcn_agg<128><<<NN, 128>>>(pH, bg2, pB);
    gemm_rows<128, 256, false><<<5000, 256>>>(pB, Wg3, nullptr, nullptr, nullptr, pH, 0, 1, NN);
    gcn_agg<256><<<NN, 256>>>(pH, bg3, pA);  // g3 -> pA [N,256]

    // EdgeConv 1 (C=256)
    bnaff_kernel<<<2, 256>>>(e1g, e1b, e1m, e1v, 512);
    gemm_rows<256, 128, true><<<5000, 128>>>(pA, e1W, nullptr, pDa, pDb, pP, 0, 1, NN);
    edge_agg<256><<<148, 128, SM256>>>(pA, pDa + 256, pDb + 256, e1W + 256 * 128, pP, pB);

    // EdgeConv 2 (C=128)
    bnaff_kernel<<<1, 256>>>(e2g, e2b, e2m, e2v, 256);
    gemm_rows<128, 128, true><<<5000, 128>>>(pB, e2W, nullptr, pDa, pDb, pP, 0, 1, NN);
    edge_agg<128><<<296, 128, SM128>>>(pB, pDa + 128, pDb + 128, e2W + 128 * 128, pP, pA);

    // EdgeConv 3 (C=128)
    bnaff_kernel<<<1, 256>>>(e3g, e3b, e3m, e3v, 256);
    gemm_rows<128, 128, true><<<5000, 128>>>(pA, e3W, nullptr, pDa, pDb, pP, 0, 1, NN);
    edge_agg<128><<<296, 128, SM128>>>(pA, pDa + 128, pDb + 128, e3W + 128 * 128, pP, pB);

    // final FC
    fc_kernel<<<5000, 128>>>(pB, Wfc, bfc, out);
}

// round 2
// speedup vs baseline: 2.1066x; 2.1066x over previous
#include <cuda_runtime.h>
#include <cuda_bf16.h>
#include <cstdint>

#define NN 20000
#define EE 320000

// ---------------- scratch (device globals; no allocation) ----------------
__device__ float d_bufA[NN * 256];
__device__ float d_bufB[NN * 256];
__device__ float d_h[NN * 256];
__device__ float d_x0[NN * 64];
__device__ float d_P[NN * 128];
__device__ float d_aAff[512];
__device__ float d_bAff[512];
__device__ float d_dinv[NN];
__device__ int   d_indeg[NN];
__device__ int   d_rowptr[NN + 1];
__device__ int   d_cursor[NN];
__device__ int   d_csrsrc[EE];

// ---------------- f32x2 packed helpers ----------------
__device__ __forceinline__ unsigned long long pack2(float x, float y) {
    unsigned long long r;
    unsigned a = __float_as_uint(x), b = __float_as_uint(y);
    asm("mov.b64 %0, {%1, %2};" : "=l"(r) : "r"(a), "r"(b));
    return r;
}
__device__ __forceinline__ unsigned long long bcast2(float x) {
    unsigned long long r;
    unsigned a = __float_as_uint(x);
    asm("mov.b64 %0, {%1, %1};" : "=l"(r) : "r"(a));
    return r;
}
__device__ __forceinline__ void fma2(unsigned long long& d, unsigned long long a, unsigned long long b) {
    asm("fma.rn.f32x2 %0, %1, %2, %0;" : "+l"(d) : "l"(a), "l"(b));
}
__device__ __forceinline__ float2 unpack2(unsigned long long v) {
    unsigned a, b;
    asm("mov.b64 {%0, %1}, %2;" : "=r"(a), "=r"(b) : "l"(v));
    return make_float2(__uint_as_float(a), __uint_as_float(b));
}

// ---------------- CSR build ----------------
__global__ void zero_indeg_kernel() {
    int i = blockIdx.x * blockDim.x + threadIdx.x;
    if (i < NN) d_indeg[i] = 0;
}

__global__ void count_kernel(const int* __restrict__ ei) {
    int i = blockIdx.x * blockDim.x + threadIdx.x;
    if (i < EE) atomicAdd(&d_indeg[ei[EE + i]], 1);
}

__global__ void scan_kernel() {
    __shared__ int sh[1024];
    __shared__ int carry;
    int tid = threadIdx.x;
    if (tid == 0) carry = 0;
    __syncthreads();
    for (int base = 0; base < NN; base += 1024) {
        int i = base + tid;
        int v = (i < NN) ? d_indeg[i] : 0;
        sh[tid] = v;
        __syncthreads();
        for (int off = 1; off < 1024; off <<= 1) {
            int t = (tid >= off) ? sh[tid - off] : 0;
            __syncthreads();
            sh[tid] += t;
            __syncthreads();
        }
        int incl = sh[tid];
        int base_c = carry;
        if (i < NN) {
            int excl = base_c + incl - v;
            d_rowptr[i] = excl;
            d_cursor[i] = excl;
            d_dinv[i] = rsqrtf((float)(v + 1));  // deg includes self-loop
        }
        __syncthreads();
        if (tid == 1023) carry = base_c + sh[1023];
        __syncthreads();
    }
    if (tid == 0) d_rowptr[NN] = carry;
}

__global__ void fill_kernel(const int* __restrict__ ei) {
    int i = blockIdx.x * blockDim.x + threadIdx.x;
    if (i < EE) {
        int s = ei[i];
        int d = ei[EE + i];
        int pos = atomicAdd(&d_cursor[d], 1);
        d_csrsrc[pos] = s;
    }
}

// ---------------- row GEMM: out = act(A) @ W (+bias), 8 rows/block, f32x2 ----------------
// blockDim = COUT. As interleaved with stride 10 so row pairs are LDS.64-loadable.
template <int K, int COUT, bool PRE>
__global__ void gemm_rows8(const float* __restrict__ A, const float* __restrict__ W,
                           const float* __restrict__ bias,
                           const float* __restrict__ aAff, const float* __restrict__ bAff,
                           float* __restrict__ out,
                           int rowStart, int rowStride, int numRows) {
    __shared__ float As[10 * K];
    int tid = threadIdx.x;
    int rblk = blockIdx.x * 8;
    for (int idx = tid; idx < 8 * K; idx += COUT) {
        int r = idx / K, k = idx - r * K;
        int rr = rblk + r;
        float v = 0.f;
        if (rr < numRows) {
            int grow = rowStart + rr * rowStride;
            v = A[(size_t)grow * K + k];
            if (PRE) v = fmaxf(fmaf(aAff[k], v, bAff[k]), 0.f);
        }
        As[k * 10 + r] = v;
    }
    __syncthreads();
    int c = tid;
    unsigned long long acc01 = 0, acc23 = 0, acc45 = 0, acc67 = 0;
#pragma unroll 4
    for (int k = 0; k < K; k++) {
        float wv = W[(size_t)k * COUT + c];
        unsigned long long ww = bcast2(wv);
        const float* row = As + k * 10;
        float2 a01 = *(const float2*)(row + 0);
        float2 a23 = *(const float2*)(row + 2);
        float2 a45 = *(const float2*)(row + 4);
        float2 a67 = *(const float2*)(row + 6);
        fma2(acc01, pack2(a01.x, a01.y), ww);
        fma2(acc23, pack2(a23.x, a23.y), ww);
        fma2(acc45, pack2(a45.x, a45.y), ww);
        fma2(acc67, pack2(a67.x, a67.y), ww);
    }
    float bv = bias ? bias[c] : 0.f;
    float res[8];
    float2 t;
    t = unpack2(acc01); res[0] = t.x; res[1] = t.y;
    t = unpack2(acc23); res[2] = t.x; res[3] = t.y;
    t = unpack2(acc45); res[4] = t.x; res[5] = t.y;
    t = unpack2(acc67); res[6] = t.x; res[7] = t.y;
#pragma unroll
    for (int r = 0; r < 8; r++) {
        int rr = rblk + r;
        if (rr < numRows) {
            int grow = rowStart + rr * rowStride;
            out[(size_t)grow * COUT + c] = res[r] + bv;
        }
    }
}

// ---------------- GCN aggregation ----------------
template <int COUT>
__global__ void gcn_agg(const float* __restrict__ h, const float* __restrict__ bias,
                        float* __restrict__ out) {
    int d = blockIdx.x;
    int c = threadIdx.x;
    float dd = d_dinv[d];
    float acc = h[(size_t)d * COUT + c] * dd * dd;
    int e0 = d_rowptr[d], e1 = d_rowptr[d + 1];
    for (int e = e0; e < e1; e++) {
        int s = d_csrsrc[e];
        acc = fmaf(h[(size_t)s * COUT + c], d_dinv[s] * dd, acc);
    }
    out[(size_t)d * COUT + c] = acc + bias[c];
}

// ---------------- BN affine precompute ----------------
__global__ void bnaff_kernel(const float* __restrict__ g, const float* __restrict__ be,
                             const float* __restrict__ mn, const float* __restrict__ vr, int n) {
    int i = blockIdx.x * blockDim.x + threadIdx.x;
    if (i < n) {
        float a = g[i] * rsqrtf(vr[i] + 1e-5f);
        d_aAff[i] = a;
        d_bAff[i] = fmaf(-mn[i], a, be[i]);
    }
}

// ---------------- y = a ⊙ x (per-channel scale) ----------------
template <int C>
__global__ void scale_kernel(const float* __restrict__ x, const float* __restrict__ a,
                             float* __restrict__ y) {
    int i = blockIdx.x * blockDim.x + threadIdx.x;  // over float4s
    int n4 = NN * C / 4;
    if (i < n4) {
        float4 v = ((const float4*)x)[i];
        int k4 = i & (C / 4 - 1);
        float4 av = ((const float4*)a)[k4];
        v.x *= av.x; v.y *= av.y; v.z *= av.z; v.w *= av.w;
        ((float4*)y)[i] = v;
    }
}

// ---------------- EdgeConv max-aggregation ----------------
// out[d] = nE>0 ? P[d] + max_e ReLU(y[s] - (y[d]-b)) @ Wbot : 0
// One node per WARP, 8-edge batches, f32x2 matvec. 8 warps/block.
template <int C>
__global__ __launch_bounds__(256) void edge_agg(const float* __restrict__ y,
                                                const float* __restrict__ bAff,
                                                const float* __restrict__ Wbot,
                                                const float* __restrict__ Pv,
                                                float* __restrict__ out) {
    extern __shared__ float sm[];
    float* Wsh = sm;                // C*128
    float* zs = Wsh + C * 128;      // 8*C   per-warp z_d
    float* tb = zs + 8 * C;         // 8*8*C per-warp edge features
    const int tid = threadIdx.x, lane = tid & 31, w = tid >> 5;

    for (int i = tid; i < C * 32; i += 256)
        ((float4*)Wsh)[i] = ((const float4*)Wbot)[i];
    __syncthreads();

    float* zd = zs + w * C;
    float* tw = tb + w * 8 * C;
    const int nwarps = gridDim.x * 8;

    for (int d = blockIdx.x * 8 + w; d < NN; d += nwarps) {
        int e0 = d_rowptr[d], eE = d_rowptr[d + 1];
        int nE = eE - e0;
        float4 m4 = make_float4(-3.4e38f, -3.4e38f, -3.4e38f, -3.4e38f);
        if (nE > 0) {
            // stage z_d = y_d - b
            for (int k4 = lane; k4 < C / 4; k4 += 32) {
                float4 yv = ((const float4*)(y + (size_t)d * C))[k4];
                float4 bv = ((const float4*)bAff)[k4];
                yv.x -= bv.x; yv.y -= bv.y; yv.z -= bv.z; yv.w -= bv.w;
                ((float4*)zd)[k4] = yv;
            }
            __syncwarp();
            for (int base = e0; base < eE; base += 8) {
                int cnt = min(8, eE - base);
                // phase A: t_j = ReLU(y_s - z_d)
#pragma unroll
                for (int j = 0; j < 8; j++) {
                    float4* twj = (float4*)(tw + j * C);
                    if (j < cnt) {
                        int s = d_csrsrc[base + j];
                        const float4* ys = (const float4*)(y + (size_t)s * C);
                        for (int k4 = lane; k4 < C / 4; k4 += 32) {
                            float4 v = ys[k4];
                            float4 z = ((const float4*)zd)[k4];
                            v.x = fmaxf(v.x - z.x, 0.f);
                            v.y = fmaxf(v.y - z.y, 0.f);
                            v.z = fmaxf(v.z - z.z, 0.f);
                            v.w = fmaxf(v.w - z.w, 0.f);
                            twj[k4] = v;
                        }
                    } else {
                        float4 zr = make_float4(0.f, 0.f, 0.f, 0.f);
                        for (int k4 = lane; k4 < C / 4; k4 += 32) twj[k4] = zr;
                    }
                }
                __syncwarp();
                // phase B: 8-edge x 4-col packed matvec
                unsigned long long q01[8], q23[8];
#pragma unroll
                for (int j = 0; j < 8; j++) { q01[j] = 0ull; q23[j] = 0ull; }
                for (int k0 = 0; k0 < C; k0 += 4) {
                    float4 t4[8];
#pragma unroll
                    for (int j = 0; j < 8; j++) t4[j] = *(const float4*)(tw + j * C + k0);
#pragma unroll
                    for (int kk = 0; kk < 4; kk++) {
                        float4 wv = *(const float4*)(Wsh + (size_t)(k0 + kk) * 128 + lane * 4);
                        unsigned long long w01 = pack2(wv.x, wv.y);
                        unsigned long long w23 = pack2(wv.z, wv.w);
#pragma unroll
                        for (int j = 0; j < 8; j++) {
                            float tv = (kk == 0) ? t4[j].x : (kk == 1) ? t4[j].y
                                     : (kk == 2) ? t4[j].z : t4[j].w;
                            unsigned long long tt = bcast2(tv);
                            fma2(q01[j], tt, w01);
                            fma2(q23[j], tt, w23);
                        }
                    }
                }
#pragma unroll
                for (int j = 0; j < 8; j++) {
                    if (j < cnt) {
                        float2 a = unpack2(q01[j]);
                        float2 b2 = unpack2(q23[j]);
                        m4.x = fmaxf(m4.x, a.x);
                        m4.y = fmaxf(m4.y, a.y);
                        m4.z = fmaxf(m4.z, b2.x);
                        m4.w = fmaxf(m4.w, b2.y);
                    }
                }
                __syncwarp();
            }
            float4 p = ((const float4*)(Pv + (size_t)d * 128))[lane];
            m4.x += p.x; m4.y += p.y; m4.z += p.z; m4.w += p.w;
        } else {
            m4 = make_float4(0.f, 0.f, 0.f, 0.f);
        }
        ((float4*)(out + (size_t)d * 128))[lane] = m4;
    }
}

// ---------------- final FC ----------------
__global__ void fc_kernel(const float* __restrict__ h, const float* __restrict__ Wfc,
                          const float* __restrict__ bfc, float* __restrict__ out) {
    int w = threadIdx.x >> 5, lane = threadIdx.x & 31;
    int d = blockIdx.x * 4 + w;
    if (d >= NN) return;
    float s = 0.f;
#pragma unroll
    for (int u = 0; u < 4; u++) {
        int k = lane + 32 * u;
        s = fmaf(h[(size_t)d * 128 + k], Wfc[k], s);
    }
#pragma unroll
    for (int off = 16; off; off >>= 1) s += __shfl_down_sync(0xffffffffu, s, off);
    if (lane == 0) out[d] = s + bfc[0];
}

// ---------------- host ----------------
extern "C" void kernel_launch(void* const* d_in, const int* in_sizes, int n_in,
                              void* d_out, int out_size) {
    const float* x   = (const float*)d_in[0];
    const int*   ei  = (const int*)d_in[1];
    const float* Wm  = (const float*)d_in[2];
    const float* bm  = (const float*)d_in[3];
    const float* Wc  = (const float*)d_in[4];
    const float* bc  = (const float*)d_in[5];
    const float* Wg1 = (const float*)d_in[6];
    const float* bg1 = (const float*)d_in[7];
    const float* Wg2 = (const float*)d_in[8];
    const float* bg2 = (const float*)d_in[9];
    const float* Wg3 = (const float*)d_in[10];
    const float* bg3 = (const float*)d_in[11];
    const float* e1g = (const float*)d_in[12];
    const float* e1b = (const float*)d_in[13];
    const float* e1m = (const float*)d_in[14];
    const float* e1v = (const float*)d_in[15];
    const float* e1W = (const float*)d_in[16];
    const float* e2g = (const float*)d_in[17];
    const float* e2b = (const float*)d_in[18];
    const float* e2m = (const float*)d_in[19];
    const float* e2v = (const float*)d_in[20];
    const float* e2W = (const float*)d_in[21];
    const float* e3g = (const float*)d_in[22];
    const float* e3b = (const float*)d_in[23];
    const float* e3m = (const float*)d_in[24];
    const float* e3v = (const float*)d_in[25];
    const float* e3W = (const float*)d_in[26];
    const float* Wfc = (const float*)d_in[27];
    const float* bfc = (const float*)d_in[28];
    float* out = (float*)d_out;

    float *pA, *pB, *pH, *pX0, *pP, *pDa, *pDb;
    cudaGetSymbolAddress((void**)&pA,  d_bufA);
    cudaGetSymbolAddress((void**)&pB,  d_bufB);
    cudaGetSymbolAddress((void**)&pH,  d_h);
    cudaGetSymbolAddress((void**)&pX0, d_x0);
    cudaGetSymbolAddress((void**)&pP,  d_P);
    cudaGetSymbolAddress((void**)&pDa, d_aAff);
    cudaGetSymbolAddress((void**)&pDb, d_bAff);

    const int SM256 = (256 * 128 + 8 * 256 + 64 * 256) * 4;  // 204800 B
    const int SM128 = (128 * 128 + 8 * 128 + 64 * 128) * 4;  // 102400 B
    cudaFuncSetAttribute(edge_agg<256>, cudaFuncAttributeMaxDynamicSharedMemorySize, SM256);
    cudaFuncSetAttribute(edge_agg<128>, cudaFuncAttributeMaxDynamicSharedMemorySize, SM128);

    // CSR build
    zero_indeg_kernel<<<(NN + 255) / 256, 256>>>();
    count_kernel<<<(EE + 255) / 256, 256>>>(ei);
    scan_kernel<<<1, 1024>>>();
    fill_kernel<<<(EE + 255) / 256, 256>>>(ei);

    // dual projection: all rows with Wc, then overwrite rows 0::4 with Wm
    gemm_rows8<512, 64, false><<<2500, 64>>>(x, Wc, bc, nullptr, nullptr, pX0, 0, 1, NN);
    gemm_rows8<512, 64, false><<<625, 64>>>(x, Wm, bm, nullptr, nullptr, pX0, 0, 4, 5000);

    // GCN stack
    gemm_rows8<64, 128, false><<<2500, 128>>>(pX0, Wg1, nullptr, nullptr, nullptr, pH, 0, 1, NN);
    gcn_agg<128><<<NN, 128>>>(pH, bg1, pA);
    gemm_rows8<128, 128, false><<<2500, 128>>>(pA, Wg2, nullptr, nullptr, nullptr, pH, 0, 1, NN);
    gcn_agg<128><<<NN, 128>>>(pH, bg2, pB);
    gemm_rows8<128, 256, false><<<2500, 256>>>(pB, Wg3, nullptr, nullptr, nullptr, pH, 0, 1, NN);
    gcn_agg<256><<<NN, 256>>>(pH, bg3, pA);  // g3 -> pA [N,256]

    // EdgeConv 1 (C=256): x = pA
    bnaff_kernel<<<2, 256>>>(e1g, e1b, e1m, e1v, 512);
    gemm_rows8<256, 128, true><<<2500, 128>>>(pA, e1W, nullptr, pDa, pDb, pP, 0, 1, NN);
    scale_kernel<256><<<(NN * 256 / 4 + 255) / 256, 256>>>(pA, pDa + 256, pH);
    edge_agg<256><<<148, 256, SM256>>>(pH, pDb + 256, e1W + 256 * 128, pP, pB);

    // EdgeConv 2 (C=128): x = pB
    bnaff_kernel<<<1, 256>>>(e2g, e2b, e2m, e2v, 256);
    gemm_rows8<128, 128, true><<<2500, 128>>>(pB, e2W, nullptr, pDa, pDb, pP, 0, 1, NN);
    scale_kernel<128><<<(NN * 128 / 4 + 255) / 256, 256>>>(pB, pDa + 128, pH);
    edge_agg<128><<<296, 256, SM128>>>(pH, pDb + 128, e2W + 128 * 128, pP, pA);

    // EdgeConv 3 (C=128): x = pA
    bnaff_kernel<<<1, 256>>>(e3g, e3b, e3m, e3v, 256);
    gemm_rows8<128, 128, true><<<2500, 128>>>(pA, e3W, nullptr, pDa, pDb, pP, 0, 1, NN);
    scale_kernel<128><<<(NN * 128 / 4 + 255) / 256, 256>>>(pA, pDa + 128, pH);
    edge_agg<128><<<296, 256, SM128>>>(pH, pDb + 128, e3W + 128 * 128, pP, pB);

    // final FC
    fc_kernel<<<5000, 128>>>(pB, Wfc, bfc, out);
}

// round 4
// speedup vs baseline: 2.8595x; 1.3574x over previous
#include <cuda_runtime.h>
#include <cuda_bf16.h>
#include <cstdint>

#define NN 20000
#define EE 320000

// ---------------- scratch (device globals; no allocation) ----------------
__device__ float d_bufA[NN * 256];
__device__ float d_bufB[NN * 256];
__device__ float d_h[NN * 256];
__device__ float d_x0[NN * 64];
__device__ float d_P[NN * 128];
__device__ float d_aAff[512];
__device__ float d_bAff[512];
__device__ float d_dinv[NN];
__device__ int   d_indeg[NN];
__device__ int   d_rowptr[NN + 1];
__device__ int   d_cursor[NN];
__device__ int   d_csrsrc[EE];
__device__ int   d_csrdst[EE];
__device__ __nv_bfloat16 d_Whi[256 * 128];
__device__ __nv_bfloat16 d_Wlo[256 * 128];
__device__ unsigned d_tmpmax[NN * 128];

// ---------------- f32x2 packed helpers ----------------
__device__ __forceinline__ unsigned long long pack2(float x, float y) {
    unsigned long long r;
    unsigned a = __float_as_uint(x), b = __float_as_uint(y);
    asm("mov.b64 %0, {%1, %2};" : "=l"(r) : "r"(a), "r"(b));
    return r;
}
__device__ __forceinline__ unsigned long long bcast2(float x) {
    unsigned long long r;
    unsigned a = __float_as_uint(x);
    asm("mov.b64 %0, {%1, %1};" : "=l"(r) : "r"(a));
    return r;
}
__device__ __forceinline__ void fma2(unsigned long long& d, unsigned long long a, unsigned long long b) {
    asm("fma.rn.f32x2 %0, %1, %2, %0;" : "+l"(d) : "l"(a), "l"(b));
}
__device__ __forceinline__ float2 unpack2(unsigned long long v) {
    unsigned a, b;
    asm("mov.b64 {%0, %1}, %2;" : "=r"(a), "=r"(b) : "l"(v));
    return make_float2(__uint_as_float(a), __uint_as_float(b));
}

// ---------------- warp MMA helpers (sm_80+ ISA, no arch-feature suffix) ----------------
__device__ __forceinline__ uint32_t smem_u32(const void* p) {
    uint32_t a;
    asm("{ .reg .u64 t; cvta.to.shared.u64 t, %1; cvt.u32.u64 %0, t; }" : "=r"(a) : "l"(p));
    return a;
}
__device__ __forceinline__ void ldsm4(uint32_t* r, uint32_t addr) {
    asm volatile("ldmatrix.sync.aligned.m8n8.x4.shared.b16 {%0,%1,%2,%3}, [%4];"
                 : "=r"(r[0]), "=r"(r[1]), "=r"(r[2]), "=r"(r[3]) : "r"(addr));
}
__device__ __forceinline__ void ldsm2(uint32_t* r, uint32_t addr) {
    asm volatile("ldmatrix.sync.aligned.m8n8.x2.shared.b16 {%0,%1}, [%2];"
                 : "=r"(r[0]), "=r"(r[1]) : "r"(addr));
}
__device__ __forceinline__ void mma16816(float* d, const uint32_t* a, const uint32_t* b) {
    asm volatile("mma.sync.aligned.m16n8k16.row.col.f32.bf16.bf16.f32 "
                 "{%0,%1,%2,%3}, {%4,%5,%6,%7}, {%8,%9}, {%0,%1,%2,%3};"
                 : "+f"(d[0]), "+f"(d[1]), "+f"(d[2]), "+f"(d[3])
                 : "r"(a[0]), "r"(a[1]), "r"(a[2]), "r"(a[3]), "r"(b[0]), "r"(b[1]));
}

__device__ __forceinline__ unsigned encf(float x) {
    unsigned s = __float_as_uint(x);
    return (s & 0x80000000u) ? ~s : (s | 0x80000000u);
}
__device__ __forceinline__ float decf(unsigned u) {
    return (u & 0x80000000u) ? __uint_as_float(u ^ 0x80000000u) : __uint_as_float(~u);
}
__device__ __forceinline__ void split2(float a, float b, uint32_t& hi, uint32_t& lo) {
    __nv_bfloat16 ha = __float2bfloat16_rn(a), hb = __float2bfloat16_rn(b);
    __nv_bfloat16 la = __float2bfloat16_rn(a - __bfloat162float(ha));
    __nv_bfloat16 lb = __float2bfloat16_rn(b - __bfloat162float(hb));
    hi = (uint32_t)__bfloat16_as_ushort(ha) | ((uint32_t)__bfloat16_as_ushort(hb) << 16);
    lo = (uint32_t)__bfloat16_as_ushort(la) | ((uint32_t)__bfloat16_as_ushort(lb) << 16);
}

// ---------------- CSR build ----------------
__global__ void zero_indeg_kernel() {
    int i = blockIdx.x * blockDim.x + threadIdx.x;
    if (i < NN) d_indeg[i] = 0;
}
__global__ void count_kernel(const int* __restrict__ ei) {
    int i = blockIdx.x * blockDim.x + threadIdx.x;
    if (i < EE) atomicAdd(&d_indeg[ei[EE + i]], 1);
}
__global__ void scan_kernel() {
    __shared__ int sh[1024];
    __shared__ int carry;
    int tid = threadIdx.x;
    if (tid == 0) carry = 0;
    __syncthreads();
    for (int base = 0; base < NN; base += 1024) {
        int i = base + tid;
        int v = (i < NN) ? d_indeg[i] : 0;
        sh[tid] = v;
        __syncthreads();
        for (int off = 1; off < 1024; off <<= 1) {
            int t = (tid >= off) ? sh[tid - off] : 0;
            __syncthreads();
            sh[tid] += t;
            __syncthreads();
        }
        int incl = sh[tid];
        int base_c = carry;
        if (i < NN) {
            int excl = base_c + incl - v;
            d_rowptr[i] = excl;
            d_cursor[i] = excl;
            d_dinv[i] = rsqrtf((float)(v + 1));
        }
        __syncthreads();
        if (tid == 1023) carry = base_c + sh[1023];
        __syncthreads();
    }
    if (tid == 0) d_rowptr[NN] = carry;
}
__global__ void fill_kernel(const int* __restrict__ ei) {
    int i = blockIdx.x * blockDim.x + threadIdx.x;
    if (i < EE) {
        int s = ei[i];
        int d = ei[EE + i];
        int pos = atomicAdd(&d_cursor[d], 1);
        d_csrsrc[pos] = s;
        d_csrdst[pos] = d;
    }
}

// ---------------- row GEMM (f32x2), 8 rows/block ----------------
template <int K, int COUT, bool PRE>
__global__ void gemm_rows8(const float* __restrict__ A, const float* __restrict__ W,
                           const float* __restrict__ bias,
                           const float* __restrict__ aAff, const float* __restrict__ bAff,
                           float* __restrict__ out,
                           int rowStart, int rowStride, int numRows) {
    __shared__ float As[10 * K];
    int tid = threadIdx.x;
    int rblk = blockIdx.x * 8;
    for (int idx = tid; idx < 8 * K; idx += COUT) {
        int r = idx / K, k = idx - r * K;
        int rr = rblk + r;
        float v = 0.f;
        if (rr < numRows) {
            int grow = rowStart + rr * rowStride;
            v = A[(size_t)grow * K + k];
            if (PRE) v = fmaxf(fmaf(aAff[k], v, bAff[k]), 0.f);
        }
        As[k * 10 + r] = v;
    }
    __syncthreads();
    int c = tid;
    unsigned long long acc01 = 0, acc23 = 0, acc45 = 0, acc67 = 0;
#pragma unroll 4
    for (int k = 0; k < K; k++) {
        float wv = W[(size_t)k * COUT + c];
        unsigned long long ww = bcast2(wv);
        const float* row = As + k * 10;
        float2 a01 = *(const float2*)(row + 0);
        float2 a23 = *(const float2*)(row + 2);
        float2 a45 = *(const float2*)(row + 4);
        float2 a67 = *(const float2*)(row + 6);
        fma2(acc01, pack2(a01.x, a01.y), ww);
        fma2(acc23, pack2(a23.x, a23.y), ww);
        fma2(acc45, pack2(a45.x, a45.y), ww);
        fma2(acc67, pack2(a67.x, a67.y), ww);
    }
    float bv = bias ? bias[c] : 0.f;
    float res[8];
    float2 t;
    t = unpack2(acc01); res[0] = t.x; res[1] = t.y;
    t = unpack2(acc23); res[2] = t.x; res[3] = t.y;
    t = unpack2(acc45); res[4] = t.x; res[5] = t.y;
    t = unpack2(acc67); res[6] = t.x; res[7] = t.y;
#pragma unroll
    for (int r = 0; r < 8; r++) {
        int rr = rblk + r;
        if (rr < numRows) {
            int grow = rowStart + rr * rowStride;
            out[(size_t)grow * COUT + c] = res[r] + bv;
        }
    }
}

// ---------------- GCN aggregation ----------------
template <int COUT>
__global__ void gcn_agg(const float* __restrict__ h, const float* __restrict__ bias,
                        float* __restrict__ out) {
    int d = blockIdx.x;
    int c = threadIdx.x;
    float dd = d_dinv[d];
    float acc = h[(size_t)d * COUT + c] * dd * dd;
    int e0 = d_rowptr[d], e1 = d_rowptr[d + 1];
    for (int e = e0; e < e1; e++) {
        int s = d_csrsrc[e];
        acc = fmaf(h[(size_t)s * COUT + c], d_dinv[s] * dd, acc);
    }
    out[(size_t)d * COUT + c] = acc + bias[c];
}

// ---------------- BN affine precompute ----------------
__global__ void bnaff_kernel(const float* __restrict__ g, const float* __restrict__ be,
                             const float* __restrict__ mn, const float* __restrict__ vr, int n) {
    int i = blockIdx.x * blockDim.x + threadIdx.x;
    if (i < n) {
        float a = g[i] * rsqrtf(vr[i] + 1e-5f);
        d_aAff[i] = a;
        d_bAff[i] = fmaf(-mn[i], a, be[i]);
    }
}

// ---------------- y = a ⊙ x ----------------
template <int C>
__global__ void scale_kernel(const float* __restrict__ x, const float* __restrict__ a,
                             float* __restrict__ y) {
    int i = blockIdx.x * blockDim.x + threadIdx.x;
    int n4 = NN * C / 4;
    if (i < n4) {
        float4 v = ((const float4*)x)[i];
        int k4 = i & (C / 4 - 1);
        float4 av = ((const float4*)a)[k4];
        v.x *= av.x; v.y *= av.y; v.z *= av.z; v.w *= av.w;
        ((float4*)y)[i] = v;
    }
}

// ---------------- W split/transpose: Wt[n][k] = bf16split(W[k][n]) ----------------
__global__ void wsplit_kernel(const float* __restrict__ W, int C) {
    int id = blockIdx.x * blockDim.x + threadIdx.x;
    if (id < C * 128) {
        int k = id >> 7, n = id & 127;
        float w = W[id];
        __nv_bfloat16 hi = __float2bfloat16_rn(w);
        __nv_bfloat16 lo = __float2bfloat16_rn(w - __bfloat162float(hi));
        d_Whi[n * C + k] = hi;
        d_Wlo[n * C + k] = lo;
    }
}

// ---------------- init tmpmax to 0 (= -inf under encf ordering) ----------------
__global__ void init_tmp_kernel() {
    int i = blockIdx.x * blockDim.x + threadIdx.x;
    if (i < NN * 128 / 4) ((uint4*)d_tmpmax)[i] = make_uint4(0, 0, 0, 0);
}

// ---------------- EdgeConv via bf16-split mma.sync ----------------
// Tile = 128 edges x 128 outs, K = C. Q = ReLU(y[s]-y[d]+b) @ Wbot.
// 8 warps, warp = 16 edge rows x 128 cols. Epilogue: segmented max + atomicMax.
template <int C>
__global__ __launch_bounds__(256, 1) void edge_mma_kernel(const float* __restrict__ y,
                                                          const float* __restrict__ bAff) {
    constexpr int NCH = C / 64;
    constexpr int ASTRIDE = 72;                 // bf16 per A row (64 + pad)
    constexpr int ABYTES = 128 * ASTRIDE * 2;   // 18432 per half
    constexpr int AHI = 0, ALO = ABYTES, BOFF = 2 * ABYTES;  // B at 36864
    constexpr int BSTRIDE = C + 8;              // bf16 per Wt row
    constexpr int BHALF = 128 * BSTRIDE * 2;    // bytes per half
    extern __shared__ char smem[];
    float* buf = (float*)smem;                  // epilogue staging (128*33 f32), aliases A
    uint32_t sb = smem_u32(smem);
    const int tid = threadIdx.x, lane = tid & 31, w = tid >> 5;
    const unsigned fullm = 0xFFFFFFFFu;

    // stage Wt hi/lo into padded SMEM (once per block)
    for (int idx = tid; idx < C * 128 / 8; idx += 256) {
        int n = idx / (C / 8), kb = (idx % (C / 8)) * 8;
        uint32_t off = BOFF + (uint32_t)(n * BSTRIDE + kb) * 2;
        *(uint4*)(smem + off) = ((const uint4*)d_Whi)[idx];
        *(uint4*)(smem + off + BHALF) = ((const uint4*)d_Wlo)[idx];
    }

    const int arow = tid >> 1, ahalf = tid & 1;  // staging: thread = (row, 32-k half)

    for (int t = blockIdx.x; t < EE / 128; t += gridDim.x) {
        float acc[16][4];
#pragma unroll
        for (int i = 0; i < 16; i++) { acc[i][0] = acc[i][1] = acc[i][2] = acc[i][3] = 0.f; }

        const int sA = d_csrsrc[t * 128 + arow];
        const int dA = d_csrdst[t * 128 + arow];

        for (int ch = 0; ch < NCH; ch++) {
            __syncthreads();
            // stage A chunk: feature = ReLU(y_s - y_d + b), split to bf16 hi/lo
            {
                int kb = ch * 64 + ahalf * 32;
                const float4* ys = (const float4*)(y + (size_t)sA * C + kb);
                const float4* yd = (const float4*)(y + (size_t)dA * C + kb);
                const float4* bb = (const float4*)(bAff + kb);
#pragma unroll
                for (int q = 0; q < 4; q++) {
                    float4 a0 = ys[q * 2], a1 = ys[q * 2 + 1];
                    float4 b0 = yd[q * 2], b1 = yd[q * 2 + 1];
                    float4 c0 = __ldg(bb + q * 2), c1 = __ldg(bb + q * 2 + 1);
                    float v0 = fmaxf(a0.x - b0.x + c0.x, 0.f);
                    float v1 = fmaxf(a0.y - b0.y + c0.y, 0.f);
                    float v2 = fmaxf(a0.z - b0.z + c0.z, 0.f);
                    float v3 = fmaxf(a0.w - b0.w + c0.w, 0.f);
                    float v4 = fmaxf(a1.x - b1.x + c1.x, 0.f);
                    float v5 = fmaxf(a1.y - b1.y + c1.y, 0.f);
                    float v6 = fmaxf(a1.z - b1.z + c1.z, 0.f);
                    float v7 = fmaxf(a1.w - b1.w + c1.w, 0.f);
                    uint4 H, L;
                    split2(v0, v1, H.x, L.x);
                    split2(v2, v3, H.y, L.y);
                    split2(v4, v5, H.z, L.z);
                    split2(v6, v7, H.w, L.w);
                    uint32_t off = (uint32_t)(arow * ASTRIDE + ahalf * 32 + q * 8) * 2;
                    *(uint4*)(smem + AHI + off) = H;
                    *(uint4*)(smem + ALO + off) = L;
                }
            }
            __syncthreads();
            // MMA over the chunk (4 k-steps of 16)
#pragma unroll
            for (int ks = 0; ks < 4; ks++) {
                uint32_t ah[4], al[4];
                uint32_t aaddr = sb + AHI +
                    (uint32_t)((w * 16 + (lane & 15)) * ASTRIDE + ks * 16 + (lane >> 4) * 8) * 2;
                ldsm4(ah, aaddr);
                ldsm4(al, aaddr + ABYTES);
                int tt = lane & 15;
                uint32_t brow = tt & 7, bsel = tt >> 3;
#pragma unroll
                for (int nt = 0; nt < 16; nt++) {
                    uint32_t baddr = sb + BOFF +
                        (uint32_t)((nt * 8 + brow) * BSTRIDE + ch * 64 + ks * 16 + bsel * 8) * 2;
                    uint32_t bh[2], bl[2];
                    ldsm2(bh, baddr);
                    ldsm2(bl, baddr + BHALF);
                    mma16816(acc[nt], ah, bh);
                    mma16816(acc[nt], ah, bl);
                    mma16816(acc[nt], al, bh);
                }
            }
        }
        // ---- epilogue: segmented max over CSR runs ----
        int erow = t * 128 + (w & 3) * 32 + lane;
        int dl = d_csrdst[erow];
        int prev = __shfl_up_sync(fullm, dl, 1);
        bool head = (lane == 0) || (dl != prev);
        unsigned Hb = __ballot_sync(fullm, head);
        unsigned mle;
        asm("mov.u32 %0, %%lanemask_le;" : "=r"(mle));
        int run_start = 31 - __clz(Hb & mle);
        bool tail = (lane == 31) || ((Hb >> (lane + 1)) & 1);
        unsigned* trow = d_tmpmax + (size_t)dl * 128;
#pragma unroll
        for (int g = 0; g < 4; g++) {
            __syncthreads();
#pragma unroll
            for (int q = 0; q < 4; q++) {
                int nt = g * 4 + q;
                int lcol = q * 8 + (lane & 3) * 2;
                int r0 = w * 16 + (lane >> 2);
                buf[r0 * 33 + lcol]           = acc[nt][0];
                buf[r0 * 33 + lcol + 1]       = acc[nt][1];
                buf[(r0 + 8) * 33 + lcol]     = acc[nt][2];
                buf[(r0 + 8) * 33 + lcol + 1] = acc[nt][3];
            }
            __syncthreads();
            int rr = (w & 3) * 32 + lane;
            int cb = (w >> 2) * 16;
            float v[16];
#pragma unroll
            for (int j = 0; j < 16; j++) v[j] = buf[rr * 33 + cb + j];
#pragma unroll
            for (int dlt = 1; dlt < 32; dlt <<= 1) {
#pragma unroll
                for (int j = 0; j < 16; j++) {
                    float u = __shfl_up_sync(fullm, v[j], dlt);
                    if ((int)lane - dlt >= run_start) v[j] = fmaxf(v[j], u);
                }
            }
            if (tail) {
#pragma unroll
                for (int j = 0; j < 16; j++) atomicMax(trow + g * 32 + cb + j, encf(v[j]));
            }
        }
    }
}

// ---------------- finalize: out[d] = deg>0 ? P[d] + dec(tmp[d]) : 0 ----------------
__global__ void edge_final_kernel(const float* __restrict__ P, float* __restrict__ out) {
    int i = blockIdx.x * blockDim.x + threadIdx.x;
    if (i < NN * 128) {
        int d = i >> 7;
        float r = 0.f;
        if (d_indeg[d] > 0) r = P[i] + decf(d_tmpmax[i]);
        out[i] = r;
    }
}

// ---------------- final FC ----------------
__global__ void fc_kernel(const float* __restrict__ h, const float* __restrict__ Wfc,
                          const float* __restrict__ bfc, float* __restrict__ out) {
    int w = threadIdx.x >> 5, lane = threadIdx.x & 31;
    int d = blockIdx.x * 4 + w;
    if (d >= NN) return;
    float s = 0.f;
#pragma unroll
    for (int u = 0; u < 4; u++) {
        int k = lane + 32 * u;
        s = fmaf(h[(size_t)d * 128 + k], Wfc[k], s);
    }
#pragma unroll
    for (int off = 16; off; off >>= 1) s += __shfl_down_sync(0xffffffffu, s, off);
    if (lane == 0) out[d] = s + bfc[0];
}

// ---------------- host ----------------
extern "C" void kernel_launch(void* const* d_in, const int* in_sizes, int n_in,
                              void* d_out, int out_size) {
    const float* x   = (const float*)d_in[0];
    const int*   ei  = (const int*)d_in[1];
    const float* Wm  = (const float*)d_in[2];
    const float* bm  = (const float*)d_in[3];
    const float* Wc  = (const float*)d_in[4];
    const float* bc  = (const float*)d_in[5];
    const float* Wg1 = (const float*)d_in[6];
    const float* bg1 = (const float*)d_in[7];
    const float* Wg2 = (const float*)d_in[8];
    const float* bg2 = (const float*)d_in[9];
    const float* Wg3 = (const float*)d_in[10];
    const float* bg3 = (const float*)d_in[11];
    const float* e1g = (const float*)d_in[12];
    const float* e1b = (const float*)d_in[13];
    const float* e1m = (const float*)d_in[14];
    const float* e1v = (const float*)d_in[15];
    const float* e1W = (const float*)d_in[16];
    const float* e2g = (const float*)d_in[17];
    const float* e2b = (const float*)d_in[18];
    const float* e2m = (const float*)d_in[19];
    const float* e2v = (const float*)d_in[20];
    const float* e2W = (const float*)d_in[21];
    const float* e3g = (const float*)d_in[22];
    const float* e3b = (const float*)d_in[23];
    const float* e3m = (const float*)d_in[24];
    const float* e3v = (const float*)d_in[25];
    const float* e3W = (const float*)d_in[26];
    const float* Wfc = (const float*)d_in[27];
    const float* bfc = (const float*)d_in[28];
    float* out = (float*)d_out;

    float *pA, *pB, *pH, *pX0, *pP, *pDa, *pDb;
    cudaGetSymbolAddress((void**)&pA,  d_bufA);
    cudaGetSymbolAddress((void**)&pB,  d_bufB);
    cudaGetSymbolAddress((void**)&pH,  d_h);
    cudaGetSymbolAddress((void**)&pX0, d_x0);
    cudaGetSymbolAddress((void**)&pP,  d_P);
    cudaGetSymbolAddress((void**)&pDa, d_aAff);
    cudaGetSymbolAddress((void**)&pDb, d_bAff);

    // smem: A(2*18432) + B(2*128*(C+8)*2)
    const int SME1 = 36864 + 2 * 128 * (256 + 8) * 2;  // 172032 (C=256)
    const int SME2 = 36864 + 2 * 128 * (128 + 8) * 2;  // 106496 (C=128)
    cudaFuncSetAttribute(edge_mma_kernel<256>, cudaFuncAttributeMaxDynamicSharedMemorySize, SME1);
    cudaFuncSetAttribute(edge_mma_kernel<128>, cudaFuncAttributeMaxDynamicSharedMemorySize, SME2);

    // CSR build
    zero_indeg_kernel<<<(NN + 255) / 256, 256>>>();
    count_kernel<<<(EE + 255) / 256, 256>>>(ei);
    scan_kernel<<<1, 1024>>>();
    fill_kernel<<<(EE + 255) / 256, 256>>>(ei);

    // dual projection
    gemm_rows8<512, 64, false><<<2500, 64>>>(x, Wc, bc, nullptr, nullptr, pX0, 0, 1, NN);
    gemm_rows8<512, 64, false><<<625, 64>>>(x, Wm, bm, nullptr, nullptr, pX0, 0, 4, 5000);

    // GCN stack
    gemm_rows8<64, 128, false><<<2500, 128>>>(pX0, Wg1, nullptr, nullptr, nullptr, pH, 0, 1, NN);
    gcn_agg<128><<<NN, 128>>>(pH, bg1, pA);
    gemm_rows8<128, 128, false><<<2500, 128>>>(pA, Wg2, nullptr, nullptr, nullptr, pH, 0, 1, NN);
    gcn_agg<128><<<NN, 128>>>(pH, bg2, pB);
    gemm_rows8<128, 256, false><<<2500, 256>>>(pB, Wg3, nullptr, nullptr, nullptr, pH, 0, 1, NN);
    gcn_agg<256><<<NN, 256>>>(pH, bg3, pA);  // g3 -> pA [N,256]

    // EdgeConv 1 (C=256): x = pA -> out pB
    bnaff_kernel<<<2, 256>>>(e1g, e1b, e1m, e1v, 512);
    gemm_rows8<256, 128, true><<<2500, 128>>>(pA, e1W, nullptr, pDa, pDb, pP, 0, 1, NN);
    scale_kernel<256><<<(NN * 256 / 4 + 255) / 256, 256>>>(pA, pDa + 256, pH);
    wsplit_kernel<<<(256 * 128 + 255) / 256, 256>>>(e1W + 256 * 128, 256);
    init_tmp_kernel<<<(NN * 128 / 4 + 255) / 256, 256>>>();
    edge_mma_kernel<256><<<148, 256, SME1>>>(pH, pDb + 256);
    edge_final_kernel<<<(NN * 128 + 255) / 256, 256>>>(pP, pB);

    // EdgeConv 2 (C=128): x = pB -> out pA
    bnaff_kernel<<<1, 256>>>(e2g, e2b, e2m, e2v, 256);
    gemm_rows8<128, 128, true><<<2500, 128>>>(pB, e2W, nullptr, pDa, pDb, pP, 0, 1, NN);
    scale_kernel<128><<<(NN * 128 / 4 + 255) / 256, 256>>>(pB, pDa + 128, pH);
    wsplit_kernel<<<(128 * 128 + 255) / 256, 256>>>(e2W + 128 * 128, 128);
    init_tmp_kernel<<<(NN * 128 / 4 + 255) / 256, 256>>>();
    edge_mma_kernel<128><<<296, 256, SME2>>>(pH, pDb + 128);
    edge_final_kernel<<<(NN * 128 + 255) / 256, 256>>>(pP, pA);

    // EdgeConv 3 (C=128): x = pA -> out pB
    bnaff_kernel<<<1, 256>>>(e3g, e3b, e3m, e3v, 256);
    gemm_rows8<128, 128, true><<<2500, 128>>>(pA, e3W, nullptr, pDa, pDb, pP, 0, 1, NN);
    scale_kernel<128><<<(NN * 128 / 4 + 255) / 256, 256>>>(pA, pDa + 128, pH);
    wsplit_kernel<<<(128 * 128 + 255) / 256, 256>>>(e3W + 128 * 128, 128);
    init_tmp_kernel<<<(NN * 128 / 4 + 255) / 256, 256>>>();
    edge_mma_kernel<128><<<296, 256, SME2>>>(pH, pDb + 128);
    edge_final_kernel<<<(NN * 128 + 255) / 256, 256>>>(pP, pB);

    // final FC
    fc_kernel<<<5000, 128>>>(pB, Wfc, bfc, out);
}

// round 5
// speedup vs baseline: 2.9103x; 1.0178x over previous
#include <cuda_runtime.h>
#include <cuda_bf16.h>
#include <cstdint>

#define NN 20000
#define EE 320000

// ---------------- scratch (device globals; no allocation) ----------------
__device__ float d_bufA[NN * 256];
__device__ float d_bufB[NN * 256];
__device__ float d_h[NN * 256];
__device__ float d_x0[NN * 64];
__device__ float d_P[NN * 128];
__device__ float d_aAff[512];
__device__ float d_bAff[512];
__device__ float d_dinv[NN];
__device__ int   d_indeg[NN];
__device__ int   d_rowptr[NN + 1];
__device__ int   d_cursor[NN];
__device__ int   d_csrsrc[EE];
__device__ int   d_csrdst[EE];
__device__ __nv_bfloat16 d_Whi[256 * 128];
__device__ __nv_bfloat16 d_Wlo[256 * 128];
__device__ unsigned d_tmpmax[NN * 128];

// ---------------- f32x2 packed helpers ----------------
__device__ __forceinline__ unsigned long long pack2(float x, float y) {
    unsigned long long r;
    unsigned a = __float_as_uint(x), b = __float_as_uint(y);
    asm("mov.b64 %0, {%1, %2};" : "=l"(r) : "r"(a), "r"(b));
    return r;
}
__device__ __forceinline__ unsigned long long bcast2(float x) {
    unsigned long long r;
    unsigned a = __float_as_uint(x);
    asm("mov.b64 %0, {%1, %1};" : "=l"(r) : "r"(a));
    return r;
}
__device__ __forceinline__ void fma2(unsigned long long& d, unsigned long long a, unsigned long long b) {
    asm("fma.rn.f32x2 %0, %1, %2, %0;" : "+l"(d) : "l"(a), "l"(b));
}
__device__ __forceinline__ float2 unpack2(unsigned long long v) {
    unsigned a, b;
    asm("mov.b64 {%0, %1}, %2;" : "=r"(a), "=r"(b) : "l"(v));
    return make_float2(__uint_as_float(a), __uint_as_float(b));
}

// ---------------- warp MMA helpers ----------------
__device__ __forceinline__ uint32_t smem_u32(const void* p) {
    uint32_t a;
    asm("{ .reg .u64 t; cvta.to.shared.u64 t, %1; cvt.u32.u64 %0, t; }" : "=r"(a) : "l"(p));
    return a;
}
__device__ __forceinline__ void ldsm4(uint32_t* r, uint32_t addr) {
    asm volatile("ldmatrix.sync.aligned.m8n8.x4.shared.b16 {%0,%1,%2,%3}, [%4];"
                 : "=r"(r[0]), "=r"(r[1]), "=r"(r[2]), "=r"(r[3]) : "r"(addr));
}
__device__ __forceinline__ void mma16816(float* d, const uint32_t* a, const uint32_t* b) {
    asm volatile("mma.sync.aligned.m16n8k16.row.col.f32.bf16.bf16.f32 "
                 "{%0,%1,%2,%3}, {%4,%5,%6,%7}, {%8,%9}, {%0,%1,%2,%3};"
                 : "+f"(d[0]), "+f"(d[1]), "+f"(d[2]), "+f"(d[3])
                 : "r"(a[0]), "r"(a[1]), "r"(a[2]), "r"(a[3]), "r"(b[0]), "r"(b[1]));
}

__device__ __forceinline__ unsigned encf(float x) {
    unsigned s = __float_as_uint(x);
    return (s & 0x80000000u) ? ~s : (s | 0x80000000u);
}
__device__ __forceinline__ float decf(unsigned u) {
    return (u & 0x80000000u) ? __uint_as_float(u ^ 0x80000000u) : __uint_as_float(~u);
}
__device__ __forceinline__ void split2(float a, float b, uint32_t& hi, uint32_t& lo) {
    __nv_bfloat16 ha = __float2bfloat16_rn(a), hb = __float2bfloat16_rn(b);
    __nv_bfloat16 la = __float2bfloat16_rn(a - __bfloat162float(ha));
    __nv_bfloat16 lb = __float2bfloat16_rn(b - __bfloat162float(hb));
    hi = (uint32_t)__bfloat16_as_ushort(ha) | ((uint32_t)__bfloat16_as_ushort(hb) << 16);
    lo = (uint32_t)__bfloat16_as_ushort(la) | ((uint32_t)__bfloat16_as_ushort(lb) << 16);
}

// ---------------- CSR build ----------------
__global__ void zero_indeg_kernel() {
    int i = blockIdx.x * blockDim.x + threadIdx.x;
    if (i < NN) d_indeg[i] = 0;
}
__global__ void count_kernel(const int* __restrict__ ei) {
    int i = blockIdx.x * blockDim.x + threadIdx.x;
    if (i < EE) atomicAdd(&d_indeg[ei[EE + i]], 1);
}
__global__ void scan_kernel() {
    __shared__ int sh[1024];
    __shared__ int carry;
    int tid = threadIdx.x;
    if (tid == 0) carry = 0;
    __syncthreads();
    for (int base = 0; base < NN; base += 1024) {
        int i = base + tid;
        int v = (i < NN) ? d_indeg[i] : 0;
        sh[tid] = v;
        __syncthreads();
        for (int off = 1; off < 1024; off <<= 1) {
            int t = (tid >= off) ? sh[tid - off] : 0;
            __syncthreads();
            sh[tid] += t;
            __syncthreads();
        }
        int incl = sh[tid];
        int base_c = carry;
        if (i < NN) {
            int excl = base_c + incl - v;
            d_rowptr[i] = excl;
            d_cursor[i] = excl;
            d_dinv[i] = rsqrtf((float)(v + 1));
        }
        __syncthreads();
        if (tid == 1023) carry = base_c + sh[1023];
        __syncthreads();
    }
    if (tid == 0) d_rowptr[NN] = carry;
}
__global__ void fill_kernel(const int* __restrict__ ei) {
    int i = blockIdx.x * blockDim.x + threadIdx.x;
    if (i < EE) {
        int s = ei[i];
        int d = ei[EE + i];
        int pos = atomicAdd(&d_cursor[d], 1);
        d_csrsrc[pos] = s;
        d_csrdst[pos] = d;
    }
}

// ---------------- row GEMM (f32x2), 8 rows/block ----------------
template <int K, int COUT, bool PRE>
__global__ void gemm_rows8(const float* __restrict__ A, const float* __restrict__ W,
                           const float* __restrict__ bias,
                           const float* __restrict__ aAff, const float* __restrict__ bAff,
                           float* __restrict__ out,
                           int rowStart, int rowStride, int numRows) {
    __shared__ float As[10 * K];
    int tid = threadIdx.x;
    int rblk = blockIdx.x * 8;
    for (int idx = tid; idx < 8 * K; idx += COUT) {
        int r = idx / K, k = idx - r * K;
        int rr = rblk + r;
        float v = 0.f;
        if (rr < numRows) {
            int grow = rowStart + rr * rowStride;
            v = A[(size_t)grow * K + k];
            if (PRE) v = fmaxf(fmaf(aAff[k], v, bAff[k]), 0.f);
        }
        As[k * 10 + r] = v;
    }
    __syncthreads();
    int c = tid;
    unsigned long long acc01 = 0, acc23 = 0, acc45 = 0, acc67 = 0;
#pragma unroll 4
    for (int k = 0; k < K; k++) {
        float wv = W[(size_t)k * COUT + c];
        unsigned long long ww = bcast2(wv);
        const float* row = As + k * 10;
        float2 a01 = *(const float2*)(row + 0);
        float2 a23 = *(const float2*)(row + 2);
        float2 a45 = *(const float2*)(row + 4);
        float2 a67 = *(const float2*)(row + 6);
        fma2(acc01, pack2(a01.x, a01.y), ww);
        fma2(acc23, pack2(a23.x, a23.y), ww);
        fma2(acc45, pack2(a45.x, a45.y), ww);
        fma2(acc67, pack2(a67.x, a67.y), ww);
    }
    float bv = bias ? bias[c] : 0.f;
    float res[8];
    float2 t;
    t = unpack2(acc01); res[0] = t.x; res[1] = t.y;
    t = unpack2(acc23); res[2] = t.x; res[3] = t.y;
    t = unpack2(acc45); res[4] = t.x; res[5] = t.y;
    t = unpack2(acc67); res[6] = t.x; res[7] = t.y;
#pragma unroll
    for (int r = 0; r < 8; r++) {
        int rr = rblk + r;
        if (rr < numRows) {
            int grow = rowStart + rr * rowStride;
            out[(size_t)grow * COUT + c] = res[r] + bv;
        }
    }
}

// ---------------- GCN aggregation on PRE-GEMM features (agg is linear) ----------------
// out[d] = (sum_s x[s]*dinv[s]) * dinv[d] + x[d]*dinv[d]^2
template <int C>
__global__ void gcn_agg_pre(const float* __restrict__ x, float* __restrict__ out) {
    constexpr int NPB = 128 / C;
    int local = threadIdx.x / C;
    int node = blockIdx.x * NPB + local;
    int c = threadIdx.x - local * C;
    if (node >= NN) return;
    float dd = d_dinv[node];
    float self = x[(size_t)node * C + c] * dd * dd;
    int e0 = d_rowptr[node], e1 = d_rowptr[node + 1];
    float a0 = 0.f, a1 = 0.f, a2 = 0.f, a3 = 0.f;
    int e = e0;
    for (; e + 4 <= e1; e += 4) {
        int s0 = d_csrsrc[e], s1 = d_csrsrc[e + 1], s2 = d_csrsrc[e + 2], s3 = d_csrsrc[e + 3];
        float w0 = d_dinv[s0], w1 = d_dinv[s1], w2 = d_dinv[s2], w3 = d_dinv[s3];
        float h0 = x[(size_t)s0 * C + c];
        float h1 = x[(size_t)s1 * C + c];
        float h2 = x[(size_t)s2 * C + c];
        float h3 = x[(size_t)s3 * C + c];
        a0 = fmaf(h0, w0, a0);
        a1 = fmaf(h1, w1, a1);
        a2 = fmaf(h2, w2, a2);
        a3 = fmaf(h3, w3, a3);
    }
    for (; e < e1; e++) {
        int s = d_csrsrc[e];
        a0 = fmaf(x[(size_t)s * C + c], d_dinv[s], a0);
    }
    out[(size_t)node * C + c] = fmaf((a0 + a1) + (a2 + a3), dd, self);
}

// ---------------- BN affine precompute ----------------
__global__ void bnaff_kernel(const float* __restrict__ g, const float* __restrict__ be,
                             const float* __restrict__ mn, const float* __restrict__ vr, int n) {
    int i = blockIdx.x * blockDim.x + threadIdx.x;
    if (i < n) {
        float a = g[i] * rsqrtf(vr[i] + 1e-5f);
        d_aAff[i] = a;
        d_bAff[i] = fmaf(-mn[i], a, be[i]);
    }
}

// ---------------- W split/transpose: Wt[n][k] = bf16split(W[k][n]) ----------------
__global__ void wsplit_kernel(const float* __restrict__ W, int C) {
    int id = blockIdx.x * blockDim.x + threadIdx.x;
    if (id < C * 128) {
        int k = id >> 7, n = id & 127;
        float w = W[id];
        __nv_bfloat16 hi = __float2bfloat16_rn(w);
        __nv_bfloat16 lo = __float2bfloat16_rn(w - __bfloat162float(hi));
        d_Whi[n * C + k] = hi;
        d_Wlo[n * C + k] = lo;
    }
}

// ---------------- init tmpmax to 0 (= -inf under encf ordering) ----------------
__global__ void init_tmp_kernel() {
    int i = blockIdx.x * blockDim.x + threadIdx.x;
    if (i < NN * 128 / 4) ((uint4*)d_tmpmax)[i] = make_uint4(0, 0, 0, 0);
}

// ---------------- EdgeConv via bf16-split mma.sync ----------------
// Tile = 128 edges x 128 outs, K = C. Q = ReLU(a*(x[s]-x[d])+b) @ Wbot.
// 8 warps, warp = 16 edge rows x 128 cols. Epilogue: segmented max + atomicMax.
template <int C>
__global__ __launch_bounds__(256, 1) void edge_mma_kernel(const float* __restrict__ x,
                                                          const float* __restrict__ aAff,
                                                          const float* __restrict__ bAff) {
    constexpr int NCH = C / 64;
    constexpr int ASTRIDE = 72;                 // bf16 per A row (64 + pad)
    constexpr int ABYTES = 128 * ASTRIDE * 2;   // 18432 per half
    constexpr int AHI = 0, ALO = ABYTES, BOFF = 2 * ABYTES;
    constexpr int BSTRIDE = C + 8;              // bf16 per Wt row
    constexpr int BHALF = 128 * BSTRIDE * 2;
    extern __shared__ char smem[];
    float* buf = (float*)smem;                  // epilogue staging (128*33 f32), aliases A
    uint32_t sb = smem_u32(smem);
    const int tid = threadIdx.x, lane = tid & 31, w = tid >> 5;
    const unsigned fullm = 0xFFFFFFFFu;

    // stage Wt hi/lo into padded SMEM (once per block)
    for (int idx = tid; idx < C * 128 / 8; idx += 256) {
        int n = idx / (C / 8), kb = (idx % (C / 8)) * 8;
        uint32_t off = BOFF + (uint32_t)(n * BSTRIDE + kb) * 2;
        *(uint4*)(smem + off) = ((const uint4*)d_Whi)[idx];
        *(uint4*)(smem + off + BHALF) = ((const uint4*)d_Wlo)[idx];
    }

    const int arow = tid >> 1, ahalf = tid & 1;  // staging: thread = (row, 32-k half)

    for (int t = blockIdx.x; t < EE / 128; t += gridDim.x) {
        float acc[16][4];
#pragma unroll
        for (int i = 0; i < 16; i++) { acc[i][0] = acc[i][1] = acc[i][2] = acc[i][3] = 0.f; }

        const int sA = d_csrsrc[t * 128 + arow];
        const int dA = d_csrdst[t * 128 + arow];

        for (int ch = 0; ch < NCH; ch++) {
            __syncthreads();
            // stage A chunk: feature = ReLU(a*(x_s - x_d) + b), split to bf16 hi/lo
            {
                int kb = ch * 64 + ahalf * 32;
                const float4* xs = (const float4*)(x + (size_t)sA * C + kb);
                const float4* xd = (const float4*)(x + (size_t)dA * C + kb);
                const float4* aa = (const float4*)(aAff + kb);
                const float4* bb = (const float4*)(bAff + kb);
#pragma unroll
                for (int q = 0; q < 4; q++) {
                    float4 s0 = xs[q * 2], s1 = xs[q * 2 + 1];
                    float4 d0 = xd[q * 2], d1 = xd[q * 2 + 1];
                    float4 A0 = __ldg(aa + q * 2), A1 = __ldg(aa + q * 2 + 1);
                    float4 B0 = __ldg(bb + q * 2), B1 = __ldg(bb + q * 2 + 1);
                    float v0 = fmaxf(fmaf(A0.x, s0.x - d0.x, B0.x), 0.f);
                    float v1 = fmaxf(fmaf(A0.y, s0.y - d0.y, B0.y), 0.f);
                    float v2 = fmaxf(fmaf(A0.z, s0.z - d0.z, B0.z), 0.f);
                    float v3 = fmaxf(fmaf(A0.w, s0.w - d0.w, B0.w), 0.f);
                    float v4 = fmaxf(fmaf(A1.x, s1.x - d1.x, B1.x), 0.f);
                    float v5 = fmaxf(fmaf(A1.y, s1.y - d1.y, B1.y), 0.f);
                    float v6 = fmaxf(fmaf(A1.z, s1.z - d1.z, B1.z), 0.f);
                    float v7 = fmaxf(fmaf(A1.w, s1.w - d1.w, B1.w), 0.f);
                    uint4 H, L;
                    split2(v0, v1, H.x, L.x);
                    split2(v2, v3, H.y, L.y);
                    split2(v4, v5, H.z, L.z);
                    split2(v6, v7, H.w, L.w);
                    uint32_t off = (uint32_t)(arow * ASTRIDE + ahalf * 32 + q * 8) * 2;
                    *(uint4*)(smem + AHI + off) = H;
                    *(uint4*)(smem + ALO + off) = L;
                }
            }
            __syncthreads();
            // MMA over the chunk (4 k-steps of 16); B via ldsm4 (2 n-tiles/op)
            const uint32_t within = lane & 15;
            const uint32_t brow = within & 7, bsel = within >> 3;
            const uint32_t ntoff = lane >> 4;  // 0: even n-tile, 1: odd
#pragma unroll
            for (int ks = 0; ks < 4; ks++) {
                uint32_t ah[4], al[4];
                uint32_t aaddr = sb + AHI +
                    (uint32_t)((w * 16 + (lane & 15)) * ASTRIDE + ks * 16 + (lane >> 4) * 8) * 2;
                ldsm4(ah, aaddr);
                ldsm4(al, aaddr + ABYTES);
#pragma unroll
                for (int np = 0; np < 8; np++) {
                    uint32_t baddr = sb + BOFF +
                        (uint32_t)((np * 16 + ntoff * 8 + brow) * BSTRIDE + ch * 64 + ks * 16 + bsel * 8) * 2;
                    uint32_t bh[4], bl[4];
                    ldsm4(bh, baddr);
                    ldsm4(bl, baddr + BHALF);
                    mma16816(acc[np * 2], ah, bh);
                    mma16816(acc[np * 2], ah, bl);
                    mma16816(acc[np * 2], al, bh);
                    mma16816(acc[np * 2 + 1], ah, bh + 2);
                    mma16816(acc[np * 2 + 1], ah, bl + 2);
                    mma16816(acc[np * 2 + 1], al, bh + 2);
                }
            }
        }
        // ---- epilogue: segmented max over CSR runs ----
        int erow = t * 128 + (w & 3) * 32 + lane;
        int dl = d_csrdst[erow];
        int prev = __shfl_up_sync(fullm, dl, 1);
        bool head = (lane == 0) || (dl != prev);
        unsigned Hb = __ballot_sync(fullm, head);
        unsigned mle;
        asm("mov.u32 %0, %%lanemask_le;" : "=r"(mle));
        int run_start = 31 - __clz(Hb & mle);
        bool tail = (lane == 31) || ((Hb >> (lane + 1)) & 1);
        unsigned* trow = d_tmpmax + (size_t)dl * 128;
#pragma unroll
        for (int g = 0; g < 4; g++) {
            __syncthreads();
#pragma unroll
            for (int q = 0; q < 4; q++) {
                int nt = g * 4 + q;
                int lcol = q * 8 + (lane & 3) * 2;
                int r0 = w * 16 + (lane >> 2);
                buf[r0 * 33 + lcol]           = acc[nt][0];
                buf[r0 * 33 + lcol + 1]       = acc[nt][1];
                buf[(r0 + 8) * 33 + lcol]     = acc[nt][2];
                buf[(r0 + 8) * 33 + lcol + 1] = acc[nt][3];
            }
            __syncthreads();
            int rr = (w & 3) * 32 + lane;
            int cb = (w >> 2) * 16;
            float v[16];
#pragma unroll
            for (int j = 0; j < 16; j++) v[j] = buf[rr * 33 + cb + j];
#pragma unroll
            for (int dlt = 1; dlt < 32; dlt <<= 1) {
#pragma unroll
                for (int j = 0; j < 16; j++) {
                    float u = __shfl_up_sync(fullm, v[j], dlt);
                    if ((int)lane - dlt >= run_start) v[j] = fmaxf(v[j], u);
                }
            }
            if (tail) {
#pragma unroll
                for (int j = 0; j < 16; j++) atomicMax(trow + g * 32 + cb + j, encf(v[j]));
            }
        }
    }
}

// ---------------- finalize: out[d] = deg>0 ? P[d] + dec(tmp[d]) : 0 ; reset tmp ----------------
__global__ void edge_final_kernel(const float* __restrict__ P, float* __restrict__ out) {
    int i = blockIdx.x * blockDim.x + threadIdx.x;
    if (i < NN * 128) {
        int d = i >> 7;
        float r = 0.f;
        if (d_indeg[d] > 0) r = P[i] + decf(d_tmpmax[i]);
        out[i] = r;
        d_tmpmax[i] = 0;  // reset for next edge layer / next replay
    }
}

// ---------------- fused last-layer finalize + FC ----------------
__global__ void fc_fused_kernel(const float* __restrict__ P, const float* __restrict__ Wfc,
                                const float* __restrict__ bfc, float* __restrict__ out) {
    int w = threadIdx.x >> 5, lane = threadIdx.x & 31;
    int d = blockIdx.x * 4 + w;
    if (d >= NN) return;
    bool nz = d_indeg[d] > 0;
    float s = 0.f;
#pragma unroll
    for (int u = 0; u < 4; u++) {
        int k = lane + 32 * u;
        float h = nz ? P[(size_t)d * 128 + k] + decf(d_tmpmax[(size_t)d * 128 + k]) : 0.f;
        s = fmaf(h, Wfc[k], s);
    }
#pragma unroll
    for (int off = 16; off; off >>= 1) s += __shfl_down_sync(0xffffffffu, s, off);
    if (lane == 0) out[d] = s + bfc[0];
}

// ---------------- host ----------------
extern "C" void kernel_launch(void* const* d_in, const int* in_sizes, int n_in,
                              void* d_out, int out_size) {
    const float* x   = (const float*)d_in[0];
    const int*   ei  = (const int*)d_in[1];
    const float* Wm  = (const float*)d_in[2];
    const float* bm  = (const float*)d_in[3];
    const float* Wc  = (const float*)d_in[4];
    const float* bc  = (const float*)d_in[5];
    const float* Wg1 = (const float*)d_in[6];
    const float* bg1 = (const float*)d_in[7];
    const float* Wg2 = (const float*)d_in[8];
    const float* bg2 = (const float*)d_in[9];
    const float* Wg3 = (const float*)d_in[10];
    const float* bg3 = (const float*)d_in[11];
    const float* e1g = (const float*)d_in[12];
    const float* e1b = (const float*)d_in[13];
    const float* e1m = (const float*)d_in[14];
    const float* e1v = (const float*)d_in[15];
    const float* e1W = (const float*)d_in[16];
    const float* e2g = (const float*)d_in[17];
    const float* e2b = (const float*)d_in[18];
    const float* e2m = (const float*)d_in[19];
    const float* e2v = (const float*)d_in[20];
    const float* e2W = (const float*)d_in[21];
    const float* e3g = (const float*)d_in[22];
    const float* e3b = (const float*)d_in[23];
    const float* e3m = (const float*)d_in[24];
    const float* e3v = (const float*)d_in[25];
    const float* e3W = (const float*)d_in[26];
    const float* Wfc = (const float*)d_in[27];
    const float* bfc = (const float*)d_in[28];
    float* out = (float*)d_out;

    float *pA, *pB, *pH, *pX0, *pP, *pDa, *pDb;
    cudaGetSymbolAddress((void**)&pA,  d_bufA);
    cudaGetSymbolAddress((void**)&pB,  d_bufB);
    cudaGetSymbolAddress((void**)&pH,  d_h);
    cudaGetSymbolAddress((void**)&pX0, d_x0);
    cudaGetSymbolAddress((void**)&pP,  d_P);
    cudaGetSymbolAddress((void**)&pDa, d_aAff);
    cudaGetSymbolAddress((void**)&pDb, d_bAff);

    // smem: A(2*18432) + B(2*128*(C+8)*2)
    const int SME1 = 36864 + 2 * 128 * (256 + 8) * 2;  // 172032 (C=256)
    const int SME2 = 36864 + 2 * 128 * (128 + 8) * 2;  // 106496 (C=128)
    cudaFuncSetAttribute(edge_mma_kernel<256>, cudaFuncAttributeMaxDynamicSharedMemorySize, SME1);
    cudaFuncSetAttribute(edge_mma_kernel<128>, cudaFuncAttributeMaxDynamicSharedMemorySize, SME2);

    // CSR build
    zero_indeg_kernel<<<(NN + 255) / 256, 256>>>();
    count_kernel<<<(EE + 255) / 256, 256>>>(ei);
    scan_kernel<<<1, 1024>>>();
    fill_kernel<<<(EE + 255) / 256, 256>>>(ei);

    // dual projection
    gemm_rows8<512, 64, false><<<2500, 64>>>(x, Wc, bc, nullptr, nullptr, pX0, 0, 1, NN);
    gemm_rows8<512, 64, false><<<625, 64>>>(x, Wm, bm, nullptr, nullptr, pX0, 0, 4, 5000);

    // GCN stack (aggregate-then-GEMM; agg is linear)
    gcn_agg_pre<64><<<NN / 2, 128>>>(pX0, pH);
    gemm_rows8<64, 128, false><<<2500, 128>>>(pH, Wg1, bg1, nullptr, nullptr, pA, 0, 1, NN);
    gcn_agg_pre<128><<<NN, 128>>>(pA, pH);
    gemm_rows8<128, 128, false><<<2500, 128>>>(pH, Wg2, bg2, nullptr, nullptr, pB, 0, 1, NN);
    gcn_agg_pre<128><<<NN, 128>>>(pB, pH);
    gemm_rows8<128, 256, false><<<2500, 256>>>(pH, Wg3, bg3, nullptr, nullptr, pA, 0, 1, NN);
    // g3 -> pA [N,256]

    init_tmp_kernel<<<(NN * 128 / 4 + 255) / 256, 256>>>();

    // EdgeConv 1 (C=256): x = pA -> out pB
    bnaff_kernel<<<2, 256>>>(e1g, e1b, e1m, e1v, 512);
    gemm_rows8<256, 128, true><<<2500, 128>>>(pA, e1W, nullptr, pDa, pDb, pP, 0, 1, NN);
    wsplit_kernel<<<(256 * 128 + 255) / 256, 256>>>(e1W + 256 * 128, 256);
    edge_mma_kernel<256><<<148, 256, SME1>>>(pA, pDa + 256, pDb + 256);
    edge_final_kernel<<<(NN * 128 + 255) / 256, 256>>>(pP, pB);

    // EdgeConv 2 (C=128): x = pB -> out pA
    bnaff_kernel<<<1, 256>>>(e2g, e2b, e2m, e2v, 256);
    gemm_rows8<128, 128, true><<<2500, 128>>>(pB, e2W, nullptr, pDa, pDb, pP, 0, 1, NN);
    wsplit_kernel<<<(128 * 128 + 255) / 256, 256>>>(e2W + 128 * 128, 128);
    edge_mma_kernel<128><<<296, 256, SME2>>>(pB, pDa + 128, pDb + 128);
    edge_final_kernel<<<(NN * 128 + 255) / 256, 256>>>(pP, pA);

    // EdgeConv 3 (C=128): x = pA -> fused finalize+FC
    bnaff_kernel<<<1, 256>>>(e3g, e3b, e3m, e3v, 256);
    gemm_rows8<128, 128, true><<<2500, 128>>>(pA, e3W, nullptr, pDa, pDb, pP, 0, 1, NN);
    wsplit_kernel<<<(128 * 128 + 255) / 256, 256>>>(e3W + 128 * 128, 128);
    edge_mma_kernel<128><<<296, 256, SME2>>>(pA, pDa + 128, pDb + 128);
    fc_fused_kernel<<<5000, 128>>>(pP, Wfc, bfc, out);
}

// round 6
// speedup vs baseline: 3.2553x; 1.1186x over previous
#include <cuda_runtime.h>
#include <cuda_bf16.h>
#include <cuda_fp16.h>
#include <cstdint>

#define NN 20000
#define EE 320000

// ---------------- scratch (device globals; no allocation) ----------------
__device__ float d_bufA[NN * 256];
__device__ float d_bufB[NN * 256];
__device__ float d_h[NN * 256];
__device__ float d_x0[NN * 64];
__device__ float d_P[NN * 128];
__device__ float d_aAff[512];
__device__ float d_bAff[512];
__device__ float d_dinv[NN];
__device__ int   d_indeg[NN];
__device__ int   d_rowptr[NN + 1];
__device__ int   d_cursor[NN];
__device__ int   d_csrsrc[EE];
__device__ int   d_csrdst[EE];
__device__ __half d_Whi[256 * 128];
__device__ __half d_Wlo[256 * 128];
__device__ unsigned d_tmpmax[NN * 128];

// ---------------- f32x2 packed helpers ----------------
__device__ __forceinline__ unsigned long long pack2(float x, float y) {
    unsigned long long r;
    unsigned a = __float_as_uint(x), b = __float_as_uint(y);
    asm("mov.b64 %0, {%1, %2};" : "=l"(r) : "r"(a), "r"(b));
    return r;
}
__device__ __forceinline__ unsigned long long bcast2(float x) {
    unsigned long long r;
    unsigned a = __float_as_uint(x);
    asm("mov.b64 %0, {%1, %1};" : "=l"(r) : "r"(a));
    return r;
}
__device__ __forceinline__ void fma2(unsigned long long& d, unsigned long long a, unsigned long long b) {
    asm("fma.rn.f32x2 %0, %1, %2, %0;" : "+l"(d) : "l"(a), "l"(b));
}
__device__ __forceinline__ float2 unpack2(unsigned long long v) {
    unsigned a, b;
    asm("mov.b64 {%0, %1}, %2;" : "=r"(a), "=r"(b) : "l"(v));
    return make_float2(__uint_as_float(a), __uint_as_float(b));
}

// ---------------- warp MMA helpers ----------------
__device__ __forceinline__ uint32_t smem_u32(const void* p) {
    uint32_t a;
    asm("{ .reg .u64 t; cvta.to.shared.u64 t, %1; cvt.u32.u64 %0, t; }" : "=r"(a) : "l"(p));
    return a;
}
__device__ __forceinline__ void ldsm4(uint32_t* r, uint32_t addr) {
    asm volatile("ldmatrix.sync.aligned.m8n8.x4.shared.b16 {%0,%1,%2,%3}, [%4];"
                 : "=r"(r[0]), "=r"(r[1]), "=r"(r[2]), "=r"(r[3]) : "r"(addr));
}
__device__ __forceinline__ void mma16816f(float* d, const uint32_t* a, const uint32_t* b) {
    asm volatile("mma.sync.aligned.m16n8k16.row.col.f32.f16.f16.f32 "
                 "{%0,%1,%2,%3}, {%4,%5,%6,%7}, {%8,%9}, {%0,%1,%2,%3};"
                 : "+f"(d[0]), "+f"(d[1]), "+f"(d[2]), "+f"(d[3])
                 : "r"(a[0]), "r"(a[1]), "r"(a[2]), "r"(a[3]), "r"(b[0]), "r"(b[1]));
}

__device__ __forceinline__ unsigned encf(float x) {
    unsigned s = __float_as_uint(x);
    return (s & 0x80000000u) ? ~s : (s | 0x80000000u);
}
__device__ __forceinline__ float decf(unsigned u) {
    return (u & 0x80000000u) ? __uint_as_float(u ^ 0x80000000u) : __uint_as_float(~u);
}
__device__ __forceinline__ uint32_t ph2(float a, float b) {
    __half2 h = __floats2half2_rn(a, b);
    return *(uint32_t*)&h;
}

// ---------------- CSR build ----------------
__global__ void count_kernel(const int* __restrict__ ei) {
    int i = blockIdx.x * blockDim.x + threadIdx.x;
    if (i < EE) atomicAdd(&d_indeg[ei[EE + i]], 1);
}
__global__ void scan_kernel() {
    __shared__ int sh[1024];
    __shared__ int carry;
    int tid = threadIdx.x;
    if (tid == 0) carry = 0;
    __syncthreads();
    for (int base = 0; base < NN; base += 1024) {
        int i = base + tid;
        int v = (i < NN) ? d_indeg[i] : 0;
        sh[tid] = v;
        __syncthreads();
        for (int off = 1; off < 1024; off <<= 1) {
            int t = (tid >= off) ? sh[tid - off] : 0;
            __syncthreads();
            sh[tid] += t;
            __syncthreads();
        }
        int incl = sh[tid];
        int base_c = carry;
        if (i < NN) {
            int excl = base_c + incl - v;
            d_rowptr[i] = excl;
            d_cursor[i] = excl;
            d_dinv[i] = rsqrtf((float)(v + 1));
        }
        __syncthreads();
        if (tid == 1023) carry = base_c + sh[1023];
        __syncthreads();
    }
    if (tid == 0) d_rowptr[NN] = carry;
}
__global__ void fill_kernel(const int* __restrict__ ei) {
    int i = blockIdx.x * blockDim.x + threadIdx.x;
    if (i < EE) {
        int s = ei[i];
        int d = ei[EE + i];
        int pos = atomicAdd(&d_cursor[d], 1);
        d_csrsrc[pos] = s;
        d_csrdst[pos] = d;
    }
}

// ---------------- row GEMM (f32x2), 8 rows/block ----------------
template <int K, int COUT, bool PRE>
__global__ void gemm_rows8(const float* __restrict__ A, const float* __restrict__ W,
                           const float* __restrict__ bias,
                           const float* __restrict__ aAff, const float* __restrict__ bAff,
                           float* __restrict__ out,
                           int rowStart, int rowStride, int numRows) {
    __shared__ float As[10 * K];
    int tid = threadIdx.x;
    int rblk = blockIdx.x * 8;
    for (int idx = tid; idx < 8 * K; idx += COUT) {
        int r = idx / K, k = idx - r * K;
        int rr = rblk + r;
        float v = 0.f;
        if (rr < numRows) {
            int grow = rowStart + rr * rowStride;
            v = A[(size_t)grow * K + k];
            if (PRE) v = fmaxf(fmaf(aAff[k], v, bAff[k]), 0.f);
        }
        As[k * 10 + r] = v;
    }
    __syncthreads();
    int c = tid;
    unsigned long long acc01 = 0, acc23 = 0, acc45 = 0, acc67 = 0;
#pragma unroll 4
    for (int k = 0; k < K; k++) {
        float wv = W[(size_t)k * COUT + c];
        unsigned long long ww = bcast2(wv);
        const float* row = As + k * 10;
        float2 a01 = *(const float2*)(row + 0);
        float2 a23 = *(const float2*)(row + 2);
        float2 a45 = *(const float2*)(row + 4);
        float2 a67 = *(const float2*)(row + 6);
        fma2(acc01, pack2(a01.x, a01.y), ww);
        fma2(acc23, pack2(a23.x, a23.y), ww);
        fma2(acc45, pack2(a45.x, a45.y), ww);
        fma2(acc67, pack2(a67.x, a67.y), ww);
    }
    float bv = bias ? bias[c] : 0.f;
    float res[8];
    float2 t;
    t = unpack2(acc01); res[0] = t.x; res[1] = t.y;
    t = unpack2(acc23); res[2] = t.x; res[3] = t.y;
    t = unpack2(acc45); res[4] = t.x; res[5] = t.y;
    t = unpack2(acc67); res[6] = t.x; res[7] = t.y;
#pragma unroll
    for (int r = 0; r < 8; r++) {
        int rr = rblk + r;
        if (rr < numRows) {
            int grow = rowStart + rr * rowStride;
            out[(size_t)grow * COUT + c] = res[r] + bv;
        }
    }
}

// ---------------- GCN aggregation on PRE-GEMM features (agg is linear) ----------------
template <int C>
__global__ void gcn_agg_pre(const float* __restrict__ x, float* __restrict__ out) {
    constexpr int NPB = 128 / C;
    int local = threadIdx.x / C;
    int node = blockIdx.x * NPB + local;
    int c = threadIdx.x - local * C;
    if (node >= NN) return;
    float dd = d_dinv[node];
    float self = x[(size_t)node * C + c] * dd * dd;
    int e0 = d_rowptr[node], e1 = d_rowptr[node + 1];
    float a0 = 0.f, a1 = 0.f, a2 = 0.f, a3 = 0.f;
    int e = e0;
    for (; e + 4 <= e1; e += 4) {
        int s0 = d_csrsrc[e], s1 = d_csrsrc[e + 1], s2 = d_csrsrc[e + 2], s3 = d_csrsrc[e + 3];
        float w0 = d_dinv[s0], w1 = d_dinv[s1], w2 = d_dinv[s2], w3 = d_dinv[s3];
        float h0 = x[(size_t)s0 * C + c];
        float h1 = x[(size_t)s1 * C + c];
        float h2 = x[(size_t)s2 * C + c];
        float h3 = x[(size_t)s3 * C + c];
        a0 = fmaf(h0, w0, a0);
        a1 = fmaf(h1, w1, a1);
        a2 = fmaf(h2, w2, a2);
        a3 = fmaf(h3, w3, a3);
    }
    for (; e < e1; e++) {
        int s = d_csrsrc[e];
        a0 = fmaf(x[(size_t)s * C + c], d_dinv[s], a0);
    }
    out[(size_t)node * C + c] = fmaf((a0 + a1) + (a2 + a3), dd, self);
}

// ---------------- BN affine precompute ----------------
__global__ void bnaff_kernel(const float* __restrict__ g, const float* __restrict__ be,
                             const float* __restrict__ mn, const float* __restrict__ vr, int n) {
    int i = blockIdx.x * blockDim.x + threadIdx.x;
    if (i < n) {
        float a = g[i] * rsqrtf(vr[i] + 1e-5f);
        d_aAff[i] = a;
        d_bAff[i] = fmaf(-mn[i], a, be[i]);
    }
}

// ---------------- W split/transpose: Wt[n][k] = fp16split(W[k][n]) ----------------
__global__ void wsplit_kernel(const float* __restrict__ W, int C) {
    int id = blockIdx.x * blockDim.x + threadIdx.x;
    if (id < C * 128) {
        int k = id >> 7, n = id & 127;
        float w = W[id];
        __half hi = __float2half_rn(w);
        __half lo = __float2half_rn(w - __half2float(hi));
        d_Whi[n * C + k] = hi;
        d_Wlo[n * C + k] = lo;
    }
}

// ---------------- EdgeConv via fp16 2-term mma.sync ----------------
// Tile = 128 edges x 128 outs. Q = ReLU(a*(x[s]-x[d])+b) @ Wbot.
// A = fp16(feature) (single); B = fp16 hi/lo split: A@(bh+bl) error ~ 2^-12 rel.
template <int C>
__global__ __launch_bounds__(256, 2) void edge_mma_kernel(const float* __restrict__ x,
                                                          const float* __restrict__ aAff,
                                                          const float* __restrict__ bAff) {
    constexpr int NCH = C / 64;
    constexpr int ASTRIDE = 72;                 // fp16 per A row (64 + pad)
    constexpr int ABYTES = 128 * ASTRIDE * 2;   // 18432
    constexpr int BOFF = ABYTES;
    constexpr int BSTRIDE = C + 8;              // fp16 per Wt row
    constexpr int BHALF = 128 * BSTRIDE * 2;
    extern __shared__ char smem[];
    float* buf = (float*)smem;                  // epilogue staging (128*33 f32), aliases A
    uint32_t sb = smem_u32(smem);
    const int tid = threadIdx.x, lane = tid & 31, w = tid >> 5;
    const unsigned fullm = 0xFFFFFFFFu;

    // stage Wt hi/lo into padded SMEM (once per block)
    for (int idx = tid; idx < C * 128 / 8; idx += 256) {
        int n = idx / (C / 8), kb = (idx % (C / 8)) * 8;
        uint32_t off = BOFF + (uint32_t)(n * BSTRIDE + kb) * 2;
        *(uint4*)(smem + off) = ((const uint4*)d_Whi)[idx];
        *(uint4*)(smem + off + BHALF) = ((const uint4*)d_Wlo)[idx];
    }

    const int arow = tid >> 1, ahalf = tid & 1;  // staging: thread = (row, 32-ch half)

    for (int t = blockIdx.x; t < EE / 128; t += gridDim.x) {
        float acc[16][4];
#pragma unroll
        for (int i = 0; i < 16; i++) { acc[i][0] = acc[i][1] = acc[i][2] = acc[i][3] = 0.f; }

        const int sA = d_csrsrc[t * 128 + arow];
        const int dA = d_csrdst[t * 128 + arow];

        for (int ch = 0; ch < NCH; ch++) {
            __syncthreads();
            // stage A chunk: feature = fp16(ReLU(a*(x_s - x_d) + b))
            {
                int kb = ch * 64 + ahalf * 32;
                const float4* xs = (const float4*)(x + (size_t)sA * C + kb);
                const float4* xd = (const float4*)(x + (size_t)dA * C + kb);
                const float4* aa = (const float4*)(aAff + kb);
                const float4* bb = (const float4*)(bAff + kb);
#pragma unroll
                for (int q = 0; q < 4; q++) {
                    float4 s0 = xs[q * 2], s1 = xs[q * 2 + 1];
                    float4 d0 = xd[q * 2], d1 = xd[q * 2 + 1];
                    float4 A0 = __ldg(aa + q * 2), A1 = __ldg(aa + q * 2 + 1);
                    float4 B0 = __ldg(bb + q * 2), B1 = __ldg(bb + q * 2 + 1);
                    float v0 = fmaxf(fmaf(A0.x, s0.x - d0.x, B0.x), 0.f);
                    float v1 = fmaxf(fmaf(A0.y, s0.y - d0.y, B0.y), 0.f);
                    float v2 = fmaxf(fmaf(A0.z, s0.z - d0.z, B0.z), 0.f);
                    float v3 = fmaxf(fmaf(A0.w, s0.w - d0.w, B0.w), 0.f);
                    float v4 = fmaxf(fmaf(A1.x, s1.x - d1.x, B1.x), 0.f);
                    float v5 = fmaxf(fmaf(A1.y, s1.y - d1.y, B1.y), 0.f);
                    float v6 = fmaxf(fmaf(A1.z, s1.z - d1.z, B1.z), 0.f);
                    float v7 = fmaxf(fmaf(A1.w, s1.w - d1.w, B1.w), 0.f);
                    uint4 H;
                    H.x = ph2(v0, v1);
                    H.y = ph2(v2, v3);
                    H.z = ph2(v4, v5);
                    H.w = ph2(v6, v7);
                    uint32_t off = (uint32_t)(arow * ASTRIDE + ahalf * 32 + q * 8) * 2;
                    *(uint4*)(smem + off) = H;
                }
            }
            __syncthreads();
            // MMA over the chunk (4 k-steps of 16); 2 products per (ks, n-pair)
            const uint32_t within = lane & 15;
            const uint32_t brow = within & 7, bsel = within >> 3;
            const uint32_t ntoff = lane >> 4;
#pragma unroll
            for (int ks = 0; ks < 4; ks++) {
                uint32_t ah[4];
                uint32_t aaddr = sb +
                    (uint32_t)((w * 16 + (lane & 15)) * ASTRIDE + ks * 16 + (lane >> 4) * 8) * 2;
                ldsm4(ah, aaddr);
#pragma unroll
                for (int np = 0; np < 8; np++) {
                    uint32_t baddr = sb + BOFF +
                        (uint32_t)((np * 16 + ntoff * 8 + brow) * BSTRIDE + ch * 64 + ks * 16 + bsel * 8) * 2;
                    uint32_t bh[4], bl[4];
                    ldsm4(bh, baddr);
                    ldsm4(bl, baddr + BHALF);
                    mma16816f(acc[np * 2], ah, bh);
                    mma16816f(acc[np * 2], ah, bl);
                    mma16816f(acc[np * 2 + 1], ah, bh + 2);
                    mma16816f(acc[np * 2 + 1], ah, bl + 2);
                }
            }
        }
        // ---- epilogue: segmented max over CSR runs ----
        int erow = t * 128 + (w & 3) * 32 + lane;
        int dl = d_csrdst[erow];
        int prev = __shfl_up_sync(fullm, dl, 1);
        bool head = (lane == 0) || (dl != prev);
        unsigned Hb = __ballot_sync(fullm, head);
        unsigned mle;
        asm("mov.u32 %0, %%lanemask_le;" : "=r"(mle));
        int run_start = 31 - __clz(Hb & mle);
        bool tail = (lane == 31) || ((Hb >> (lane + 1)) & 1);
        unsigned* trow = d_tmpmax + (size_t)dl * 128;
#pragma unroll
        for (int g = 0; g < 4; g++) {
            __syncthreads();
#pragma unroll
            for (int q = 0; q < 4; q++) {
                int nt = g * 4 + q;
                int lcol = q * 8 + (lane & 3) * 2;
                int r0 = w * 16 + (lane >> 2);
                buf[r0 * 33 + lcol]           = acc[nt][0];
                buf[r0 * 33 + lcol + 1]       = acc[nt][1];
                buf[(r0 + 8) * 33 + lcol]     = acc[nt][2];
                buf[(r0 + 8) * 33 + lcol + 1] = acc[nt][3];
            }
            __syncthreads();
            int rr = (w & 3) * 32 + lane;
            int cb = (w >> 2) * 16;
            float v[16];
#pragma unroll
            for (int j = 0; j < 16; j++) v[j] = buf[rr * 33 + cb + j];
#pragma unroll
            for (int dlt = 1; dlt < 32; dlt <<= 1) {
#pragma unroll
                for (int j = 0; j < 16; j++) {
                    float u = __shfl_up_sync(fullm, v[j], dlt);
                    if ((int)lane - dlt >= run_start) v[j] = fmaxf(v[j], u);
                }
            }
            if (tail) {
#pragma unroll
                for (int j = 0; j < 16; j++) atomicMax(trow + g * 32 + cb + j, encf(v[j]));
            }
        }
    }
}

// ---------------- finalize: out[d] = deg>0 ? P[d] + dec(tmp[d]) : 0 ; reset tmp ----------------
__global__ void edge_final_kernel(const float* __restrict__ P, float* __restrict__ out) {
    int i = blockIdx.x * blockDim.x + threadIdx.x;
    if (i < NN * 128) {
        int d = i >> 7;
        float r = 0.f;
        if (d_indeg[d] > 0) r = P[i] + decf(d_tmpmax[i]);
        out[i] = r;
        d_tmpmax[i] = 0;  // reset for next edge layer / next replay
    }
}

// ---------------- fused last-layer finalize + FC; resets indeg & tmpmax for next replay ----------------
__global__ void fc_fused_kernel(const float* __restrict__ P, const float* __restrict__ Wfc,
                                const float* __restrict__ bfc, float* __restrict__ out) {
    int w = threadIdx.x >> 5, lane = threadIdx.x & 31;
    int d = blockIdx.x * 4 + w;
    if (d >= NN) return;
    bool nz = d_indeg[d] > 0;
    float s = 0.f;
#pragma unroll
    for (int u = 0; u < 4; u++) {
        int k = lane + 32 * u;
        size_t idx = (size_t)d * 128 + k;
        float h = nz ? P[idx] + decf(d_tmpmax[idx]) : 0.f;
        d_tmpmax[idx] = 0;  // reset for next replay
        s = fmaf(h, Wfc[k], s);
    }
#pragma unroll
    for (int off = 16; off; off >>= 1) s += __shfl_down_sync(0xffffffffu, s, off);
    if (lane == 0) {
        out[d] = s + bfc[0];
        d_indeg[d] = 0;  // reset for next replay (count_kernel accumulates)
    }
}

// ---------------- host ----------------
extern "C" void kernel_launch(void* const* d_in, const int* in_sizes, int n_in,
                              void* d_out, int out_size) {
    const float* x   = (const float*)d_in[0];
    const int*   ei  = (const int*)d_in[1];
    const float* Wm  = (const float*)d_in[2];
    const float* bm  = (const float*)d_in[3];
    const float* Wc  = (const float*)d_in[4];
    const float* bc  = (const float*)d_in[5];
    const float* Wg1 = (const float*)d_in[6];
    const float* bg1 = (const float*)d_in[7];
    const float* Wg2 = (const float*)d_in[8];
    const float* bg2 = (const float*)d_in[9];
    const float* Wg3 = (const float*)d_in[10];
    const float* bg3 = (const float*)d_in[11];
    const float* e1g = (const float*)d_in[12];
    const float* e1b = (const float*)d_in[13];
    const float* e1m = (const float*)d_in[14];
    const float* e1v = (const float*)d_in[15];
    const float* e1W = (const float*)d_in[16];
    const float* e2g = (const float*)d_in[17];
    const float* e2b = (const float*)d_in[18];
    const float* e2m = (const float*)d_in[19];
    const float* e2v = (const float*)d_in[20];
    const float* e2W = (const float*)d_in[21];
    const float* e3g = (const float*)d_in[22];
    const float* e3b = (const float*)d_in[23];
    const float* e3m = (const float*)d_in[24];
    const float* e3v = (const float*)d_in[25];
    const float* e3W = (const float*)d_in[26];
    const float* Wfc = (const float*)d_in[27];
    const float* bfc = (const float*)d_in[28];
    float* out = (float*)d_out;

    float *pA, *pB, *pH, *pX0, *pP, *pDa, *pDb;
    cudaGetSymbolAddress((void**)&pA,  d_bufA);
    cudaGetSymbolAddress((void**)&pB,  d_bufB);
    cudaGetSymbolAddress((void**)&pH,  d_h);
    cudaGetSymbolAddress((void**)&pX0, d_x0);
    cudaGetSymbolAddress((void**)&pP,  d_P);
    cudaGetSymbolAddress((void**)&pDa, d_aAff);
    cudaGetSymbolAddress((void**)&pDb, d_bAff);

    // smem: A(18432) + B(2 * 128*(C+8)*2)
    const int SME1 = 18432 + 2 * 128 * (256 + 8) * 2;  // 153600 (C=256)
    const int SME2 = 18432 + 2 * 128 * (128 + 8) * 2;  //  88064 (C=128, 2 CTAs/SM)
    cudaFuncSetAttribute(edge_mma_kernel<256>, cudaFuncAttributeMaxDynamicSharedMemorySize, SME1);
    cudaFuncSetAttribute(edge_mma_kernel<128>, cudaFuncAttributeMaxDynamicSharedMemorySize, SME2);

    // CSR build (indeg zeroed by fc_fused at end of previous replay; static-zero first run)
    count_kernel<<<(EE + 255) / 256, 256>>>(ei);
    scan_kernel<<<1, 1024>>>();
    fill_kernel<<<(EE + 255) / 256, 256>>>(ei);

    // dual projection (first one lands in the ncu-profiled slot)
    gemm_rows8<512, 64, false><<<2500, 64>>>(x, Wc, bc, nullptr, nullptr, pX0, 0, 1, NN);
    gemm_rows8<512, 64, false><<<625, 64>>>(x, Wm, bm, nullptr, nullptr, pX0, 0, 4, 5000);

    // GCN stack (aggregate-then-GEMM; agg is linear)
    gcn_agg_pre<64><<<NN / 2, 128>>>(pX0, pH);
    gemm_rows8<64, 128, false><<<2500, 128>>>(pH, Wg1, bg1, nullptr, nullptr, pA, 0, 1, NN);
    gcn_agg_pre<128><<<NN, 128>>>(pA, pH);
    gemm_rows8<128, 128, false><<<2500, 128>>>(pH, Wg2, bg2, nullptr, nullptr, pB, 0, 1, NN);
    gcn_agg_pre<128><<<NN, 128>>>(pB, pH);
    gemm_rows8<128, 256, false><<<2500, 256>>>(pH, Wg3, bg3, nullptr, nullptr, pA, 0, 1, NN);
    // g3 -> pA [N,256]

    // EdgeConv 1 (C=256): x = pA -> out pB
    bnaff_kernel<<<2, 256>>>(e1g, e1b, e1m, e1v, 512);
    gemm_rows8<256, 128, true><<<2500, 128>>>(pA, e1W, nullptr, pDa, pDb, pP, 0, 1, NN);
    wsplit_kernel<<<(256 * 128 + 255) / 256, 256>>>(e1W + 256 * 128, 256);
    edge_mma_kernel<256><<<148, 256, SME1>>>(pA, pDa + 256, pDb + 256);
    edge_final_kernel<<<(NN * 128 + 255) / 256, 256>>>(pP, pB);

    // EdgeConv 2 (C=128): x = pB -> out pA
    bnaff_kernel<<<1, 256>>>(e2g, e2b, e2m, e2v, 256);
    gemm_rows8<128, 128, true><<<2500, 128>>>(pB, e2W, nullptr, pDa, pDb, pP, 0, 1, NN);
    wsplit_kernel<<<(128 * 128 + 255) / 256, 256>>>(e2W + 128 * 128, 128);
    edge_mma_kernel<128><<<296, 256, SME2>>>(pB, pDa + 128, pDb + 128);
    edge_final_kernel<<<(NN * 128 + 255) / 256, 256>>>(pP, pA);

    // EdgeConv 3 (C=128): x = pA -> fused finalize+FC (+state reset for replay)
    bnaff_kernel<<<1, 256>>>(e3g, e3b, e3m, e3v, 256);
    gemm_rows8<128, 128, true><<<2500, 128>>>(pA, e3W, nullptr, pDa, pDb, pP, 0, 1, NN);
    wsplit_kernel<<<(128 * 128 + 255) / 256, 256>>>(e3W + 128 * 128, 128);
    edge_mma_kernel<128><<<296, 256, SME2>>>(pA, pDa + 128, pDb + 128);
    fc_fused_kernel<<<5000, 128>>>(pP, Wfc, bfc, out);
}

// round 7
// speedup vs baseline: 3.2856x; 1.0093x over previous
#include <cuda_runtime.h>
#include <cuda_bf16.h>
#include <cuda_fp16.h>
#include <cstdint>

#define NN 20000
#define EE 320000

// ---------------- scratch (device globals; no allocation) ----------------
__device__ float d_bufA[NN * 256];
__device__ float d_bufB[NN * 256];
__device__ float d_h[NN * 256];
__device__ float d_x0[NN * 64];
__device__ float d_P[NN * 128];
__device__ float d_aAff[512];
__device__ float d_bAff[512];
__device__ float d_dinv[NN];
__device__ int   d_indeg[NN];
__device__ int   d_rowptr[NN + 1];
__device__ int   d_cursor[NN];
__device__ int   d_csrsrc[EE];
__device__ int   d_csrdst[EE];
__device__ __half d_Whi[256 * 128];
__device__ __half d_Wlo[256 * 128];
__device__ unsigned d_tmpmax[NN * 128];

// ---------------- f32x2 packed helpers ----------------
__device__ __forceinline__ unsigned long long pack2(float x, float y) {
    unsigned long long r;
    unsigned a = __float_as_uint(x), b = __float_as_uint(y);
    asm("mov.b64 %0, {%1, %2};" : "=l"(r) : "r"(a), "r"(b));
    return r;
}
__device__ __forceinline__ unsigned long long bcast2(float x) {
    unsigned long long r;
    unsigned a = __float_as_uint(x);
    asm("mov.b64 %0, {%1, %1};" : "=l"(r) : "r"(a));
    return r;
}
__device__ __forceinline__ void fma2(unsigned long long& d, unsigned long long a, unsigned long long b) {
    asm("fma.rn.f32x2 %0, %1, %2, %0;" : "+l"(d) : "l"(a), "l"(b));
}
__device__ __forceinline__ float2 unpack2(unsigned long long v) {
    unsigned a, b;
    asm("mov.b64 {%0, %1}, %2;" : "=r"(a), "=r"(b) : "l"(v));
    return make_float2(__uint_as_float(a), __uint_as_float(b));
}

// ---------------- warp MMA helpers ----------------
__device__ __forceinline__ uint32_t smem_u32(const void* p) {
    uint32_t a;
    asm("{ .reg .u64 t; cvta.to.shared.u64 t, %1; cvt.u32.u64 %0, t; }" : "=r"(a) : "l"(p));
    return a;
}
__device__ __forceinline__ void ldsm4(uint32_t* r, uint32_t addr) {
    asm volatile("ldmatrix.sync.aligned.m8n8.x4.shared.b16 {%0,%1,%2,%3}, [%4];"
                 : "=r"(r[0]), "=r"(r[1]), "=r"(r[2]), "=r"(r[3]) : "r"(addr));
}
__device__ __forceinline__ void mma16816f(float* d, const uint32_t* a, const uint32_t* b) {
    asm volatile("mma.sync.aligned.m16n8k16.row.col.f32.f16.f16.f32 "
                 "{%0,%1,%2,%3}, {%4,%5,%6,%7}, {%8,%9}, {%0,%1,%2,%3};"
                 : "+f"(d[0]), "+f"(d[1]), "+f"(d[2]), "+f"(d[3])
                 : "r"(a[0]), "r"(a[1]), "r"(a[2]), "r"(a[3]), "r"(b[0]), "r"(b[1]));
}

__device__ __forceinline__ unsigned encf(float x) {
    unsigned s = __float_as_uint(x);
    return (s & 0x80000000u) ? ~s : (s | 0x80000000u);
}
__device__ __forceinline__ float decf(unsigned u) {
    return (u & 0x80000000u) ? __uint_as_float(u ^ 0x80000000u) : __uint_as_float(~u);
}
__device__ __forceinline__ uint32_t ph2(float a, float b) {
    __half2 h = __floats2half2_rn(a, b);
    return *(uint32_t*)&h;
}

// ---------------- CSR build ----------------
__global__ void count_kernel(const int* __restrict__ ei) {
    int i = blockIdx.x * blockDim.x + threadIdx.x;
    if (i < EE) atomicAdd(&d_indeg[ei[EE + i]], 1);
}
__global__ void scan_kernel() {
    __shared__ int sh[1024];
    __shared__ int carry;
    int tid = threadIdx.x;
    if (tid == 0) carry = 0;
    __syncthreads();
    for (int base = 0; base < NN; base += 1024) {
        int i = base + tid;
        int v = (i < NN) ? d_indeg[i] : 0;
        sh[tid] = v;
        __syncthreads();
        for (int off = 1; off < 1024; off <<= 1) {
            int t = (tid >= off) ? sh[tid - off] : 0;
            __syncthreads();
            sh[tid] += t;
            __syncthreads();
        }
        int incl = sh[tid];
        int base_c = carry;
        if (i < NN) {
            int excl = base_c + incl - v;
            d_rowptr[i] = excl;
            d_cursor[i] = excl;
            d_dinv[i] = rsqrtf((float)(v + 1));
        }
        __syncthreads();
        if (tid == 1023) carry = base_c + sh[1023];
        __syncthreads();
    }
    if (tid == 0) d_rowptr[NN] = carry;
}
__global__ void fill_kernel(const int* __restrict__ ei) {
    int i = blockIdx.x * blockDim.x + threadIdx.x;
    if (i < EE) {
        int s = ei[i];
        int d = ei[EE + i];
        int pos = atomicAdd(&d_cursor[d], 1);
        d_csrsrc[pos] = s;
        d_csrdst[pos] = d;
    }
}

// ---------------- tiled GEMM: out = act(A) @ W (+bias) ----------------
// Block = 256 threads, R = 2048/COUT rows, K staged in KC-chunks. Both A and W
// chunks live in SMEM so the k-loop never touches L2. f32x2 accumulators.
template <int K, int COUT, bool PRE>
__global__ __launch_bounds__(256) void gemm_tile(const float* __restrict__ A,
                                                 const float* __restrict__ W,
                                                 const float* __restrict__ bias,
                                                 const float* __restrict__ aAff,
                                                 const float* __restrict__ bAff,
                                                 float* __restrict__ out,
                                                 int rowStart, int rowStride, int numRows) {
    constexpr int R = 2048 / COUT;   // 32 / 16 / 8
    constexpr int KC = 4096 / COUT;  // 64 / 32 / 16
    constexpr int NCHK = K / KC;
    constexpr int ASTR = R + 4;      // float4-aligned, padded
    static_assert(K % KC == 0, "");
    __shared__ float Ws[KC * COUT];
    __shared__ float As[KC * ASTR];
    const int tid = threadIdx.x;
    const int c = tid % COUT;
    const int g = tid / COUT;        // row-group 0..R/8-1
    const int rblk = blockIdx.x * R;

    unsigned long long acc01 = 0, acc23 = 0, acc45 = 0, acc67 = 0;
    for (int ch = 0; ch < NCHK; ch++) {
        const int k0 = ch * KC;
        for (int idx = tid; idx < KC * COUT; idx += 256)
            Ws[idx] = W[(size_t)(k0 + idx / COUT) * COUT + (idx % COUT)];
        for (int idx = tid; idx < R * KC; idx += 256) {
            int r = idx / KC, k = idx - r * KC;
            int rr = rblk + r;
            float v = 0.f;
            if (rr < numRows) {
                int grow = rowStart + rr * rowStride;
                v = A[(size_t)grow * K + k0 + k];
                if (PRE) v = fmaxf(fmaf(aAff[k0 + k], v, bAff[k0 + k]), 0.f);
            }
            As[k * ASTR + r] = v;
        }
        __syncthreads();
#pragma unroll 4
        for (int k = 0; k < KC; k++) {
            float wv = Ws[k * COUT + c];
            unsigned long long ww = bcast2(wv);
            const float4* row = (const float4*)(As + k * ASTR + g * 8);
            float4 a03 = row[0], a47 = row[1];
            fma2(acc01, pack2(a03.x, a03.y), ww);
            fma2(acc23, pack2(a03.z, a03.w), ww);
            fma2(acc45, pack2(a47.x, a47.y), ww);
            fma2(acc67, pack2(a47.z, a47.w), ww);
        }
        __syncthreads();
    }
    float bv = bias ? bias[c] : 0.f;
    float res[8];
    float2 t;
    t = unpack2(acc01); res[0] = t.x; res[1] = t.y;
    t = unpack2(acc23); res[2] = t.x; res[3] = t.y;
    t = unpack2(acc45); res[4] = t.x; res[5] = t.y;
    t = unpack2(acc67); res[6] = t.x; res[7] = t.y;
#pragma unroll
    for (int j = 0; j < 8; j++) {
        int rr = rblk + g * 8 + j;
        if (rr < numRows) {
            int grow = rowStart + rr * rowStride;
            out[(size_t)grow * COUT + c] = res[j] + bv;
        }
    }
}

// ---------------- GCN aggregation on PRE-GEMM features (agg is linear) ----------------
template <int C>
__global__ void gcn_agg_pre(const float* __restrict__ x, float* __restrict__ out) {
    constexpr int NPB = 128 / C;
    int local = threadIdx.x / C;
    int node = blockIdx.x * NPB + local;
    int c = threadIdx.x - local * C;
    if (node >= NN) return;
    float dd = d_dinv[node];
    float self = x[(size_t)node * C + c] * dd * dd;
    int e0 = d_rowptr[node], e1 = d_rowptr[node + 1];
    float a0 = 0.f, a1 = 0.f, a2 = 0.f, a3 = 0.f;
    int e = e0;
    for (; e + 4 <= e1; e += 4) {
        int s0 = d_csrsrc[e], s1 = d_csrsrc[e + 1], s2 = d_csrsrc[e + 2], s3 = d_csrsrc[e + 3];
        float w0 = d_dinv[s0], w1 = d_dinv[s1], w2 = d_dinv[s2], w3 = d_dinv[s3];
        float h0 = x[(size_t)s0 * C + c];
        float h1 = x[(size_t)s1 * C + c];
        float h2 = x[(size_t)s2 * C + c];
        float h3 = x[(size_t)s3 * C + c];
        a0 = fmaf(h0, w0, a0);
        a1 = fmaf(h1, w1, a1);
        a2 = fmaf(h2, w2, a2);
        a3 = fmaf(h3, w3, a3);
    }
    for (; e < e1; e++) {
        int s = d_csrsrc[e];
        a0 = fmaf(x[(size_t)s * C + c], d_dinv[s], a0);
    }
    out[(size_t)node * C + c] = fmaf((a0 + a1) + (a2 + a3), dd, self);
}

// ---------------- BN affine precompute ----------------
__global__ void bnaff_kernel(const float* __restrict__ g, const float* __restrict__ be,
                             const float* __restrict__ mn, const float* __restrict__ vr, int n) {
    int i = blockIdx.x * blockDim.x + threadIdx.x;
    if (i < n) {
        float a = g[i] * rsqrtf(vr[i] + 1e-5f);
        d_aAff[i] = a;
        d_bAff[i] = fmaf(-mn[i], a, be[i]);
    }
}

// ---------------- W split/transpose: Wt[n][k] = fp16split(W[k][n]) ----------------
__global__ void wsplit_kernel(const float* __restrict__ W, int C) {
    int id = blockIdx.x * blockDim.x + threadIdx.x;
    if (id < C * 128) {
        int k = id >> 7, n = id & 127;
        float w = W[id];
        __half hi = __float2half_rn(w);
        __half lo = __float2half_rn(w - __half2float(hi));
        d_Whi[n * C + k] = hi;
        d_Wlo[n * C + k] = lo;
    }
}

// ---------------- EdgeConv via fp16 2-term mma.sync ----------------
template <int C>
__global__ __launch_bounds__(256, 2) void edge_mma_kernel(const float* __restrict__ x,
                                                          const float* __restrict__ aAff,
                                                          const float* __restrict__ bAff) {
    constexpr int NCH = C / 64;
    constexpr int ASTRIDE = 72;
    constexpr int ABYTES = 128 * ASTRIDE * 2;   // 18432
    constexpr int BOFF = ABYTES;
    constexpr int BSTRIDE = C + 8;
    constexpr int BHALF = 128 * BSTRIDE * 2;
    extern __shared__ char smem[];
    float* buf = (float*)smem;
    uint32_t sb = smem_u32(smem);
    const int tid = threadIdx.x, lane = tid & 31, w = tid >> 5;
    const unsigned fullm = 0xFFFFFFFFu;

    for (int idx = tid; idx < C * 128 / 8; idx += 256) {
        int n = idx / (C / 8), kb = (idx % (C / 8)) * 8;
        uint32_t off = BOFF + (uint32_t)(n * BSTRIDE + kb) * 2;
        *(uint4*)(smem + off) = ((const uint4*)d_Whi)[idx];
        *(uint4*)(smem + off + BHALF) = ((const uint4*)d_Wlo)[idx];
    }

    const int arow = tid >> 1, ahalf = tid & 1;

    for (int t = blockIdx.x; t < EE / 128; t += gridDim.x) {
        float acc[16][4];
#pragma unroll
        for (int i = 0; i < 16; i++) { acc[i][0] = acc[i][1] = acc[i][2] = acc[i][3] = 0.f; }

        const int sA = d_csrsrc[t * 128 + arow];
        const int dA = d_csrdst[t * 128 + arow];

        for (int ch = 0; ch < NCH; ch++) {
            __syncthreads();
            {
                int kb = ch * 64 + ahalf * 32;
                const float4* xs = (const float4*)(x + (size_t)sA * C + kb);
                const float4* xd = (const float4*)(x + (size_t)dA * C + kb);
                const float4* aa = (const float4*)(aAff + kb);
                const float4* bb = (const float4*)(bAff + kb);
#pragma unroll
                for (int q = 0; q < 4; q++) {
                    float4 s0 = xs[q * 2], s1 = xs[q * 2 + 1];
                    float4 d0 = xd[q * 2], d1 = xd[q * 2 + 1];
                    float4 A0 = __ldg(aa + q * 2), A1 = __ldg(aa + q * 2 + 1);
                    float4 B0 = __ldg(bb + q * 2), B1 = __ldg(bb + q * 2 + 1);
                    float v0 = fmaxf(fmaf(A0.x, s0.x - d0.x, B0.x), 0.f);
                    float v1 = fmaxf(fmaf(A0.y, s0.y - d0.y, B0.y), 0.f);
                    float v2 = fmaxf(fmaf(A0.z, s0.z - d0.z, B0.z), 0.f);
                    float v3 = fmaxf(fmaf(A0.w, s0.w - d0.w, B0.w), 0.f);
                    float v4 = fmaxf(fmaf(A1.x, s1.x - d1.x, B1.x), 0.f);
                    float v5 = fmaxf(fmaf(A1.y, s1.y - d1.y, B1.y), 0.f);
                    float v6 = fmaxf(fmaf(A1.z, s1.z - d1.z, B1.z), 0.f);
                    float v7 = fmaxf(fmaf(A1.w, s1.w - d1.w, B1.w), 0.f);
                    uint4 H;
                    H.x = ph2(v0, v1);
                    H.y = ph2(v2, v3);
                    H.z = ph2(v4, v5);
                    H.w = ph2(v6, v7);
                    uint32_t off = (uint32_t)(arow * ASTRIDE + ahalf * 32 + q * 8) * 2;
                    *(uint4*)(smem + off) = H;
                }
            }
            __syncthreads();
            const uint32_t within = lane & 15;
            const uint32_t brow = within & 7, bsel = within >> 3;
            const uint32_t ntoff = lane >> 4;
#pragma unroll
            for (int ks = 0; ks < 4; ks++) {
                uint32_t ah[4];
                uint32_t aaddr = sb +
                    (uint32_t)((w * 16 + (lane & 15)) * ASTRIDE + ks * 16 + (lane >> 4) * 8) * 2;
                ldsm4(ah, aaddr);
#pragma unroll
                for (int np = 0; np < 8; np++) {
                    uint32_t baddr = sb + BOFF +
                        (uint32_t)((np * 16 + ntoff * 8 + brow) * BSTRIDE + ch * 64 + ks * 16 + bsel * 8) * 2;
                    uint32_t bh[4], bl[4];
                    ldsm4(bh, baddr);
                    ldsm4(bl, baddr + BHALF);
                    mma16816f(acc[np * 2], ah, bh);
                    mma16816f(acc[np * 2], ah, bl);
                    mma16816f(acc[np * 2 + 1], ah, bh + 2);
                    mma16816f(acc[np * 2 + 1], ah, bl + 2);
                }
            }
        }
        // ---- epilogue: segmented max over CSR runs ----
        int erow = t * 128 + (w & 3) * 32 + lane;
        int dl = d_csrdst[erow];
        int prev = __shfl_up_sync(fullm, dl, 1);
        bool head = (lane == 0) || (dl != prev);
        unsigned Hb = __ballot_sync(fullm, head);
        unsigned mle;
        asm("mov.u32 %0, %%lanemask_le;" : "=r"(mle));
        int run_start = 31 - __clz(Hb & mle);
        bool tail = (lane == 31) || ((Hb >> (lane + 1)) & 1);
        unsigned* trow = d_tmpmax + (size_t)dl * 128;
#pragma unroll
        for (int g = 0; g < 4; g++) {
            __syncthreads();
#pragma unroll
            for (int q = 0; q < 4; q++) {
                int nt = g * 4 + q;
                int lcol = q * 8 + (lane & 3) * 2;
                int r0 = w * 16 + (lane >> 2);
                buf[r0 * 33 + lcol]           = acc[nt][0];
                buf[r0 * 33 + lcol + 1]       = acc[nt][1];
                buf[(r0 + 8) * 33 + lcol]     = acc[nt][2];
                buf[(r0 + 8) * 33 + lcol + 1] = acc[nt][3];
            }
            __syncthreads();
            int rr = (w & 3) * 32 + lane;
            int cb = (w >> 2) * 16;
            float v[16];
#pragma unroll
            for (int j = 0; j < 16; j++) v[j] = buf[rr * 33 + cb + j];
#pragma unroll
            for (int dlt = 1; dlt < 32; dlt <<= 1) {
#pragma unroll
                for (int j = 0; j < 16; j++) {
                    float u = __shfl_up_sync(fullm, v[j], dlt);
                    if ((int)lane - dlt >= run_start) v[j] = fmaxf(v[j], u);
                }
            }
            if (tail) {
#pragma unroll
                for (int j = 0; j < 16; j++) atomicMax(trow + g * 32 + cb + j, encf(v[j]));
            }
        }
    }
}

// ---------------- finalize: out[d] = deg>0 ? P[d] + dec(tmp[d]) : 0 ; reset tmp ----------------
__global__ void edge_final_kernel(const float* __restrict__ P, float* __restrict__ out) {
    int i = blockIdx.x * blockDim.x + threadIdx.x;
    if (i < NN * 128) {
        int d = i >> 7;
        float r = 0.f;
        if (d_indeg[d] > 0) r = P[i] + decf(d_tmpmax[i]);
        out[i] = r;
        d_tmpmax[i] = 0;
    }
}

// ---------------- fused last-layer finalize + FC; resets indeg & tmpmax ----------------
__global__ void fc_fused_kernel(const float* __restrict__ P, const float* __restrict__ Wfc,
                                const float* __restrict__ bfc, float* __restrict__ out) {
    int w = threadIdx.x >> 5, lane = threadIdx.x & 31;
    int d = blockIdx.x * 4 + w;
    if (d >= NN) return;
    bool nz = d_indeg[d] > 0;
    float s = 0.f;
#pragma unroll
    for (int u = 0; u < 4; u++) {
        int k = lane + 32 * u;
        size_t idx = (size_t)d * 128 + k;
        float h = nz ? P[idx] + decf(d_tmpmax[idx]) : 0.f;
        d_tmpmax[idx] = 0;
        s = fmaf(h, Wfc[k], s);
    }
#pragma unroll
    for (int off = 16; off; off >>= 1) s += __shfl_down_sync(0xffffffffu, s, off);
    if (lane == 0) {
        out[d] = s + bfc[0];
        d_indeg[d] = 0;
    }
}

// ---------------- host ----------------
extern "C" void kernel_launch(void* const* d_in, const int* in_sizes, int n_in,
                              void* d_out, int out_size) {
    const float* x   = (const float*)d_in[0];
    const int*   ei  = (const int*)d_in[1];
    const float* Wm  = (const float*)d_in[2];
    const float* bm  = (const float*)d_in[3];
    const float* Wc  = (const float*)d_in[4];
    const float* bc  = (const float*)d_in[5];
    const float* Wg1 = (const float*)d_in[6];
    const float* bg1 = (const float*)d_in[7];
    const float* Wg2 = (const float*)d_in[8];
    const float* bg2 = (const float*)d_in[9];
    const float* Wg3 = (const float*)d_in[10];
    const float* bg3 = (const float*)d_in[11];
    const float* e1g = (const float*)d_in[12];
    const float* e1b = (const float*)d_in[13];
    const float* e1m = (const float*)d_in[14];
    const float* e1v = (const float*)d_in[15];
    const float* e1W = (const float*)d_in[16];
    const float* e2g = (const float*)d_in[17];
    const float* e2b = (const float*)d_in[18];
    const float* e2m = (const float*)d_in[19];
    const float* e2v = (const float*)d_in[20];
    const float* e2W = (const float*)d_in[21];
    const float* e3g = (const float*)d_in[22];
    const float* e3b = (const float*)d_in[23];
    const float* e3m = (const float*)d_in[24];
    const float* e3v = (const float*)d_in[25];
    const float* e3W = (const float*)d_in[26];
    const float* Wfc = (const float*)d_in[27];
    const float* bfc = (const float*)d_in[28];
    float* out = (float*)d_out;

    float *pA, *pB, *pH, *pX0, *pP, *pDa, *pDb;
    cudaGetSymbolAddress((void**)&pA,  d_bufA);
    cudaGetSymbolAddress((void**)&pB,  d_bufB);
    cudaGetSymbolAddress((void**)&pH,  d_h);
    cudaGetSymbolAddress((void**)&pX0, d_x0);
    cudaGetSymbolAddress((void**)&pP,  d_P);
    cudaGetSymbolAddress((void**)&pDa, d_aAff);
    cudaGetSymbolAddress((void**)&pDb, d_bAff);

    const int SME1 = 18432 + 2 * 128 * (256 + 8) * 2;  // 153600 (C=256)
    const int SME2 = 18432 + 2 * 128 * (128 + 8) * 2;  //  88064 (C=128, 2 CTAs/SM)
    cudaFuncSetAttribute(edge_mma_kernel<256>, cudaFuncAttributeMaxDynamicSharedMemorySize, SME1);
    cudaFuncSetAttribute(edge_mma_kernel<128>, cudaFuncAttributeMaxDynamicSharedMemorySize, SME2);

    // CSR build (indeg zeroed by fc_fused at end of previous replay)
    count_kernel<<<(EE + 255) / 256, 256>>>(ei);
    scan_kernel<<<1, 1024>>>();
    fill_kernel<<<(EE + 255) / 256, 256>>>(ei);

    // dual projection
    gemm_tile<512, 64, false><<<625, 256>>>(x, Wc, bc, nullptr, nullptr, pX0, 0, 1, NN);
    gemm_tile<512, 64, false><<<157, 256>>>(x, Wm, bm, nullptr, nullptr, pX0, 0, 4, 5000);

    // GCN stack (aggregate-then-GEMM; agg is linear)
    gcn_agg_pre<64><<<NN / 2, 128>>>(pX0, pH);
    gemm_tile<64, 128, false><<<1250, 256>>>(pH, Wg1, bg1, nullptr, nullptr, pA, 0, 1, NN);
    gcn_agg_pre<128><<<NN, 128>>>(pA, pH);
    gemm_tile<128, 128, false><<<1250, 256>>>(pH, Wg2, bg2, nullptr, nullptr, pB, 0, 1, NN);
    gcn_agg_pre<128><<<NN, 128>>>(pB, pH);
    gemm_tile<128, 256, false><<<2500, 256>>>(pH, Wg3, bg3, nullptr, nullptr, pA, 0, 1, NN);
    // g3 -> pA [N,256]

    // EdgeConv 1 (C=256): x = pA -> out pB
    bnaff_kernel<<<2, 256>>>(e1g, e1b, e1m, e1v, 512);
    gemm_tile<256, 128, true><<<1250, 256>>>(pA, e1W, nullptr, pDa, pDb, pP, 0, 1, NN);
    wsplit_kernel<<<(256 * 128 + 255) / 256, 256>>>(e1W + 256 * 128, 256);
    edge_mma_kernel<256><<<148, 256, SME1>>>(pA, pDa + 256, pDb + 256);
    edge_final_kernel<<<(NN * 128 + 255) / 256, 256>>>(pP, pB);

    // EdgeConv 2 (C=128): x = pB -> out pA
    bnaff_kernel<<<1, 256>>>(e2g, e2b, e2m, e2v, 256);
    gemm_tile<128, 128, true><<<1250, 256>>>(pB, e2W, nullptr, pDa, pDb, pP, 0, 1, NN);
    wsplit_kernel<<<(128 * 128 + 255) / 256, 256>>>(e2W + 128 * 128, 128);
    edge_mma_kernel<128><<<296, 256, SME2>>>(pB, pDa + 128, pDb + 128);
    edge_final_kernel<<<(NN * 128 + 255) / 256, 256>>>(pP, pA);

    // EdgeConv 3 (C=128): x = pA -> fused finalize+FC (+state reset for replay)
    bnaff_kernel<<<1, 256>>>(e3g, e3b, e3m, e3v, 256);
    gemm_tile<128, 128, true><<<1250, 256>>>(pA, e3W, nullptr, pDa, pDb, pP, 0, 1, NN);
    wsplit_kernel<<<(128 * 128 + 255) / 256, 256>>>(e3W + 128 * 128, 128);
    edge_mma_kernel<128><<<296, 256, SME2>>>(pA, pDa + 128, pDb + 128);
    fc_fused_kernel<<<5000, 128>>>(pP, Wfc, bfc, out);
}

// round 8
// speedup vs baseline: 3.5762x; 1.0885x over previous
#include <cuda_runtime.h>
#include <cuda_bf16.h>
#include <cuda_fp16.h>
#include <cstdint>

#define NN 20000
#define EE 320000

// ---------------- scratch (device globals; no allocation) ----------------
__device__ float d_bufA[NN * 256];
__device__ float d_bufB[NN * 256];
__device__ float d_h[NN * 256];
__device__ float d_x0[NN * 64];
__device__ float d_P[NN * 128];
__device__ float d_aAff[512];
__device__ float d_bAff[512];
__device__ float d_dinv[NN];
__device__ int   d_indeg[NN];
__device__ int   d_rowptr[NN + 1];
__device__ int   d_cursor[NN];
__device__ int   d_csrsrc[EE];
__device__ int   d_csrdst[EE];
__device__ __half d_Whi[256 * 128];
__device__ unsigned d_tmpmax[NN * 128];

// ---------------- f32x2 packed helpers ----------------
__device__ __forceinline__ unsigned long long pack2(float x, float y) {
    unsigned long long r;
    unsigned a = __float_as_uint(x), b = __float_as_uint(y);
    asm("mov.b64 %0, {%1, %2};" : "=l"(r) : "r"(a), "r"(b));
    return r;
}
__device__ __forceinline__ unsigned long long bcast2(float x) {
    unsigned long long r;
    unsigned a = __float_as_uint(x);
    asm("mov.b64 %0, {%1, %1};" : "=l"(r) : "r"(a));
    return r;
}
__device__ __forceinline__ void fma2(unsigned long long& d, unsigned long long a, unsigned long long b) {
    asm("fma.rn.f32x2 %0, %1, %2, %0;" : "+l"(d) : "l"(a), "l"(b));
}
__device__ __forceinline__ float2 unpack2(unsigned long long v) {
    unsigned a, b;
    asm("mov.b64 {%0, %1}, %2;" : "=r"(a), "=r"(b) : "l"(v));
    return make_float2(__uint_as_float(a), __uint_as_float(b));
}

// ---------------- warp MMA helpers ----------------
__device__ __forceinline__ uint32_t smem_u32(const void* p) {
    uint32_t a;
    asm("{ .reg .u64 t; cvta.to.shared.u64 t, %1; cvt.u32.u64 %0, t; }" : "=r"(a) : "l"(p));
    return a;
}
__device__ __forceinline__ void ldsm4(uint32_t* r, uint32_t addr) {
    asm volatile("ldmatrix.sync.aligned.m8n8.x4.shared.b16 {%0,%1,%2,%3}, [%4];"
                 : "=r"(r[0]), "=r"(r[1]), "=r"(r[2]), "=r"(r[3]) : "r"(addr));
}
__device__ __forceinline__ void mma16816f(float* d, const uint32_t* a, const uint32_t* b) {
    asm volatile("mma.sync.aligned.m16n8k16.row.col.f32.f16.f16.f32 "
                 "{%0,%1,%2,%3}, {%4,%5,%6,%7}, {%8,%9}, {%0,%1,%2,%3};"
                 : "+f"(d[0]), "+f"(d[1]), "+f"(d[2]), "+f"(d[3])
                 : "r"(a[0]), "r"(a[1]), "r"(a[2]), "r"(a[3]), "r"(b[0]), "r"(b[1]));
}

__device__ __forceinline__ unsigned encf(float x) {
    unsigned s = __float_as_uint(x);
    return (s & 0x80000000u) ? ~s : (s | 0x80000000u);
}
__device__ __forceinline__ float decf(unsigned u) {
    return (u & 0x80000000u) ? __uint_as_float(u ^ 0x80000000u) : __uint_as_float(~u);
}
__device__ __forceinline__ uint32_t ph2(float a, float b) {
    __half2 h = __floats2half2_rn(a, b);
    return *(uint32_t*)&h;
}

// ---------------- CSR build ----------------
__global__ void count_kernel(const int* __restrict__ ei) {
    int i = blockIdx.x * blockDim.x + threadIdx.x;
    if (i < EE) atomicAdd(&d_indeg[ei[EE + i]], 1);
}
__global__ void scan_kernel() {
    __shared__ int sh[1024];
    __shared__ int carry;
    int tid = threadIdx.x;
    if (tid == 0) carry = 0;
    __syncthreads();
    for (int base = 0; base < NN; base += 1024) {
        int i = base + tid;
        int v = (i < NN) ? d_indeg[i] : 0;
        sh[tid] = v;
        __syncthreads();
        for (int off = 1; off < 1024; off <<= 1) {
            int t = (tid >= off) ? sh[tid - off] : 0;
            __syncthreads();
            sh[tid] += t;
            __syncthreads();
        }
        int incl = sh[tid];
        int base_c = carry;
        if (i < NN) {
            int excl = base_c + incl - v;
            d_rowptr[i] = excl;
            d_cursor[i] = excl;
            d_dinv[i] = rsqrtf((float)(v + 1));
        }
        __syncthreads();
        if (tid == 1023) carry = base_c + sh[1023];
        __syncthreads();
    }
    if (tid == 0) d_rowptr[NN] = carry;
}
__global__ void fill_kernel(const int* __restrict__ ei) {
    int i = blockIdx.x * blockDim.x + threadIdx.x;
    if (i < EE) {
        int s = ei[i];
        int d = ei[EE + i];
        int pos = atomicAdd(&d_cursor[d], 1);
        d_csrsrc[pos] = s;
        d_csrdst[pos] = d;
    }
}

// ---------------- tiled GEMM: out = act(A) @ W (+bias) ----------------
template <int K, int COUT, bool PRE>
__global__ __launch_bounds__(256) void gemm_tile(const float* __restrict__ A,
                                                 const float* __restrict__ W,
                                                 const float* __restrict__ bias,
                                                 const float* __restrict__ aAff,
                                                 const float* __restrict__ bAff,
                                                 float* __restrict__ out,
                                                 int rowStart, int rowStride, int numRows) {
    constexpr int R = 2048 / COUT;
    constexpr int KC = 4096 / COUT;
    constexpr int NCHK = K / KC;
    constexpr int ASTR = R + 4;
    static_assert(K % KC == 0, "");
    __shared__ float Ws[KC * COUT];
    __shared__ float As[KC * ASTR];
    const int tid = threadIdx.x;
    const int c = tid % COUT;
    const int g = tid / COUT;
    const int rblk = blockIdx.x * R;

    unsigned long long acc01 = 0, acc23 = 0, acc45 = 0, acc67 = 0;
    for (int ch = 0; ch < NCHK; ch++) {
        const int k0 = ch * KC;
        for (int idx = tid; idx < KC * COUT; idx += 256)
            Ws[idx] = W[(size_t)(k0 + idx / COUT) * COUT + (idx % COUT)];
        for (int idx = tid; idx < R * KC; idx += 256) {
            int r = idx / KC, k = idx - r * KC;
            int rr = rblk + r;
            float v = 0.f;
            if (rr < numRows) {
                int grow = rowStart + rr * rowStride;
                v = A[(size_t)grow * K + k0 + k];
                if (PRE) v = fmaxf(fmaf(aAff[k0 + k], v, bAff[k0 + k]), 0.f);
            }
            As[k * ASTR + r] = v;
        }
        __syncthreads();
#pragma unroll 4
        for (int k = 0; k < KC; k++) {
            float wv = Ws[k * COUT + c];
            unsigned long long ww = bcast2(wv);
            const float4* row = (const float4*)(As + k * ASTR + g * 8);
            float4 a03 = row[0], a47 = row[1];
            fma2(acc01, pack2(a03.x, a03.y), ww);
            fma2(acc23, pack2(a03.z, a03.w), ww);
            fma2(acc45, pack2(a47.x, a47.y), ww);
            fma2(acc67, pack2(a47.z, a47.w), ww);
        }
        __syncthreads();
    }
    float bv = bias ? bias[c] : 0.f;
    float res[8];
    float2 t;
    t = unpack2(acc01); res[0] = t.x; res[1] = t.y;
    t = unpack2(acc23); res[2] = t.x; res[3] = t.y;
    t = unpack2(acc45); res[4] = t.x; res[5] = t.y;
    t = unpack2(acc67); res[6] = t.x; res[7] = t.y;
#pragma unroll
    for (int j = 0; j < 8; j++) {
        int rr = rblk + g * 8 + j;
        if (rr < numRows) {
            int grow = rowStart + rr * rowStride;
            out[(size_t)grow * COUT + c] = res[j] + bv;
        }
    }
}

// ---------------- GCN aggregation on PRE-GEMM features (agg is linear) ----------------
template <int C>
__global__ void gcn_agg_pre(const float* __restrict__ x, float* __restrict__ out) {
    constexpr int NPB = 128 / C;
    int local = threadIdx.x / C;
    int node = blockIdx.x * NPB + local;
    int c = threadIdx.x - local * C;
    if (node >= NN) return;
    float dd = d_dinv[node];
    float self = x[(size_t)node * C + c] * dd * dd;
    int e0 = d_rowptr[node], e1 = d_rowptr[node + 1];
    float a0 = 0.f, a1 = 0.f, a2 = 0.f, a3 = 0.f;
    int e = e0;
    for (; e + 4 <= e1; e += 4) {
        int s0 = d_csrsrc[e], s1 = d_csrsrc[e + 1], s2 = d_csrsrc[e + 2], s3 = d_csrsrc[e + 3];
        float w0 = d_dinv[s0], w1 = d_dinv[s1], w2 = d_dinv[s2], w3 = d_dinv[s3];
        float h0 = x[(size_t)s0 * C + c];
        float h1 = x[(size_t)s1 * C + c];
        float h2 = x[(size_t)s2 * C + c];
        float h3 = x[(size_t)s3 * C + c];
        a0 = fmaf(h0, w0, a0);
        a1 = fmaf(h1, w1, a1);
        a2 = fmaf(h2, w2, a2);
        a3 = fmaf(h3, w3, a3);
    }
    for (; e < e1; e++) {
        int s = d_csrsrc[e];
        a0 = fmaf(x[(size_t)s * C + c], d_dinv[s], a0);
    }
    out[(size_t)node * C + c] = fmaf((a0 + a1) + (a2 + a3), dd, self);
}

// ---------------- BN affine precompute ----------------
__global__ void bnaff_kernel(const float* __restrict__ g, const float* __restrict__ be,
                             const float* __restrict__ mn, const float* __restrict__ vr, int n) {
    int i = blockIdx.x * blockDim.x + threadIdx.x;
    if (i < n) {
        float a = g[i] * rsqrtf(vr[i] + 1e-5f);
        d_aAff[i] = a;
        d_bAff[i] = fmaf(-mn[i], a, be[i]);
    }
}

// ---------------- W transpose to fp16: Wt[n][k] = fp16(W[k][n]) ----------------
__global__ void wsplit_kernel(const float* __restrict__ W, int C) {
    int id = blockIdx.x * blockDim.x + threadIdx.x;
    if (id < C * 128) {
        int k = id >> 7, n = id & 127;
        d_Whi[n * C + k] = __float2half_rn(W[id]);
    }
}

// ---------------- EdgeConv via single-fp16 mma.sync ----------------
// Tile = 128 edges x 128 outs. Q = ReLU(a*(x[s]-x[d])+b) @ Wbot, both operands fp16.
template <int C>
__global__ __launch_bounds__(256, 2) void edge_mma_kernel(const float* __restrict__ x,
                                                          const float* __restrict__ aAff,
                                                          const float* __restrict__ bAff) {
    constexpr int NCH = C / 64;
    constexpr int ASTRIDE = 72;
    constexpr int ABYTES = 128 * ASTRIDE * 2;   // 18432
    constexpr int BOFF = ABYTES;
    constexpr int BSTRIDE = C + 8;
    extern __shared__ char smem[];
    float* buf = (float*)smem;
    uint32_t sb = smem_u32(smem);
    const int tid = threadIdx.x, lane = tid & 31, w = tid >> 5;
    const unsigned fullm = 0xFFFFFFFFu;

    for (int idx = tid; idx < C * 128 / 8; idx += 256) {
        int n = idx / (C / 8), kb = (idx % (C / 8)) * 8;
        uint32_t off = BOFF + (uint32_t)(n * BSTRIDE + kb) * 2;
        *(uint4*)(smem + off) = ((const uint4*)d_Whi)[idx];
    }

    const int arow = tid >> 1, ahalf = tid & 1;

    for (int t = blockIdx.x; t < EE / 128; t += gridDim.x) {
        float acc[16][4];
#pragma unroll
        for (int i = 0; i < 16; i++) { acc[i][0] = acc[i][1] = acc[i][2] = acc[i][3] = 0.f; }

        const int sA = d_csrsrc[t * 128 + arow];
        const int dA = d_csrdst[t * 128 + arow];

        for (int ch = 0; ch < NCH; ch++) {
            __syncthreads();
            {
                int kb = ch * 64 + ahalf * 32;
                const float4* xs = (const float4*)(x + (size_t)sA * C + kb);
                const float4* xd = (const float4*)(x + (size_t)dA * C + kb);
                const float4* aa = (const float4*)(aAff + kb);
                const float4* bb = (const float4*)(bAff + kb);
#pragma unroll
                for (int q = 0; q < 4; q++) {
                    float4 s0 = xs[q * 2], s1 = xs[q * 2 + 1];
                    float4 d0 = xd[q * 2], d1 = xd[q * 2 + 1];
                    float4 A0 = __ldg(aa + q * 2), A1 = __ldg(aa + q * 2 + 1);
                    float4 B0 = __ldg(bb + q * 2), B1 = __ldg(bb + q * 2 + 1);
                    float v0 = fmaxf(fmaf(A0.x, s0.x - d0.x, B0.x), 0.f);
                    float v1 = fmaxf(fmaf(A0.y, s0.y - d0.y, B0.y), 0.f);
                    float v2 = fmaxf(fmaf(A0.z, s0.z - d0.z, B0.z), 0.f);
                    float v3 = fmaxf(fmaf(A0.w, s0.w - d0.w, B0.w), 0.f);
                    float v4 = fmaxf(fmaf(A1.x, s1.x - d1.x, B1.x), 0.f);
                    float v5 = fmaxf(fmaf(A1.y, s1.y - d1.y, B1.y), 0.f);
                    float v6 = fmaxf(fmaf(A1.z, s1.z - d1.z, B1.z), 0.f);
                    float v7 = fmaxf(fmaf(A1.w, s1.w - d1.w, B1.w), 0.f);
                    uint4 H;
                    H.x = ph2(v0, v1);
                    H.y = ph2(v2, v3);
                    H.z = ph2(v4, v5);
                    H.w = ph2(v6, v7);
                    uint32_t off = (uint32_t)(arow * ASTRIDE + ahalf * 32 + q * 8) * 2;
                    *(uint4*)(smem + off) = H;
                }
            }
            __syncthreads();
            const uint32_t within = lane & 15;
            const uint32_t brow = within & 7, bsel = within >> 3;
            const uint32_t ntoff = lane >> 4;
#pragma unroll
            for (int ks = 0; ks < 4; ks++) {
                uint32_t ah[4];
                uint32_t aaddr = sb +
                    (uint32_t)((w * 16 + (lane & 15)) * ASTRIDE + ks * 16 + (lane >> 4) * 8) * 2;
                ldsm4(ah, aaddr);
#pragma unroll
                for (int np = 0; np < 8; np++) {
                    uint32_t baddr = sb + BOFF +
                        (uint32_t)((np * 16 + ntoff * 8 + brow) * BSTRIDE + ch * 64 + ks * 16 + bsel * 8) * 2;
                    uint32_t bh[4];
                    ldsm4(bh, baddr);
                    mma16816f(acc[np * 2], ah, bh);
                    mma16816f(acc[np * 2 + 1], ah, bh + 2);
                }
            }
        }
        // ---- epilogue: segmented max over CSR runs ----
        int erow = t * 128 + (w & 3) * 32 + lane;
        int dl = d_csrdst[erow];
        int prev = __shfl_up_sync(fullm, dl, 1);
        bool head = (lane == 0) || (dl != prev);
        unsigned Hb = __ballot_sync(fullm, head);
        unsigned mle;
        asm("mov.u32 %0, %%lanemask_le;" : "=r"(mle));
        int run_start = 31 - __clz(Hb & mle);
        bool tail = (lane == 31) || ((Hb >> (lane + 1)) & 1);
        unsigned* trow = d_tmpmax + (size_t)dl * 128;
#pragma unroll
        for (int g = 0; g < 4; g++) {
            __syncthreads();
#pragma unroll
            for (int q = 0; q < 4; q++) {
                int nt = g * 4 + q;
                int lcol = q * 8 + (lane & 3) * 2;
                int r0 = w * 16 + (lane >> 2);
                buf[r0 * 33 + lcol]           = acc[nt][0];
                buf[r0 * 33 + lcol + 1]       = acc[nt][1];
                buf[(r0 + 8) * 33 + lcol]     = acc[nt][2];
                buf[(r0 + 8) * 33 + lcol + 1] = acc[nt][3];
            }
            __syncthreads();
            int rr = (w & 3) * 32 + lane;
            int cb = (w >> 2) * 16;
            float v[16];
#pragma unroll
            for (int j = 0; j < 16; j++) v[j] = buf[rr * 33 + cb + j];
#pragma unroll
            for (int dlt = 1; dlt < 32; dlt <<= 1) {
#pragma unroll
                for (int j = 0; j < 16; j++) {
                    float u = __shfl_up_sync(fullm, v[j], dlt);
                    if ((int)lane - dlt >= run_start) v[j] = fmaxf(v[j], u);
                }
            }
            if (tail) {
#pragma unroll
                for (int j = 0; j < 16; j++) atomicMax(trow + g * 32 + cb + j, encf(v[j]));
            }
        }
    }
}

// ---------------- finalize: out[d] = deg>0 ? P[d] + dec(tmp[d]) : 0 ; reset tmp ----------------
__global__ void edge_final_kernel(const float* __restrict__ P, float* __restrict__ out) {
    int i = blockIdx.x * blockDim.x + threadIdx.x;
    if (i < NN * 128) {
        int d = i >> 7;
        float r = 0.f;
        if (d_indeg[d] > 0) r = P[i] + decf(d_tmpmax[i]);
        out[i] = r;
        d_tmpmax[i] = 0;
    }
}

// ---------------- fused last-layer finalize + FC; resets indeg & tmpmax ----------------
__global__ void fc_fused_kernel(const float* __restrict__ P, const float* __restrict__ Wfc,
                                const float* __restrict__ bfc, float* __restrict__ out) {
    int w = threadIdx.x >> 5, lane = threadIdx.x & 31;
    int d = blockIdx.x * 4 + w;
    if (d >= NN) return;
    bool nz = d_indeg[d] > 0;
    float s = 0.f;
#pragma unroll
    for (int u = 0; u < 4; u++) {
        int k = lane + 32 * u;
        size_t idx = (size_t)d * 128 + k;
        float h = nz ? P[idx] + decf(d_tmpmax[idx]) : 0.f;
        d_tmpmax[idx] = 0;
        s = fmaf(h, Wfc[k], s);
    }
#pragma unroll
    for (int off = 16; off; off >>= 1) s += __shfl_down_sync(0xffffffffu, s, off);
    if (lane == 0) {
        out[d] = s + bfc[0];
        d_indeg[d] = 0;
    }
}

// ---------------- host ----------------
extern "C" void kernel_launch(void* const* d_in, const int* in_sizes, int n_in,
                              void* d_out, int out_size) {
    const float* x   = (const float*)d_in[0];
    const int*   ei  = (const int*)d_in[1];
    const float* Wm  = (const float*)d_in[2];
    const float* bm  = (const float*)d_in[3];
    const float* Wc  = (const float*)d_in[4];
    const float* bc  = (const float*)d_in[5];
    const float* Wg1 = (const float*)d_in[6];
    const float* bg1 = (const float*)d_in[7];
    const float* Wg2 = (const float*)d_in[8];
    const float* bg2 = (const float*)d_in[9];
    const float* Wg3 = (const float*)d_in[10];
    const float* bg3 = (const float*)d_in[11];
    const float* e1g = (const float*)d_in[12];
    const float* e1b = (const float*)d_in[13];
    const float* e1m = (const float*)d_in[14];
    const float* e1v = (const float*)d_in[15];
    const float* e1W = (const float*)d_in[16];
    const float* e2g = (const float*)d_in[17];
    const float* e2b = (const float*)d_in[18];
    const float* e2m = (const float*)d_in[19];
    const float* e2v = (const float*)d_in[20];
    const float* e2W = (const float*)d_in[21];
    const float* e3g = (const float*)d_in[22];
    const float* e3b = (const float*)d_in[23];
    const float* e3m = (const float*)d_in[24];
    const float* e3v = (const float*)d_in[25];
    const float* e3W = (const float*)d_in[26];
    const float* Wfc = (const float*)d_in[27];
    const float* bfc = (const float*)d_in[28];
    float* out = (float*)d_out;

    float *pA, *pB, *pH, *pX0, *pP, *pDa, *pDb;
    cudaGetSymbolAddress((void**)&pA,  d_bufA);
    cudaGetSymbolAddress((void**)&pB,  d_bufB);
    cudaGetSymbolAddress((void**)&pH,  d_h);
    cudaGetSymbolAddress((void**)&pX0, d_x0);
    cudaGetSymbolAddress((void**)&pP,  d_P);
    cudaGetSymbolAddress((void**)&pDa, d_aAff);
    cudaGetSymbolAddress((void**)&pDb, d_bAff);

    const int SME1 = 18432 + 128 * (256 + 8) * 2;  // 86016 (C=256, 2 CTAs/SM)
    const int SME2 = 18432 + 128 * (128 + 8) * 2;  // 53248 (C=128, up to 4 CTAs/SM)
    cudaFuncSetAttribute(edge_mma_kernel<256>, cudaFuncAttributeMaxDynamicSharedMemorySize, SME1);
    cudaFuncSetAttribute(edge_mma_kernel<128>, cudaFuncAttributeMaxDynamicSharedMemorySize, SME2);

    // CSR build (indeg zeroed by fc_fused at end of previous replay)
    count_kernel<<<(EE + 255) / 256, 256>>>(ei);
    scan_kernel<<<1, 1024>>>();
    fill_kernel<<<(EE + 255) / 256, 256>>>(ei);

    // dual projection
    gemm_tile<512, 64, false><<<625, 256>>>(x, Wc, bc, nullptr, nullptr, pX0, 0, 1, NN);
    gemm_tile<512, 64, false><<<157, 256>>>(x, Wm, bm, nullptr, nullptr, pX0, 0, 4, 5000);

    // GCN stack (aggregate-then-GEMM; agg is linear)
    gcn_agg_pre<64><<<NN / 2, 128>>>(pX0, pH);
    gemm_tile<64, 128, false><<<1250, 256>>>(pH, Wg1, bg1, nullptr, nullptr, pA, 0, 1, NN);
    gcn_agg_pre<128><<<NN, 128>>>(pA, pH);
    gemm_tile<128, 128, false><<<1250, 256>>>(pH, Wg2, bg2, nullptr, nullptr, pB, 0, 1, NN);
    gcn_agg_pre<128><<<NN, 128>>>(pB, pH);
    gemm_tile<128, 256, false><<<2500, 256>>>(pH, Wg3, bg3, nullptr, nullptr, pA, 0, 1, NN);
    // g3 -> pA [N,256]

    // EdgeConv 1 (C=256): x = pA -> out pB
    bnaff_kernel<<<2, 256>>>(e1g, e1b, e1m, e1v, 512);
    gemm_tile<256, 128, true><<<1250, 256>>>(pA, e1W, nullptr, pDa, pDb, pP, 0, 1, NN);
    wsplit_kernel<<<(256 * 128 + 255) / 256, 256>>>(e1W + 256 * 128, 256);
    edge_mma_kernel<256><<<296, 256, SME1>>>(pA, pDa + 256, pDb + 256);
    edge_final_kernel<<<(NN * 128 + 255) / 256, 256>>>(pP, pB);

    // EdgeConv 2 (C=128): x = pB -> out pA
    bnaff_kernel<<<1, 256>>>(e2g, e2b, e2m, e2v, 256);
    gemm_tile<128, 128, true><<<1250, 256>>>(pB, e2W, nullptr, pDa, pDb, pP, 0, 1, NN);
    wsplit_kernel<<<(128 * 128 + 255) / 256, 256>>>(e2W + 128 * 128, 128);
    edge_mma_kernel<128><<<592, 256, SME2>>>(pB, pDa + 128, pDb + 128);
    edge_final_kernel<<<(NN * 128 + 255) / 256, 256>>>(pP, pA);

    // EdgeConv 3 (C=128): x = pA -> fused finalize+FC (+state reset for replay)
    bnaff_kernel<<<1, 256>>>(e3g, e3b, e3m, e3v, 256);
    gemm_tile<128, 128, true><<<1250, 256>>>(pA, e3W, nullptr, pDa, pDb, pP, 0, 1, NN);
    wsplit_kernel<<<(128 * 128 + 255) / 256, 256>>>(e3W + 128 * 128, 128);
    edge_mma_kernel<128><<<592, 256, SME2>>>(pA, pDa + 128, pDb + 128);
    fc_fused_kernel<<<5000, 128>>>(pP, Wfc, bfc, out);
}

// round 10
// speedup vs baseline: 4.3266x; 1.2098x over previous
#include <cuda_runtime.h>
#include <cuda_bf16.h>
#include <cuda_fp16.h>
#include <cstdint>

#define NN 20000
#define EE 320000

// ---------------- scratch (device globals; no allocation) ----------------
__device__ float d_bufA[NN * 256];
__device__ float d_bufB[NN * 256];
__device__ float d_h[NN * 256];
__device__ float d_x0[NN * 64];
__device__ float d_P[NN * 128];
__device__ float d_aAff[512];
__device__ float d_bAff[512];
__device__ float d_dinv[NN];
__device__ int   d_indeg[NN];
__device__ int   d_rowptr[NN + 1];
__device__ int   d_cursor[NN];
__device__ int   d_csrsrc[EE];
__device__ int   d_csrdst[EE];
__device__ __half d_Whi[256 * 128];
__device__ __half d_Wlo[256 * 128];
__device__ unsigned d_tmpmax[NN * 128];

// ---------------- helpers ----------------
__device__ __forceinline__ uint32_t smem_u32(const void* p) {
    uint32_t a;
    asm("{ .reg .u64 t; cvta.to.shared.u64 t, %1; cvt.u32.u64 %0, t; }" : "=r"(a) : "l"(p));
    return a;
}
__device__ __forceinline__ void ldsm4(uint32_t* r, uint32_t addr) {
    asm volatile("ldmatrix.sync.aligned.m8n8.x4.shared.b16 {%0,%1,%2,%3}, [%4];"
                 : "=r"(r[0]), "=r"(r[1]), "=r"(r[2]), "=r"(r[3]) : "r"(addr));
}
__device__ __forceinline__ void mma16816f(float* d, const uint32_t* a, const uint32_t* b) {
    asm volatile("mma.sync.aligned.m16n8k16.row.col.f32.f16.f16.f32 "
                 "{%0,%1,%2,%3}, {%4,%5,%6,%7}, {%8,%9}, {%0,%1,%2,%3};"
                 : "+f"(d[0]), "+f"(d[1]), "+f"(d[2]), "+f"(d[3])
                 : "r"(a[0]), "r"(a[1]), "r"(a[2]), "r"(a[3]), "r"(b[0]), "r"(b[1]));
}
__device__ __forceinline__ unsigned encf(float x) {
    unsigned s = __float_as_uint(x);
    return (s & 0x80000000u) ? ~s : (s | 0x80000000u);
}
__device__ __forceinline__ float decf(unsigned u) {
    return (u & 0x80000000u) ? __uint_as_float(u ^ 0x80000000u) : __uint_as_float(~u);
}
__device__ __forceinline__ uint32_t ph2(float a, float b) {
    __half2 h = __floats2half2_rn(a, b);
    return *(uint32_t*)&h;
}

// ---------------- CSR build ----------------
__global__ void count_kernel(const int* __restrict__ ei) {
    int i = blockIdx.x * blockDim.x + threadIdx.x;
    if (i < EE) atomicAdd(&d_indeg[ei[EE + i]], 1);
}
__global__ void scan_kernel() {
    __shared__ int sh[1024];
    __shared__ int carry;
    int tid = threadIdx.x;
    if (tid == 0) carry = 0;
    __syncthreads();
    for (int base = 0; base < NN; base += 1024) {
        int i = base + tid;
        int v = (i < NN) ? d_indeg[i] : 0;
        sh[tid] = v;
        __syncthreads();
        for (int off = 1; off < 1024; off <<= 1) {
            int t = (tid >= off) ? sh[tid - off] : 0;
            __syncthreads();
            sh[tid] += t;
            __syncthreads();
        }
        int incl = sh[tid];
        int base_c = carry;
        if (i < NN) {
            int excl = base_c + incl - v;
            d_rowptr[i] = excl;
            d_cursor[i] = excl;
            d_dinv[i] = rsqrtf((float)(v + 1));
        }
        __syncthreads();
        if (tid == 1023) carry = base_c + sh[1023];
        __syncthreads();
    }
    if (tid == 0) d_rowptr[NN] = carry;
}
__global__ void fill_kernel(const int* __restrict__ ei) {
    int i = blockIdx.x * blockDim.x + threadIdx.x;
    if (i < EE) {
        int s = ei[i];
        int d = ei[EE + i];
        int pos = atomicAdd(&d_cursor[d], 1);
        d_csrsrc[pos] = s;
        d_csrdst[pos] = d;
    }
}

// ---------------- GCN aggregation on PRE-GEMM features (agg is linear) ----------------
template <int C>
__global__ void gcn_agg_pre(const float* __restrict__ x, float* __restrict__ out) {
    constexpr int NPB = 128 / C;
    int local = threadIdx.x / C;
    int node = blockIdx.x * NPB + local;
    int c = threadIdx.x - local * C;
    if (node >= NN) return;
    float dd = d_dinv[node];
    float self = x[(size_t)node * C + c] * dd * dd;
    int e0 = d_rowptr[node], e1 = d_rowptr[node + 1];
    float a0 = 0.f, a1 = 0.f, a2 = 0.f, a3 = 0.f;
    int e = e0;
    for (; e + 4 <= e1; e += 4) {
        int s0 = d_csrsrc[e], s1 = d_csrsrc[e + 1], s2 = d_csrsrc[e + 2], s3 = d_csrsrc[e + 3];
        float w0 = d_dinv[s0], w1 = d_dinv[s1], w2 = d_dinv[s2], w3 = d_dinv[s3];
        float h0 = x[(size_t)s0 * C + c];
        float h1 = x[(size_t)s1 * C + c];
        float h2 = x[(size_t)s2 * C + c];
        float h3 = x[(size_t)s3 * C + c];
        a0 = fmaf(h0, w0, a0);
        a1 = fmaf(h1, w1, a1);
        a2 = fmaf(h2, w2, a2);
        a3 = fmaf(h3, w3, a3);
    }
    for (; e < e1; e++) {
        int s = d_csrsrc[e];
        a0 = fmaf(x[(size_t)s * C + c], d_dinv[s], a0);
    }
    out[(size_t)node * C + c] = fmaf((a0 + a1) + (a2 + a3), dd, self);
}

// ---------------- BN affine precompute ----------------
__global__ void bnaff_kernel(const float* __restrict__ g, const float* __restrict__ be,
                             const float* __restrict__ mn, const float* __restrict__ vr, int n) {
    int i = blockIdx.x * blockDim.x + threadIdx.x;
    if (i < n) {
        float a = g[i] * rsqrtf(vr[i] + 1e-5f);
        d_aAff[i] = a;
        d_bAff[i] = fmaf(-mn[i], a, be[i]);
    }
}

// ---------------- W split/transpose for gemm_mma: Wt[n][k] hi/lo ----------------
// W element (k, colOff+n) at W[k*ldW + colOff + n]; output index id = n*K + k.
__global__ void wsplit2_kernel(const float* __restrict__ W, int K, int ldW,
                               int Ncols, int colOff) {
    int id = blockIdx.x * blockDim.x + threadIdx.x;
    if (id < Ncols * K) {
        int n = id / K, k = id - n * K;
        float w = W[(size_t)k * ldW + colOff + n];
        __half hi = __float2half_rn(w);
        d_Whi[id] = hi;
        d_Wlo[id] = __float2half_rn(w - __half2float(hi));
    }
}

// ---------------- W transpose to fp16 (edge, hi only): Wt[n][k] ----------------
__global__ void wsplit_kernel(const float* __restrict__ W, int C) {
    int id = blockIdx.x * blockDim.x + threadIdx.x;
    if (id < C * 128) {
        int k = id >> 7, n = id & 127;
        d_Whi[n * C + k] = __float2half_rn(W[id]);
    }
}

// ---------------- dense GEMM via fp16 2-term mma: out = act(A)@W + bias ----------------
// Tile = 128 rows x N cols. A fp16-staged (optional affine+ReLU); W from d_Whi/d_Wlo.
template <int K, int N, bool PRE>
__global__ __launch_bounds__(256, 2) void gemm_mma(const float* __restrict__ A,
                                                   const float* __restrict__ bias,
                                                   const float* __restrict__ aAff,
                                                   const float* __restrict__ bAff,
                                                   float* __restrict__ out,
                                                   int rowStart, int rowStride, int numRows,
                                                   int outStride, int colOff) {
    constexpr int NCH = K / 64;
    constexpr int ASTR = 72;
    constexpr int ABYTES = 128 * ASTR * 2;   // 18432
    constexpr int BSTR = 72;
    constexpr int BBYTES = N * BSTR * 2;
    constexpr int BOFF = ABYTES;
    static_assert(K % 64 == 0, "");
    extern __shared__ char smem[];
    uint32_t sb = smem_u32(smem);
    const int tid = threadIdx.x, lane = tid & 31, w = tid >> 5;
    const int tileBase = blockIdx.x * 128;

    float acc[N / 8][4];
#pragma unroll
    for (int i = 0; i < N / 8; i++) { acc[i][0] = acc[i][1] = acc[i][2] = acc[i][3] = 0.f; }

    const int arow = tid >> 1, ahalf = tid & 1;
    const int rrA = tileBase + arow;
    const bool rowOK = rrA < numRows;
    const float* Arow = A + (size_t)(rowStart + (rowOK ? rrA : 0) * rowStride) * K;

    for (int ch = 0; ch < NCH; ch++) {
        __syncthreads();
        // stage A chunk (fp16, optional affine+ReLU)
        {
            int kb = ch * 64 + ahalf * 32;
            const float4* xs = (const float4*)(Arow + kb);
            const float4* aa = (const float4*)(aAff + kb);
            const float4* bb = (const float4*)(bAff + kb);
#pragma unroll
            for (int q = 0; q < 4; q++) {
                uint4 H;
                if (rowOK) {
                    float4 s0 = xs[q * 2], s1 = xs[q * 2 + 1];
                    float v0 = s0.x, v1 = s0.y, v2 = s0.z, v3 = s0.w;
                    float v4 = s1.x, v5 = s1.y, v6 = s1.z, v7 = s1.w;
                    if (PRE) {
                        float4 A0 = __ldg(aa + q * 2), A1 = __ldg(aa + q * 2 + 1);
                        float4 B0 = __ldg(bb + q * 2), B1 = __ldg(bb + q * 2 + 1);
                        v0 = fmaxf(fmaf(A0.x, v0, B0.x), 0.f);
                        v1 = fmaxf(fmaf(A0.y, v1, B0.y), 0.f);
                        v2 = fmaxf(fmaf(A0.z, v2, B0.z), 0.f);
                        v3 = fmaxf(fmaf(A0.w, v3, B0.w), 0.f);
                        v4 = fmaxf(fmaf(A1.x, v4, B1.x), 0.f);
                        v5 = fmaxf(fmaf(A1.y, v5, B1.y), 0.f);
                        v6 = fmaxf(fmaf(A1.z, v6, B1.z), 0.f);
                        v7 = fmaxf(fmaf(A1.w, v7, B1.w), 0.f);
                    }
                    H.x = ph2(v0, v1);
                    H.y = ph2(v2, v3);
                    H.z = ph2(v4, v5);
                    H.w = ph2(v6, v7);
                } else {
                    H = make_uint4(0, 0, 0, 0);
                }
                uint32_t off = (uint32_t)(arow * ASTR + ahalf * 32 + q * 8) * 2;
                *(uint4*)(smem + off) = H;
            }
        }
        // stage B chunk hi/lo
        for (int idx = tid; idx < N * 8; idx += 256) {
            int n = idx >> 3, kq = idx & 7;
            int src = n * (K / 8) + ch * 8 + kq;
            uint32_t off = BOFF + (uint32_t)(n * BSTR + kq * 8) * 2;
            *(uint4*)(smem + off) = ((const uint4*)d_Whi)[src];
            *(uint4*)(smem + off + BBYTES) = ((const uint4*)d_Wlo)[src];
        }
        __syncthreads();
        // MMA
        const uint32_t within = lane & 15;
        const uint32_t brow = within & 7, bsel = within >> 3;
        const uint32_t ntoff = lane >> 4;
#pragma unroll
        for (int ks = 0; ks < 4; ks++) {
            uint32_t ah[4];
            uint32_t aaddr = sb +
                (uint32_t)((w * 16 + (lane & 15)) * ASTR + ks * 16 + (lane >> 4) * 8) * 2;
            ldsm4(ah, aaddr);
#pragma unroll
            for (int np = 0; np < N / 16; np++) {
                uint32_t baddr = sb + BOFF +
                    (uint32_t)((np * 16 + ntoff * 8 + brow) * BSTR + ks * 16 + bsel * 8) * 2;
                uint32_t bh[4], bl[4];
                ldsm4(bh, baddr);
                ldsm4(bl, baddr + BBYTES);
                mma16816f(acc[np * 2], ah, bh);
                mma16816f(acc[np * 2], ah, bl);
                mma16816f(acc[np * 2 + 1], ah, bh + 2);
                mma16816f(acc[np * 2 + 1], ah, bl + 2);
            }
        }
    }
    // epilogue: direct register -> gmem
#pragma unroll
    for (int nt = 0; nt < N / 8; nt++) {
        int col = colOff + nt * 8 + (lane & 3) * 2;
        float b0 = bias ? bias[col] : 0.f;
        float b1 = bias ? bias[col + 1] : 0.f;
        int r0 = tileBase + w * 16 + (lane >> 2);
        if (r0 < numRows) {
            int grow = rowStart + r0 * rowStride;
            *(float2*)(out + (size_t)grow * outStride + col) =
                make_float2(acc[nt][0] + b0, acc[nt][1] + b1);
        }
        int r1 = r0 + 8;
        if (r1 < numRows) {
            int grow = rowStart + r1 * rowStride;
            *(float2*)(out + (size_t)grow * outStride + col) =
                make_float2(acc[nt][2] + b0, acc[nt][3] + b1);
        }
    }
}

// ---------------- EdgeConv via single-fp16 mma.sync ----------------
template <int C>
__global__ __launch_bounds__(256, 2) void edge_mma_kernel(const float* __restrict__ x,
                                                          const float* __restrict__ aAff,
                                                          const float* __restrict__ bAff) {
    constexpr int NCH = C / 64;
    constexpr int ASTRIDE = 72;
    constexpr int ABYTES = 128 * ASTRIDE * 2;   // 18432
    constexpr int BOFF = ABYTES;
    constexpr int BSTRIDE = C + 8;
    extern __shared__ char smem[];
    float* buf = (float*)smem;
    uint32_t sb = smem_u32(smem);
    const int tid = threadIdx.x, lane = tid & 31, w = tid >> 5;
    const unsigned fullm = 0xFFFFFFFFu;

    for (int idx = tid; idx < C * 128 / 8; idx += 256) {
        int n = idx / (C / 8), kb = (idx % (C / 8)) * 8;
        uint32_t off = BOFF + (uint32_t)(n * BSTRIDE + kb) * 2;
        *(uint4*)(smem + off) = ((const uint4*)d_Whi)[idx];
    }

    const int arow = tid >> 1, ahalf = tid & 1;

    for (int t = blockIdx.x; t < EE / 128; t += gridDim.x) {
        float acc[16][4];
#pragma unroll
        for (int i = 0; i < 16; i++) { acc[i][0] = acc[i][1] = acc[i][2] = acc[i][3] = 0.f; }

        const int sA = d_csrsrc[t * 128 + arow];
        const int dA = d_csrdst[t * 128 + arow];

        for (int ch = 0; ch < NCH; ch++) {
            __syncthreads();
            {
                int kb = ch * 64 + ahalf * 32;
                const float4* xs = (const float4*)(x + (size_t)sA * C + kb);
                const float4* xd = (const float4*)(x + (size_t)dA * C + kb);
                const float4* aa = (const float4*)(aAff + kb);
                const float4* bb = (const float4*)(bAff + kb);
#pragma unroll
                for (int q = 0; q < 4; q++) {
                    float4 s0 = xs[q * 2], s1 = xs[q * 2 + 1];
                    float4 d0 = xd[q * 2], d1 = xd[q * 2 + 1];
                    float4 A0 = __ldg(aa + q * 2), A1 = __ldg(aa + q * 2 + 1);
                    float4 B0 = __ldg(bb + q * 2), B1 = __ldg(bb + q * 2 + 1);
                    float v0 = fmaxf(fmaf(A0.x, s0.x - d0.x, B0.x), 0.f);
                    float v1 = fmaxf(fmaf(A0.y, s0.y - d0.y, B0.y), 0.f);
                    float v2 = fmaxf(fmaf(A0.z, s0.z - d0.z, B0.z), 0.f);
                    float v3 = fmaxf(fmaf(A0.w, s0.w - d0.w, B0.w), 0.f);
                    float v4 = fmaxf(fmaf(A1.x, s1.x - d1.x, B1.x), 0.f);
                    float v5 = fmaxf(fmaf(A1.y, s1.y - d1.y, B1.y), 0.f);
                    float v6 = fmaxf(fmaf(A1.z, s1.z - d1.z, B1.z), 0.f);
                    float v7 = fmaxf(fmaf(A1.w, s1.w - d1.w, B1.w), 0.f);
                    uint4 H;
                    H.x = ph2(v0, v1);
                    H.y = ph2(v2, v3);
                    H.z = ph2(v4, v5);
                    H.w = ph2(v6, v7);
                    uint32_t off = (uint32_t)(arow * ASTRIDE + ahalf * 32 + q * 8) * 2;
                    *(uint4*)(smem + off) = H;
                }
            }
            __syncthreads();
            const uint32_t within = lane & 15;
            const uint32_t brow = within & 7, bsel = within >> 3;
            const uint32_t ntoff = lane >> 4;
#pragma unroll
            for (int ks = 0; ks < 4; ks++) {
                uint32_t ah[4];
                uint32_t aaddr = sb +
                    (uint32_t)((w * 16 + (lane & 15)) * ASTRIDE + ks * 16 + (lane >> 4) * 8) * 2;
                ldsm4(ah, aaddr);
#pragma unroll
                for (int np = 0; np < 8; np++) {
                    uint32_t baddr = sb + BOFF +
                        (uint32_t)((np * 16 + ntoff * 8 + brow) * BSTRIDE + ch * 64 + ks * 16 + bsel * 8) * 2;
                    uint32_t bh[4];
                    ldsm4(bh, baddr);
                    mma16816f(acc[np * 2], ah, bh);
                    mma16816f(acc[np * 2 + 1], ah, bh + 2);
                }
            }
        }
        // ---- epilogue: segmented max over CSR runs ----
        int erow = t * 128 + (w & 3) * 32 + lane;
        int dl = d_csrdst[erow];
        int prev = __shfl_up_sync(fullm, dl, 1);
        bool head = (lane == 0) || (dl != prev);
        unsigned Hb = __ballot_sync(fullm, head);
        unsigned mle;
        asm("mov.u32 %0, %%lanemask_le;" : "=r"(mle));
        int run_start = 31 - __clz(Hb & mle);
        bool tail = (lane == 31) || ((Hb >> (lane + 1)) & 1);
        unsigned* trow = d_tmpmax + (size_t)dl * 128;
#pragma unroll
        for (int g = 0; g < 4; g++) {
            __syncthreads();
#pragma unroll
            for (int q = 0; q < 4; q++) {
                int nt = g * 4 + q;
                int lcol = q * 8 + (lane & 3) * 2;
                int r0 = w * 16 + (lane >> 2);
                buf[r0 * 33 + lcol]           = acc[nt][0];
                buf[r0 * 33 + lcol + 1]       = acc[nt][1];
                buf[(r0 + 8) * 33 + lcol]     = acc[nt][2];
                buf[(r0 + 8) * 33 + lcol + 1] = acc[nt][3];
            }
            __syncthreads();
            int rr = (w & 3) * 32 + lane;
            int cb = (w >> 2) * 16;
            float v[16];
#pragma unroll
            for (int j = 0; j < 16; j++) v[j] = buf[rr * 33 + cb + j];
#pragma unroll
            for (int dlt = 1; dlt < 32; dlt <<= 1) {
#pragma unroll
                for (int j = 0; j < 16; j++) {
                    float u = __shfl_up_sync(fullm, v[j], dlt);
                    if ((int)lane - dlt >= run_start) v[j] = fmaxf(v[j], u);
                }
            }
            if (tail) {
#pragma unroll
                for (int j = 0; j < 16; j++) atomicMax(trow + g * 32 + cb + j, encf(v[j]));
            }
        }
    }
}

// ---------------- finalize: out[d] = deg>0 ? P[d] + dec(tmp[d]) : 0 ; reset tmp ----------------
__global__ void edge_final_kernel(const float* __restrict__ P, float* __restrict__ out) {
    int i = blockIdx.x * blockDim.x + threadIdx.x;
    if (i < NN * 128) {
        int d = i >> 7;
        float r = 0.f;
        if (d_indeg[d] > 0) r = P[i] + decf(d_tmpmax[i]);
        out[i] = r;
        d_tmpmax[i] = 0;
    }
}

// ---------------- fused last-layer finalize + FC; resets indeg & tmpmax ----------------
__global__ void fc_fused_kernel(const float* __restrict__ P, const float* __restrict__ Wfc,
                                const float* __restrict__ bfc, float* __restrict__ out) {
    int w = threadIdx.x >> 5, lane = threadIdx.x & 31;
    int d = blockIdx.x * 4 + w;
    if (d >= NN) return;
    bool nz = d_indeg[d] > 0;
    float s = 0.f;
#pragma unroll
    for (int u = 0; u < 4; u++) {
        int k = lane + 32 * u;
        size_t idx = (size_t)d * 128 + k;
        float h = nz ? P[idx] + decf(d_tmpmax[idx]) : 0.f;
        d_tmpmax[idx] = 0;
        s = fmaf(h, Wfc[k], s);
    }
#pragma unroll
    for (int off = 16; off; off >>= 1) s += __shfl_down_sync(0xffffffffu, s, off);
    if (lane == 0) {
        out[d] = s + bfc[0];
        d_indeg[d] = 0;
    }
}

// ---------------- host ----------------
extern "C" void kernel_launch(void* const* d_in, const int* in_sizes, int n_in,
                              void* d_out, int out_size) {
    const float* x   = (const float*)d_in[0];
    const int*   ei  = (const int*)d_in[1];
    const float* Wm  = (const float*)d_in[2];
    const float* bm  = (const float*)d_in[3];
    const float* Wc  = (const float*)d_in[4];
    const float* bc  = (const float*)d_in[5];
    const float* Wg1 = (const float*)d_in[6];
    const float* bg1 = (const float*)d_in[7];
    const float* Wg2 = (const float*)d_in[8];
    const float* bg2 = (const float*)d_in[9];
    const float* Wg3 = (const float*)d_in[10];
    const float* bg3 = (const float*)d_in[11];
    const float* e1g = (const float*)d_in[12];
    const float* e1b = (const float*)d_in[13];
    const float* e1m = (const float*)d_in[14];
    const float* e1v = (const float*)d_in[15];
    const float* e1W = (const float*)d_in[16];
    const float* e2g = (const float*)d_in[17];
    const float* e2b = (const float*)d_in[18];
    const float* e2m = (const float*)d_in[19];
    const float* e2v = (const float*)d_in[20];
    const float* e2W = (const float*)d_in[21];
    const float* e3g = (const float*)d_in[22];
    const float* e3b = (const float*)d_in[23];
    const float* e3m = (const float*)d_in[24];
    const float* e3v = (const float*)d_in[25];
    const float* e3W = (const float*)d_in[26];
    const float* Wfc = (const float*)d_in[27];
    const float* bfc = (const float*)d_in[28];
    float* out = (float*)d_out;

    float *pA, *pB, *pH, *pX0, *pP, *pDa, *pDb;
    cudaGetSymbolAddress((void**)&pA,  d_bufA);
    cudaGetSymbolAddress((void**)&pB,  d_bufB);
    cudaGetSymbolAddress((void**)&pH,  d_h);
    cudaGetSymbolAddress((void**)&pX0, d_x0);
    cudaGetSymbolAddress((void**)&pP,  d_P);
    cudaGetSymbolAddress((void**)&pDa, d_aAff);
    cudaGetSymbolAddress((void**)&pDb, d_bAff);

    const int SME1 = 18432 + 128 * (256 + 8) * 2;  // 86016 (edge C=256)
    const int SME2 = 18432 + 128 * (128 + 8) * 2;  // 53248 (edge C=128)
    cudaFuncSetAttribute(edge_mma_kernel<256>, cudaFuncAttributeMaxDynamicSharedMemorySize, SME1);
    cudaFuncSetAttribute(edge_mma_kernel<128>, cudaFuncAttributeMaxDynamicSharedMemorySize, SME2);

    const int SMG64  = 18432 + 2 * 64 * 72 * 2;    // 36864 (gemm N=64)
    const int SMG128 = 18432 + 2 * 128 * 72 * 2;   // 55296 (gemm N=128)
    cudaFuncSetAttribute(gemm_mma<512, 64, false>, cudaFuncAttributeMaxDynamicSharedMemorySize, SMG64);
    cudaFuncSetAttribute(gemm_mma<64, 128, false>, cudaFuncAttributeMaxDynamicSharedMemorySize, SMG128);
    cudaFuncSetAttribute(gemm_mma<128, 128, false>, cudaFuncAttributeMaxDynamicSharedMemorySize, SMG128);
    cudaFuncSetAttribute(gemm_mma<128, 128, true>, cudaFuncAttributeMaxDynamicSharedMemorySize, SMG128);
    cudaFuncSetAttribute(gemm_mma<256, 128, true>, cudaFuncAttributeMaxDynamicSharedMemorySize, SMG128);

    const int TILES = (NN + 127) / 128;  // 157

    // CSR build (indeg zeroed by fc_fused at end of previous replay)
    count_kernel<<<(EE + 255) / 256, 256>>>(ei);
    scan_kernel<<<1, 1024>>>();
    fill_kernel<<<(EE + 255) / 256, 256>>>(ei);

    // dual projection
    wsplit2_kernel<<<(512 * 64 + 255) / 256, 256>>>(Wc, 512, 64, 64, 0);
    gemm_mma<512, 64, false><<<TILES, 256, SMG64>>>(x, bc, nullptr, nullptr, pX0, 0, 1, NN, 64, 0);
    wsplit2_kernel<<<(512 * 64 + 255) / 256, 256>>>(Wm, 512, 64, 64, 0);
    gemm_mma<512, 64, false><<<40, 256, SMG64>>>(x, bm, nullptr, nullptr, pX0, 0, 4, 5000, 64, 0);

    // GCN stack (aggregate-then-GEMM; agg is linear)
    gcn_agg_pre<64><<<NN / 2, 128>>>(pX0, pH);
    wsplit2_kernel<<<(64 * 128 + 255) / 256, 256>>>(Wg1, 64, 128, 128, 0);
    gemm_mma<64, 128, false><<<TILES, 256, SMG128>>>(pH, bg1, nullptr, nullptr, pA, 0, 1, NN, 128, 0);
    gcn_agg_pre<128><<<NN, 128>>>(pA, pH);
    wsplit2_kernel<<<(128 * 128 + 255) / 256, 256>>>(Wg2, 128, 128, 128, 0);
    gemm_mma<128, 128, false><<<TILES, 256, SMG128>>>(pH, bg2, nullptr, nullptr, pB, 0, 1, NN, 128, 0);
    gcn_agg_pre<128><<<NN, 128>>>(pB, pH);
    wsplit2_kernel<<<(128 * 128 + 255) / 256, 256>>>(Wg3, 128, 256, 128, 0);
    gemm_mma<128, 128, false><<<TILES, 256, SMG128>>>(pH, bg3, nullptr, nullptr, pA, 0, 1, NN, 256, 0);
    wsplit2_kernel<<<(128 * 128 + 255) / 256, 256>>>(Wg3, 128, 256, 128, 128);
    gemm_mma<128, 128, false><<<TILES, 256, SMG128>>>(pH, bg3, nullptr, nullptr, pA, 0, 1, NN, 256, 128);
    // g3 -> pA [N,256]

    // EdgeConv 1 (C=256): x = pA -> out pB
    bnaff_kernel<<<2, 256>>>(e1g, e1b, e1m, e1v, 512);
    wsplit2_kernel<<<(256 * 128 + 255) / 256, 256>>>(e1W, 256, 128, 128, 0);
    gemm_mma<256, 128, true><<<TILES, 256, SMG128>>>(pA, nullptr, pDa, pDb, pP, 0, 1, NN, 128, 0);
    wsplit_kernel<<<(256 * 128 + 255) / 256, 256>>>(e1W + 256 * 128, 256);
    edge_mma_kernel<256><<<296, 256, SME1>>>(pA, pDa + 256, pDb + 256);
    edge_final_kernel<<<(NN * 128 + 255) / 256, 256>>>(pP, pB);

    // EdgeConv 2 (C=128): x = pB -> out pA
    bnaff_kernel<<<1, 256>>>(e2g, e2b, e2m, e2v, 256);
    wsplit2_kernel<<<(128 * 128 + 255) / 256, 256>>>(e2W, 128, 128, 128, 0);
    gemm_mma<128, 128, true><<<TILES, 256, SMG128>>>(pB, nullptr, pDa, pDb, pP, 0, 1, NN, 128, 0);
    wsplit_kernel<<<(128 * 128 + 255) / 256, 256>>>(e2W + 128 * 128, 128);
    edge_mma_kernel<128><<<592, 256, SME2>>>(pB, pDa + 128, pDb + 128);
    edge_final_kernel<<<(NN * 128 + 255) / 256, 256>>>(pP, pA);

    // EdgeConv 3 (C=128): x = pA -> fused finalize+FC (+state reset for replay)
    bnaff_kernel<<<1, 256>>>(e3g, e3b, e3m, e3v, 256);
    wsplit2_kernel<<<(128 * 128 + 255) / 256, 256>>>(e3W, 128, 128, 128, 0);
    gemm_mma<128, 128, true><<<TILES, 256, SMG128>>>(pA, nullptr, pDa, pDb, pP, 0, 1, NN, 128, 0);
    wsplit_kernel<<<(128 * 128 + 255) / 256, 256>>>(e3W + 128 * 128, 128);
    edge_mma_kernel<128><<<592, 256, SME2>>>(pA, pDa + 128, pDb + 128);
    fc_fused_kernel<<<5000, 128>>>(pP, Wfc, bfc, out);
}

// round 11
// speedup vs baseline: 5.8016x; 1.3409x over previous
#include <cuda_runtime.h>
#include <cuda_bf16.h>
#include <cuda_fp16.h>
#include <cstdint>

#define NN 20000
#define EE 320000

// ---------------- scratch (device globals; no allocation) ----------------
__device__ float d_bufA[NN * 256];
__device__ float d_bufB[NN * 256];
__device__ float d_h[NN * 256];
__device__ float d_x0[NN * 64];
__device__ float d_P[NN * 128];
__device__ __half d_yh[NN * 256];
__device__ float d_aAff[512];
__device__ float d_bAff[512];
__device__ __half d_ratioH[256];
__device__ __half d_btopH[256];
__device__ __half d_bbotH[256];
__device__ float d_dinv[NN];
__device__ int   d_indeg[NN];
__device__ int   d_rowptr[NN + 1];
__device__ int   d_cursor[NN];
__device__ int   d_csrsrc[EE];
__device__ int   d_csrdst[EE];
__device__ __half d_Whi[256 * 128];
__device__ __half d_Wlo[256 * 128];
__device__ unsigned d_tmpmax[NN * 128];

// ---------------- helpers ----------------
__device__ __forceinline__ uint32_t smem_u32(const void* p) {
    uint32_t a;
    asm("{ .reg .u64 t; cvta.to.shared.u64 t, %1; cvt.u32.u64 %0, t; }" : "=r"(a) : "l"(p));
    return a;
}
__device__ __forceinline__ void ldsm4(uint32_t* r, uint32_t addr) {
    asm volatile("ldmatrix.sync.aligned.m8n8.x4.shared.b16 {%0,%1,%2,%3}, [%4];"
                 : "=r"(r[0]), "=r"(r[1]), "=r"(r[2]), "=r"(r[3]) : "r"(addr));
}
__device__ __forceinline__ void mma16816f(float* d, const uint32_t* a, const uint32_t* b) {
    asm volatile("mma.sync.aligned.m16n8k16.row.col.f32.f16.f16.f32 "
                 "{%0,%1,%2,%3}, {%4,%5,%6,%7}, {%8,%9}, {%0,%1,%2,%3};"
                 : "+f"(d[0]), "+f"(d[1]), "+f"(d[2]), "+f"(d[3])
                 : "r"(a[0]), "r"(a[1]), "r"(a[2]), "r"(a[3]), "r"(b[0]), "r"(b[1]));
}
__device__ __forceinline__ unsigned encf(float x) {
    unsigned s = __float_as_uint(x);
    return (s & 0x80000000u) ? ~s : (s | 0x80000000u);
}
__device__ __forceinline__ float decf(unsigned u) {
    return (u & 0x80000000u) ? __uint_as_float(u ^ 0x80000000u) : __uint_as_float(~u);
}
__device__ __forceinline__ uint32_t ph2(float a, float b) {
    __half2 h = __floats2half2_rn(a, b);
    return *(uint32_t*)&h;
}
// feature op: max(s - d + b, 0) on half2 lanes
__device__ __forceinline__ uint32_t hsubaddmax(uint32_t s, uint32_t d, uint32_t b) {
    __half2 r = __hmax2(__hadd2(__hsub2(*(__half2*)&s, *(__half2*)&d), *(__half2*)&b),
                        __float2half2_rn(0.f));
    return *(uint32_t*)&r;
}
// P op: max(ratio*y + btop, 0) on half2 lanes
__device__ __forceinline__ uint32_t hfmamax(uint32_t a, uint32_t y, uint32_t b) {
    __half2 r = __hmax2(__hfma2(*(__half2*)&a, *(__half2*)&y, *(__half2*)&b),
                        __float2half2_rn(0.f));
    return *(uint32_t*)&r;
}

// ---------------- CSR build ----------------
__global__ void count_kernel(const int* __restrict__ ei) {
    int i = blockIdx.x * blockDim.x + threadIdx.x;
    if (i < EE) atomicAdd(&d_indeg[ei[EE + i]], 1);
}
__global__ void scan_kernel() {
    __shared__ int sh[1024];
    __shared__ int carry;
    int tid = threadIdx.x;
    if (tid == 0) carry = 0;
    __syncthreads();
    for (int base = 0; base < NN; base += 1024) {
        int i = base + tid;
        int v = (i < NN) ? d_indeg[i] : 0;
        sh[tid] = v;
        __syncthreads();
        for (int off = 1; off < 1024; off <<= 1) {
            int t = (tid >= off) ? sh[tid - off] : 0;
            __syncthreads();
            sh[tid] += t;
            __syncthreads();
        }
        int incl = sh[tid];
        int base_c = carry;
        if (i < NN) {
            int excl = base_c + incl - v;
            d_rowptr[i] = excl;
            d_cursor[i] = excl;
            d_dinv[i] = rsqrtf((float)(v + 1));
        }
        __syncthreads();
        if (tid == 1023) carry = base_c + sh[1023];
        __syncthreads();
    }
    if (tid == 0) d_rowptr[NN] = carry;
}
__global__ void fill_kernel(const int* __restrict__ ei) {
    int i = blockIdx.x * blockDim.x + threadIdx.x;
    if (i < EE) {
        int s = ei[i];
        int d = ei[EE + i];
        int pos = atomicAdd(&d_cursor[d], 1);
        d_csrsrc[pos] = s;
        d_csrdst[pos] = d;
    }
}

// ---------------- GCN aggregation on PRE-GEMM features (agg is linear) ----------------
template <int C>
__global__ void gcn_agg_pre(const float* __restrict__ x, float* __restrict__ out) {
    constexpr int NPB = 128 / C;
    int local = threadIdx.x / C;
    int node = blockIdx.x * NPB + local;
    int c = threadIdx.x - local * C;
    if (node >= NN) return;
    float dd = d_dinv[node];
    float self = x[(size_t)node * C + c] * dd * dd;
    int e0 = d_rowptr[node], e1 = d_rowptr[node + 1];
    float a0 = 0.f, a1 = 0.f, a2 = 0.f, a3 = 0.f;
    int e = e0;
    for (; e + 4 <= e1; e += 4) {
        int s0 = d_csrsrc[e], s1 = d_csrsrc[e + 1], s2 = d_csrsrc[e + 2], s3 = d_csrsrc[e + 3];
        float w0 = d_dinv[s0], w1 = d_dinv[s1], w2 = d_dinv[s2], w3 = d_dinv[s3];
        float h0 = x[(size_t)s0 * C + c];
        float h1 = x[(size_t)s1 * C + c];
        float h2 = x[(size_t)s2 * C + c];
        float h3 = x[(size_t)s3 * C + c];
        a0 = fmaf(h0, w0, a0);
        a1 = fmaf(h1, w1, a1);
        a2 = fmaf(h2, w2, a2);
        a3 = fmaf(h3, w3, a3);
    }
    for (; e < e1; e++) {
        int s = d_csrsrc[e];
        a0 = fmaf(x[(size_t)s * C + c], d_dinv[s], a0);
    }
    out[(size_t)node * C + c] = fmaf((a0 + a1) + (a2 + a3), dd, self);
}

// ---------------- BN affine precompute ----------------
__global__ void bnaff_kernel(const float* __restrict__ g, const float* __restrict__ be,
                             const float* __restrict__ mn, const float* __restrict__ vr, int n) {
    int i = blockIdx.x * blockDim.x + threadIdx.x;
    if (i < n) {
        float a = g[i] * rsqrtf(vr[i] + 1e-5f);
        d_aAff[i] = a;
        d_bAff[i] = fmaf(-mn[i], a, be[i]);
    }
}
// half derived vectors: ratio = a_top/a_bot, btop, bbot (C channels)
__global__ void bnaffh_kernel(int C) {
    int i = blockIdx.x * blockDim.x + threadIdx.x;
    if (i < C) {
        d_ratioH[i] = __float2half_rn(d_aAff[i] / d_aAff[C + i]);
        d_btopH[i] = __float2half_rn(d_bAff[i]);
        d_bbotH[i] = __float2half_rn(d_bAff[C + i]);
    }
}

// ---------------- W split/transpose for gemm: Wt[n][k] hi/lo ----------------
__global__ void wsplit2_kernel(const float* __restrict__ W, int K, int ldW,
                               int Ncols, int colOff) {
    int id = blockIdx.x * blockDim.x + threadIdx.x;
    if (id < Ncols * K) {
        int n = id / K, k = id - n * K;
        float w = W[(size_t)k * ldW + colOff + n];
        __half hi = __float2half_rn(w);
        d_Whi[id] = hi;
        d_Wlo[id] = __float2half_rn(w - __half2float(hi));
    }
}
// edge-B transpose (hi only)
__global__ void wsplit_kernel(const float* __restrict__ W, int C) {
    int id = blockIdx.x * blockDim.x + threadIdx.x;
    if (id < C * 128) {
        int k = id >> 7, n = id & 127;
        d_Whi[n * C + k] = __float2half_rn(W[id]);
    }
}

// ---------------- dense GEMM (fp32 A) via fp16 2-term mma ----------------
// OUTH: write half(aOut[col] * (acc+bias)) to (__half*)out instead of fp32.
template <int K, int N, bool OUTH>
__global__ __launch_bounds__(256, 2) void gemm_mma(const float* __restrict__ A,
                                                   const float* __restrict__ bias,
                                                   const float* __restrict__ aOut,
                                                   void* __restrict__ outv,
                                                   int rowStart, int rowStride, int numRows,
                                                   int outStride, int colOff) {
    constexpr int NCH = K / 64;
    constexpr int ASTR = 72;
    constexpr int ABYTES = 128 * ASTR * 2;
    constexpr int BSTR = 72;
    constexpr int BBYTES = N * BSTR * 2;
    constexpr int BOFF = ABYTES;
    extern __shared__ char smem[];
    uint32_t sb = smem_u32(smem);
    const int tid = threadIdx.x, lane = tid & 31, w = tid >> 5;
    const int tileBase = blockIdx.x * 128;

    float acc[N / 8][4];
#pragma unroll
    for (int i = 0; i < N / 8; i++) { acc[i][0] = acc[i][1] = acc[i][2] = acc[i][3] = 0.f; }

    const int arow = tid >> 1, ahalf = tid & 1;
    const int rrA = tileBase + arow;
    const bool rowOK = rrA < numRows;
    const float* Arow = A + (size_t)(rowStart + (rowOK ? rrA : 0) * rowStride) * K;

    for (int ch = 0; ch < NCH; ch++) {
        __syncthreads();
        {
            int kb = ch * 64 + ahalf * 32;
            const float4* xs = (const float4*)(Arow + kb);
#pragma unroll
            for (int q = 0; q < 4; q++) {
                uint4 H;
                if (rowOK) {
                    float4 s0 = xs[q * 2], s1 = xs[q * 2 + 1];
                    H.x = ph2(s0.x, s0.y);
                    H.y = ph2(s0.z, s0.w);
                    H.z = ph2(s1.x, s1.y);
                    H.w = ph2(s1.z, s1.w);
                } else {
                    H = make_uint4(0, 0, 0, 0);
                }
                uint32_t off = (uint32_t)(arow * ASTR + ahalf * 32 + q * 8) * 2;
                *(uint4*)(smem + off) = H;
            }
        }
        for (int idx = tid; idx < N * 8; idx += 256) {
            int n = idx >> 3, kq = idx & 7;
            int src = n * (K / 8) + ch * 8 + kq;
            uint32_t off = BOFF + (uint32_t)(n * BSTR + kq * 8) * 2;
            *(uint4*)(smem + off) = ((const uint4*)d_Whi)[src];
            *(uint4*)(smem + off + BBYTES) = ((const uint4*)d_Wlo)[src];
        }
        __syncthreads();
        const uint32_t within = lane & 15;
        const uint32_t brow = within & 7, bsel = within >> 3;
        const uint32_t ntoff = lane >> 4;
#pragma unroll
        for (int ks = 0; ks < 4; ks++) {
            uint32_t ah[4];
            uint32_t aaddr = sb +
                (uint32_t)((w * 16 + (lane & 15)) * ASTR + ks * 16 + (lane >> 4) * 8) * 2;
            ldsm4(ah, aaddr);
#pragma unroll
            for (int np = 0; np < N / 16; np++) {
                uint32_t baddr = sb + BOFF +
                    (uint32_t)((np * 16 + ntoff * 8 + brow) * BSTR + ks * 16 + bsel * 8) * 2;
                uint32_t bh[4], bl[4];
                ldsm4(bh, baddr);
                ldsm4(bl, baddr + BBYTES);
                mma16816f(acc[np * 2], ah, bh);
                mma16816f(acc[np * 2], ah, bl);
                mma16816f(acc[np * 2 + 1], ah, bh + 2);
                mma16816f(acc[np * 2 + 1], ah, bl + 2);
            }
        }
    }
#pragma unroll
    for (int nt = 0; nt < N / 8; nt++) {
        int col = colOff + nt * 8 + (lane & 3) * 2;
        float b0 = bias ? bias[col] : 0.f;
        float b1 = bias ? bias[col + 1] : 0.f;
        float a0 = OUTH ? aOut[col] : 1.f;
        float a1 = OUTH ? aOut[col + 1] : 1.f;
        int r0 = tileBase + w * 16 + (lane >> 2);
        int r1 = r0 + 8;
        if (OUTH) {
            __half* oh = (__half*)outv;
            if (r0 < numRows) {
                int grow = rowStart + r0 * rowStride;
                *(__half2*)(oh + (size_t)grow * outStride + col) =
                    __floats2half2_rn(a0 * (acc[nt][0] + b0), a1 * (acc[nt][1] + b1));
            }
            if (r1 < numRows) {
                int grow = rowStart + r1 * rowStride;
                *(__half2*)(oh + (size_t)grow * outStride + col) =
                    __floats2half2_rn(a0 * (acc[nt][2] + b0), a1 * (acc[nt][3] + b1));
            }
        } else {
            float* of = (float*)outv;
            if (r0 < numRows) {
                int grow = rowStart + r0 * rowStride;
                *(float2*)(of + (size_t)grow * outStride + col) =
                    make_float2(acc[nt][0] + b0, acc[nt][1] + b1);
            }
            if (r1 < numRows) {
                int grow = rowStart + r1 * rowStride;
                *(float2*)(of + (size_t)grow * outStride + col) =
                    make_float2(acc[nt][2] + b0, acc[nt][3] + b1);
            }
        }
    }
}

// ---------------- P-GEMM (half A = y): out = ReLU(ratio*y + btop) @ W ----------------
template <int K, int N>
__global__ __launch_bounds__(256, 2) void gemm_mma_h(const __half* __restrict__ Y,
                                                     float* __restrict__ out) {
    constexpr int NCH = K / 64;
    constexpr int ASTR = 72;
    constexpr int ABYTES = 128 * ASTR * 2;
    constexpr int BSTR = 72;
    constexpr int BBYTES = N * BSTR * 2;
    constexpr int BOFF = ABYTES;
    extern __shared__ char smem[];
    uint32_t sb = smem_u32(smem);
    const int tid = threadIdx.x, lane = tid & 31, w = tid >> 5;
    const int tileBase = blockIdx.x * 128;

    float acc[N / 8][4];
#pragma unroll
    for (int i = 0; i < N / 8; i++) { acc[i][0] = acc[i][1] = acc[i][2] = acc[i][3] = 0.f; }

    const int arow = tid >> 1, ahalf = tid & 1;
    const int rrA = tileBase + arow;
    const bool rowOK = rrA < NN;
    const __half* Yrow = Y + (size_t)(rowOK ? rrA : 0) * K;

    for (int ch = 0; ch < NCH; ch++) {
        __syncthreads();
        {
            int kb = ch * 64 + ahalf * 32;
            const uint4* ys = (const uint4*)(Yrow + kb);
            const uint4* ra = (const uint4*)(d_ratioH + kb);
            const uint4* bt = (const uint4*)(d_btopH + kb);
#pragma unroll
            for (int q = 0; q < 4; q++) {
                uint4 H = make_uint4(0, 0, 0, 0);
                if (rowOK) {
                    uint4 yv = ys[q];
                    uint4 av = __ldg(ra + q);
                    uint4 bv = __ldg(bt + q);
                    H.x = hfmamax(av.x, yv.x, bv.x);
                    H.y = hfmamax(av.y, yv.y, bv.y);
                    H.z = hfmamax(av.z, yv.z, bv.z);
                    H.w = hfmamax(av.w, yv.w, bv.w);
                }
                uint32_t off = (uint32_t)(arow * ASTR + ahalf * 32 + q * 8) * 2;
                *(uint4*)(smem + off) = H;
            }
        }
        for (int idx = tid; idx < N * 8; idx += 256) {
            int n = idx >> 3, kq = idx & 7;
            int src = n * (K / 8) + ch * 8 + kq;
            uint32_t off = BOFF + (uint32_t)(n * BSTR + kq * 8) * 2;
            *(uint4*)(smem + off) = ((const uint4*)d_Whi)[src];
            *(uint4*)(smem + off + BBYTES) = ((const uint4*)d_Wlo)[src];
        }
        __syncthreads();
        const uint32_t within = lane & 15;
        const uint32_t brow = within & 7, bsel = within >> 3;
        const uint32_t ntoff = lane >> 4;
#pragma unroll
        for (int ks = 0; ks < 4; ks++) {
            uint32_t ah[4];
            uint32_t aaddr = sb +
                (uint32_t)((w * 16 + (lane & 15)) * ASTR + ks * 16 + (lane >> 4) * 8) * 2;
            ldsm4(ah, aaddr);
#pragma unroll
            for (int np = 0; np < N / 16; np++) {
                uint32_t baddr = sb + BOFF +
                    (uint32_t)((np * 16 + ntoff * 8 + brow) * BSTR + ks * 16 + bsel * 8) * 2;
                uint32_t bh[4], bl[4];
                ldsm4(bh, baddr);
                ldsm4(bl, baddr + BBYTES);
                mma16816f(acc[np * 2], ah, bh);
                mma16816f(acc[np * 2], ah, bl);
                mma16816f(acc[np * 2 + 1], ah, bh + 2);
                mma16816f(acc[np * 2 + 1], ah, bl + 2);
            }
        }
    }
#pragma unroll
    for (int nt = 0; nt < N / 8; nt++) {
        int col = nt * 8 + (lane & 3) * 2;
        int r0 = tileBase + w * 16 + (lane >> 2);
        if (r0 < NN)
            *(float2*)(out + (size_t)r0 * N + col) = make_float2(acc[nt][0], acc[nt][1]);
        int r1 = r0 + 8;
        if (r1 < NN)
            *(float2*)(out + (size_t)r1 * N + col) = make_float2(acc[nt][2], acc[nt][3]);
    }
}

// ---------------- EdgeConv via single-fp16 mma.sync, fp16 gather ----------------
template <int C>
__global__ __launch_bounds__(256, 2) void edge_mma_kernel(const __half* __restrict__ y) {
    constexpr int NCH = C / 64;
    constexpr int ASTRIDE = 72;
    constexpr int ABYTES = 128 * ASTRIDE * 2;
    constexpr int BOFF = ABYTES;
    constexpr int BSTRIDE = C + 8;
    extern __shared__ char smem[];
    float* buf = (float*)smem;
    uint32_t sb = smem_u32(smem);
    const int tid = threadIdx.x, lane = tid & 31, w = tid >> 5;
    const unsigned fullm = 0xFFFFFFFFu;

    for (int idx = tid; idx < C * 128 / 8; idx += 256) {
        int n = idx / (C / 8), kb = (idx % (C / 8)) * 8;
        uint32_t off = BOFF + (uint32_t)(n * BSTRIDE + kb) * 2;
        *(uint4*)(smem + off) = ((const uint4*)d_Whi)[idx];
    }

    const int arow = tid >> 1, ahalf = tid & 1;

    for (int t = blockIdx.x; t < EE / 128; t += gridDim.x) {
        float acc[16][4];
#pragma unroll
        for (int i = 0; i < 16; i++) { acc[i][0] = acc[i][1] = acc[i][2] = acc[i][3] = 0.f; }

        const int sA = d_csrsrc[t * 128 + arow];
        const int dA = d_csrdst[t * 128 + arow];

        for (int ch = 0; ch < NCH; ch++) {
            __syncthreads();
            {
                int kb = ch * 64 + ahalf * 32;
                const uint4* ys = (const uint4*)(y + (size_t)sA * C + kb);
                const uint4* yd = (const uint4*)(y + (size_t)dA * C + kb);
                const uint4* bb = (const uint4*)(d_bbotH + kb);
#pragma unroll
                for (int q = 0; q < 4; q++) {
                    uint4 sv = ys[q];
                    uint4 dv = yd[q];
                    uint4 bv = __ldg(bb + q);
                    uint4 H;
                    H.x = hsubaddmax(sv.x, dv.x, bv.x);
                    H.y = hsubaddmax(sv.y, dv.y, bv.y);
                    H.z = hsubaddmax(sv.z, dv.z, bv.z);
                    H.w = hsubaddmax(sv.w, dv.w, bv.w);
                    uint32_t off = (uint32_t)(arow * ASTRIDE + ahalf * 32 + q * 8) * 2;
                    *(uint4*)(smem + off) = H;
                }
            }
            __syncthreads();
            const uint32_t within = lane & 15;
            const uint32_t brow = within & 7, bsel = within >> 3;
            const uint32_t ntoff = lane >> 4;
#pragma unroll
            for (int ks = 0; ks < 4; ks++) {
                uint32_t ah[4];
                uint32_t aaddr = sb +
                    (uint32_t)((w * 16 + (lane & 15)) * ASTRIDE + ks * 16 + (lane >> 4) * 8) * 2;
                ldsm4(ah, aaddr);
#pragma unroll
                for (int np = 0; np < 8; np++) {
                    uint32_t baddr = sb + BOFF +
                        (uint32_t)((np * 16 + ntoff * 8 + brow) * BSTRIDE + ch * 64 + ks * 16 + bsel * 8) * 2;
                    uint32_t bh[4];
                    ldsm4(bh, baddr);
                    mma16816f(acc[np * 2], ah, bh);
                    mma16816f(acc[np * 2 + 1], ah, bh + 2);
                }
            }
        }
        // ---- epilogue: segmented max over CSR runs ----
        int erow = t * 128 + (w & 3) * 32 + lane;
        int dl = d_csrdst[erow];
        int prev = __shfl_up_sync(fullm, dl, 1);
        bool head = (lane == 0) || (dl != prev);
        unsigned Hb = __ballot_sync(fullm, head);
        unsigned mle;
        asm("mov.u32 %0, %%lanemask_le;" : "=r"(mle));
        int run_start = 31 - __clz(Hb & mle);
        bool tail = (lane == 31) || ((Hb >> (lane + 1)) & 1);
        unsigned* trow = d_tmpmax + (size_t)dl * 128;
#pragma unroll
        for (int g = 0; g < 4; g++) {
            __syncthreads();
#pragma unroll
            for (int q = 0; q < 4; q++) {
                int nt = g * 4 + q;
                int lcol = q * 8 + (lane & 3) * 2;
                int r0 = w * 16 + (lane >> 2);
                buf[r0 * 33 + lcol]           = acc[nt][0];
                buf[r0 * 33 + lcol + 1]       = acc[nt][1];
                buf[(r0 + 8) * 33 + lcol]     = acc[nt][2];
                buf[(r0 + 8) * 33 + lcol + 1] = acc[nt][3];
            }
            __syncthreads();
            int rr = (w & 3) * 32 + lane;
            int cb = (w >> 2) * 16;
            float v[16];
#pragma unroll
            for (int j = 0; j < 16; j++) v[j] = buf[rr * 33 + cb + j];
#pragma unroll
            for (int dlt = 1; dlt < 32; dlt <<= 1) {
#pragma unroll
                for (int j = 0; j < 16; j++) {
                    float u = __shfl_up_sync(fullm, v[j], dlt);
                    if ((int)lane - dlt >= run_start) v[j] = fmaxf(v[j], u);
                }
            }
            if (tail) {
#pragma unroll
                for (int j = 0; j < 16; j++) atomicMax(trow + g * 32 + cb + j, encf(v[j]));
            }
        }
    }
}

// ---------------- finalize -> fp16 y for next layer (a_bot scale); reset tmp ----------------
__global__ void edge_final_half(const float* __restrict__ P, const float* __restrict__ aNext,
                                __half* __restrict__ yout) {
    int i = blockIdx.x * blockDim.x + threadIdx.x;  // over pairs
    if (i < NN * 64) {
        int i0 = i * 2;
        int d = i0 >> 7;
        int c = i0 & 127;
        float r0 = 0.f, r1 = 0.f;
        if (d_indeg[d] > 0) {
            r0 = P[i0] + decf(d_tmpmax[i0]);
            r1 = P[i0 + 1] + decf(d_tmpmax[i0 + 1]);
        }
        *(__half2*)(yout + i0) = __floats2half2_rn(aNext[c] * r0, aNext[c + 1] * r1);
        d_tmpmax[i0] = 0;
        d_tmpmax[i0 + 1] = 0;
    }
}

// ---------------- fused last-layer finalize + FC; resets indeg & tmpmax ----------------
__global__ void fc_fused_kernel(const float* __restrict__ P, const float* __restrict__ Wfc,
                                const float* __restrict__ bfc, float* __restrict__ out) {
    int w = threadIdx.x >> 5, lane = threadIdx.x & 31;
    int d = blockIdx.x * 4 + w;
    if (d >= NN) return;
    bool nz = d_indeg[d] > 0;
    float s = 0.f;
#pragma unroll
    for (int u = 0; u < 4; u++) {
        int k = lane + 32 * u;
        size_t idx = (size_t)d * 128 + k;
        float h = nz ? P[idx] + decf(d_tmpmax[idx]) : 0.f;
        d_tmpmax[idx] = 0;
        s = fmaf(h, Wfc[k], s);
    }
#pragma unroll
    for (int off = 16; off; off >>= 1) s += __shfl_down_sync(0xffffffffu, s, off);
    if (lane == 0) {
        out[d] = s + bfc[0];
        d_indeg[d] = 0;
    }
}

// ---------------- host ----------------
extern "C" void kernel_launch(void* const* d_in, const int* in_sizes, int n_in,
                              void* d_out, int out_size) {
    const float* x   = (const float*)d_in[0];
    const int*   ei  = (const int*)d_in[1];
    const float* Wm  = (const float*)d_in[2];
    const float* bm  = (const float*)d_in[3];
    const float* Wc  = (const float*)d_in[4];
    const float* bc  = (const float*)d_in[5];
    const float* Wg1 = (const float*)d_in[6];
    const float* bg1 = (const float*)d_in[7];
    const float* Wg2 = (const float*)d_in[8];
    const float* bg2 = (const float*)d_in[9];
    const float* Wg3 = (const float*)d_in[10];
    const float* bg3 = (const float*)d_in[11];
    const float* e1g = (const float*)d_in[12];
    const float* e1b = (const float*)d_in[13];
    const float* e1m = (const float*)d_in[14];
    const float* e1v = (const float*)d_in[15];
    const float* e1W = (const float*)d_in[16];
    const float* e2g = (const float*)d_in[17];
    const float* e2b = (const float*)d_in[18];
    const float* e2m = (const float*)d_in[19];
    const float* e2v = (const float*)d_in[20];
    const float* e2W = (const float*)d_in[21];
    const float* e3g = (const float*)d_in[22];
    const float* e3b = (const float*)d_in[23];
    const float* e3m = (const float*)d_in[24];
    const float* e3v = (const float*)d_in[25];
    const float* e3W = (const float*)d_in[26];
    const float* Wfc = (const float*)d_in[27];
    const float* bfc = (const float*)d_in[28];
    float* out = (float*)d_out;

    float *pA, *pB, *pH, *pX0, *pP, *pDa;
    __half* pY;
    cudaGetSymbolAddress((void**)&pA,  d_bufA);
    cudaGetSymbolAddress((void**)&pB,  d_bufB);
    cudaGetSymbolAddress((void**)&pH,  d_h);
    cudaGetSymbolAddress((void**)&pX0, d_x0);
    cudaGetSymbolAddress((void**)&pP,  d_P);
    cudaGetSymbolAddress((void**)&pDa, d_aAff);
    cudaGetSymbolAddress((void**)&pY,  d_yh);

    const int SME1 = 18432 + 128 * (256 + 8) * 2;  // 86016 (edge C=256)
    const int SME2 = 18432 + 128 * (128 + 8) * 2;  // 53248 (edge C=128)
    cudaFuncSetAttribute(edge_mma_kernel<256>, cudaFuncAttributeMaxDynamicSharedMemorySize, SME1);
    cudaFuncSetAttribute(edge_mma_kernel<128>, cudaFuncAttributeMaxDynamicSharedMemorySize, SME2);

    const int SMG64  = 18432 + 2 * 64 * 72 * 2;    // 36864
    const int SMG128 = 18432 + 2 * 128 * 72 * 2;   // 55296
    cudaFuncSetAttribute(gemm_mma<512, 64, false>, cudaFuncAttributeMaxDynamicSharedMemorySize, SMG64);
    cudaFuncSetAttribute(gemm_mma<64, 128, false>, cudaFuncAttributeMaxDynamicSharedMemorySize, SMG128);
    cudaFuncSetAttribute(gemm_mma<128, 128, false>, cudaFuncAttributeMaxDynamicSharedMemorySize, SMG128);
    cudaFuncSetAttribute(gemm_mma<128, 128, true>, cudaFuncAttributeMaxDynamicSharedMemorySize, SMG128);
    cudaFuncSetAttribute(gemm_mma_h<256, 128>, cudaFuncAttributeMaxDynamicSharedMemorySize, SMG128);
    cudaFuncSetAttribute(gemm_mma_h<128, 128>, cudaFuncAttributeMaxDynamicSharedMemorySize, SMG128);

    const int TILES = (NN + 127) / 128;  // 157

    // CSR build (indeg zeroed by fc_fused at end of previous replay)
    count_kernel<<<(EE + 255) / 256, 256>>>(ei);
    scan_kernel<<<1, 1024>>>();
    fill_kernel<<<(EE + 255) / 256, 256>>>(ei);

    // dual projection
    wsplit2_kernel<<<(512 * 64 + 255) / 256, 256>>>(Wc, 512, 64, 64, 0);
    gemm_mma<512, 64, false><<<TILES, 256, SMG64>>>(x, bc, nullptr, pX0, 0, 1, NN, 64, 0);
    wsplit2_kernel<<<(512 * 64 + 255) / 256, 256>>>(Wm, 512, 64, 64, 0);
    gemm_mma<512, 64, false><<<40, 256, SMG64>>>(x, bm, nullptr, pX0, 0, 4, 5000, 64, 0);

    // GCN stack (aggregate-then-GEMM; agg is linear)
    gcn_agg_pre<64><<<NN / 2, 128>>>(pX0, pH);
    wsplit2_kernel<<<(64 * 128 + 255) / 256, 256>>>(Wg1, 64, 128, 128, 0);
    gemm_mma<64, 128, false><<<TILES, 256, SMG128>>>(pH, bg1, nullptr, pA, 0, 1, NN, 128, 0);
    gcn_agg_pre<128><<<NN, 128>>>(pA, pH);
    wsplit2_kernel<<<(128 * 128 + 255) / 256, 256>>>(Wg2, 128, 128, 128, 0);
    gemm_mma<128, 128, false><<<TILES, 256, SMG128>>>(pH, bg2, nullptr, pB, 0, 1, NN, 128, 0);
    gcn_agg_pre<128><<<NN, 128>>>(pB, pH);

    // bnaff(e1) BEFORE g3 so its a_bot can scale y1 in the g3 epilogue
    bnaff_kernel<<<2, 256>>>(e1g, e1b, e1m, e1v, 512);
    bnaffh_kernel<<<1, 256>>>(256);
    wsplit2_kernel<<<(128 * 128 + 255) / 256, 256>>>(Wg3, 128, 256, 128, 0);
    gemm_mma<128, 128, true><<<TILES, 256, SMG128>>>(pH, bg3, pDa + 256, pY, 0, 1, NN, 256, 0);
    wsplit2_kernel<<<(128 * 128 + 255) / 256, 256>>>(Wg3, 128, 256, 128, 128);
    gemm_mma<128, 128, true><<<TILES, 256, SMG128>>>(pH, bg3, pDa + 256, pY, 0, 1, NN, 256, 128);
    // y1 = a_bot1 ⊙ g3   [NN, 256] fp16

    // EdgeConv 1 (C=256)
    wsplit2_kernel<<<(256 * 128 + 255) / 256, 256>>>(e1W, 256, 128, 128, 0);
    gemm_mma_h<256, 128><<<TILES, 256, SMG128>>>(pY, pP);
    wsplit_kernel<<<(256 * 128 + 255) / 256, 256>>>(e1W + 256 * 128, 256);
    edge_mma_kernel<256><<<296, 256, SME1>>>(pY);
    bnaff_kernel<<<1, 256>>>(e2g, e2b, e2m, e2v, 256);
    bnaffh_kernel<<<1, 128>>>(128);
    edge_final_half<<<(NN * 64 + 255) / 256, 256>>>(pP, pDa + 128, pY);
    // y2 = a_bot2 ⊙ out1   [NN, 128] fp16

    // EdgeConv 2 (C=128)
    wsplit2_kernel<<<(128 * 128 + 255) / 256, 256>>>(e2W, 128, 128, 128, 0);
    gemm_mma_h<128, 128><<<TILES, 256, SMG128>>>(pY, pP);
    wsplit_kernel<<<(128 * 128 + 255) / 256, 256>>>(e2W + 128 * 128, 128);
    edge_mma_kernel<128><<<592, 256, SME2>>>(pY);
    bnaff_kernel<<<1, 256>>>(e3g, e3b, e3m, e3v, 256);
    bnaffh_kernel<<<1, 128>>>(128);
    edge_final_half<<<(NN * 64 + 255) / 256, 256>>>(pP, pDa + 128, pY);
    // y3 = a_bot3 ⊙ out2   [NN, 128] fp16

    // EdgeConv 3 (C=128) -> fused finalize+FC (+state reset for replay)
    wsplit2_kernel<<<(128 * 128 + 255) / 256, 256>>>(e3W, 128, 128, 128, 0);
    gemm_mma_h<128, 128><<<TILES, 256, SMG128>>>(pY, pP);
    wsplit_kernel<<<(128 * 128 + 255) / 256, 256>>>(e3W + 128 * 128, 128);
    edge_mma_kernel<128><<<592, 256, SME2>>>(pY);
    fc_fused_kernel<<<5000, 128>>>(pP, Wfc, bfc, out);
}